// round 1
// baseline (speedup 1.0000x reference)
#include <cuda_runtime.h>

#define Nn 50000
#define Ee 800000
#define DAv 256
#define DBv 128
#define Hh 256
#define EPSv 1e-5f
#define SLOPEv 0.01f

// ---------------- scratch (static device globals; no allocation) -------------
__device__ float g_aggr[(size_t)Nn * 256];      // reused per conv
__device__ float g_eA[(size_t)Nn * Hh];
__device__ float g_eB[(size_t)Nn * Hh];
__device__ float g_hA[(size_t)Nn * Hh];
__device__ float g_hB[(size_t)Nn * Hh];
__device__ float g_inv[3][Nn];                  // 1/max(cnt,1) per edge type
__device__ float g_Wf[12][Hh * Hh];             // fused weights
__device__ float g_bf[6][Hh];                   // fused biases
__device__ float g_stats[2 * Hh];               // BN column sums / sumsq
__device__ float g_prm[2 * Hh];                 // BN scale / shift

// ---------------- kernels ----------------------------------------------------

// count edges per dst node (into cnt, pre-zeroed)
__global__ void count_k(const int* __restrict__ dst, float* __restrict__ cnt) {
    int i = blockIdx.x * blockDim.x + threadIdx.x;
    if (i < Ee) atomicAdd(&cnt[dst[i]], 1.0f);
}

__global__ void inv_k(float* __restrict__ c) {
    int i = blockIdx.x * blockDim.x + threadIdx.x;
    if (i < Nn) c[i] = 1.0f / fmaxf(c[i], 1.0f);
}

// scatter-add: aggr[dst] += x[src], vectorized float4 per thread
__global__ void scatter_add_k(const float* __restrict__ x,
                              const int* __restrict__ src,
                              const int* __restrict__ dst,
                              float* __restrict__ aggr, int d) {
    int d4 = d >> 2;
    long i = (long)blockIdx.x * blockDim.x + threadIdx.x;
    long total = (long)Ee * d4;
    if (i >= total) return;
    int e = (int)(i / d4);
    int c = (int)(i % d4) * 4;
    int s = src[e];
    int dn = dst[e];
    float4 v = *(const float4*)(x + (size_t)s * d + c);
    float* p = aggr + (size_t)dn * d + c;
    atomicAdd(p + 0, v.x);
    atomicAdd(p + 1, v.y);
    atomicAdd(p + 2, v.z);
    atomicAdd(p + 3, v.w);
}

// fused weight: out[o,k] = sum_j Wupd[o, off+j] * W[j,k], j in [0,H)
__global__ void fuse_w_k(const float* __restrict__ Wupd, int off,
                         const float* __restrict__ W, int dW,
                         float* __restrict__ out) {
    int o = blockIdx.x;          // 0..255
    int k = threadIdx.x;         // 0..dW-1
    const float* wrow = Wupd + (size_t)o * (2 * Hh) + off;
    float s = 0.0f;
#pragma unroll 8
    for (int j = 0; j < Hh; j++) s += wrow[j] * W[(size_t)j * dW + k];
    out[(size_t)o * dW + k] = s;
}

// fused bias: bf[o] = bupd[o] + sum_j Wupd[o,j]*bdst[j] + Wupd[o,H+j]*bsrc[j]
__global__ void fuse_bias_k(const float* __restrict__ Wupd,
                            const float* __restrict__ bdst,
                            const float* __restrict__ bsrc,
                            const float* __restrict__ bupd,
                            float* __restrict__ out) {
    int o = threadIdx.x;
    const float* wrow = Wupd + (size_t)o * (2 * Hh);
    float s = bupd[o];
#pragma unroll 8
    for (int j = 0; j < Hh; j++) s += wrow[j] * bdst[j] + wrow[Hh + j] * bsrc[j];
    out[o] = s;
}

// C[M x 256] (+)= A[M x K] (optionally row-scaled) @ W[256 x K]^T (+ bias)
#define BMt 64
#define BNt 64
#define BKt 16
__global__ void gemm_xwT_k(const float* __restrict__ A,
                           const float* __restrict__ W,
                           const float* __restrict__ bias,
                           const float* __restrict__ rowscale,
                           float* __restrict__ C, int M, int K, int accumulate) {
    __shared__ float As[BKt][BMt];
    __shared__ float Ws[BKt][BNt];
    int tid = threadIdx.x;
    int mBase = blockIdx.x * BMt;
    int nBase = blockIdx.y * BNt;
    int lr = tid >> 2;           // 0..63
    int lc = (tid & 3) * 4;      // 0,4,8,12
    int ty = tid >> 4;           // 0..15
    int tx = tid & 15;           // 0..15

    float acc[4][4];
#pragma unroll
    for (int i = 0; i < 4; i++)
#pragma unroll
        for (int j = 0; j < 4; j++) acc[i][j] = 0.0f;

    for (int k0 = 0; k0 < K; k0 += BKt) {
        int arow = mBase + lr;
        float4 av = make_float4(0.f, 0.f, 0.f, 0.f);
        if (arow < M) {
            av = *(const float4*)(A + (size_t)arow * K + k0 + lc);
            if (rowscale) {
                float s = rowscale[arow];
                av.x *= s; av.y *= s; av.z *= s; av.w *= s;
            }
        }
        As[lc + 0][lr] = av.x;
        As[lc + 1][lr] = av.y;
        As[lc + 2][lr] = av.z;
        As[lc + 3][lr] = av.w;
        float4 wv = *(const float4*)(W + (size_t)(nBase + lr) * K + k0 + lc);
        Ws[lc + 0][lr] = wv.x;
        Ws[lc + 1][lr] = wv.y;
        Ws[lc + 2][lr] = wv.z;
        Ws[lc + 3][lr] = wv.w;
        __syncthreads();
#pragma unroll
        for (int kk = 0; kk < BKt; kk++) {
            float4 a = *(const float4*)&As[kk][ty * 4];
            float4 b = *(const float4*)&Ws[kk][tx * 4];
            acc[0][0] += a.x * b.x; acc[0][1] += a.x * b.y; acc[0][2] += a.x * b.z; acc[0][3] += a.x * b.w;
            acc[1][0] += a.y * b.x; acc[1][1] += a.y * b.y; acc[1][2] += a.y * b.z; acc[1][3] += a.y * b.w;
            acc[2][0] += a.z * b.x; acc[2][1] += a.z * b.y; acc[2][2] += a.z * b.z; acc[2][3] += a.z * b.w;
            acc[3][0] += a.w * b.x; acc[3][1] += a.w * b.y; acc[3][2] += a.w * b.z; acc[3][3] += a.w * b.w;
        }
        __syncthreads();
    }

#pragma unroll
    for (int i = 0; i < 4; i++) {
        int row = mBase + ty * 4 + i;
        if (row >= M) continue;
        float* cp = C + (size_t)row * 256 + nBase + tx * 4;
        float4 r = make_float4(acc[i][0], acc[i][1], acc[i][2], acc[i][3]);
        if (bias) {
            float4 b = *(const float4*)(bias + nBase + tx * 4);
            r.x += b.x; r.y += b.y; r.z += b.z; r.w += b.w;
        }
        if (accumulate) {
            float4 o = *(const float4*)cp;
            r.x += o.x; r.y += o.y; r.z += o.z; r.w += o.w;
        }
        *(float4*)cp = r;
    }
}

// BN column stats: sums[c] += sum(x*prescale), sums[256+c] += sum((x*prescale)^2)
#define ROWS_PER_BLK 256
__global__ void col_stats_k(const float* __restrict__ x, float prescale,
                            float* __restrict__ sums) {
    int c = threadIdx.x;
    int r0 = blockIdx.x * ROWS_PER_BLK;
    int r1 = r0 + ROWS_PER_BLK;
    if (r1 > Nn) r1 = Nn;
    float s = 0.0f, s2 = 0.0f;
    for (int r = r0; r < r1; r++) {
        float v = x[(size_t)r * Hh + c] * prescale;
        s += v;
        s2 += v * v;
    }
    atomicAdd(&sums[c], s);
    atomicAdd(&sums[Hh + c], s2);
}

__global__ void bn_finalize_k(const float* __restrict__ sums,
                              const float* __restrict__ g,
                              const float* __restrict__ b,
                              float* __restrict__ prm) {
    int c = threadIdx.x;
    float mean = sums[c] / (float)Nn;
    float var = sums[Hh + c] / (float)Nn - mean * mean;
    float sc = g[c] * rsqrtf(var + EPSv);
    prm[c] = sc;
    prm[Hh + c] = b[c] - mean * sc;
}

// y = leaky_relu(prescale*x*scale + shift)
__global__ void bn_apply_k(const float* __restrict__ x,
                           const float* __restrict__ prm, float prescale,
                           float* __restrict__ y) {
    int i = blockIdx.x * blockDim.x + threadIdx.x;  // over Nn*64 float4s
    if (i >= Nn * (Hh / 4)) return;
    int c = (i & 63) * 4;
    float4 v = *(const float4*)(x + (size_t)i * 4);
    float4 sc = *(const float4*)(prm + c);
    float4 sh = *(const float4*)(prm + Hh + c);
    float t0 = v.x * prescale * sc.x + sh.x;
    float t1 = v.y * prescale * sc.y + sh.y;
    float t2 = v.z * prescale * sc.z + sh.z;
    float t3 = v.w * prescale * sc.w + sh.w;
    float4 r;
    r.x = t0 >= 0.f ? t0 : SLOPEv * t0;
    r.y = t1 >= 0.f ? t1 : SLOPEv * t1;
    r.z = t2 >= 0.f ? t2 : SLOPEv * t2;
    r.w = t3 >= 0.f ? t3 : SLOPEv * t3;
    *(float4*)(y + (size_t)i * 4) = r;
}

// ---------------- host orchestration ----------------------------------------

static void run_gemm(const float* A, const float* W, const float* bias,
                     const float* rs, float* C, int M, int K, int acc) {
    dim3 grid((M + BMt - 1) / BMt, 256 / BNt);
    gemm_xwT_k<<<grid, 256>>>(A, W, bias, rs, C, M, K, acc);
}

static void run_scatter(const float* x, const int* src, const int* dst,
                        float* aggr, int d) {
    cudaMemsetAsync(aggr, 0, (size_t)Nn * d * sizeof(float), 0);
    long total = (long)Ee * (d / 4);
    int blocks = (int)((total + 255) / 256);
    scatter_add_k<<<blocks, 256>>>(x, src, dst, aggr, d);
}

static void run_conv(const float* xsrc, int dsrc, const float* xdst, int ddst,
                     const int* esrc, const int* edst, const float* inv,
                     const float* Wfd, const float* Wfs, const float* bias,
                     float* out, int accumulate, float* aggr) {
    run_scatter(xsrc, esrc, edst, aggr, dsrc);
    run_gemm(xdst, Wfd, bias, nullptr, out, Nn, ddst, accumulate);
    run_gemm(aggr, Wfs, nullptr, inv, out, Nn, dsrc, 1);
}

static void run_bn(const float* x, float prescale, const float* g,
                   const float* b, float* y, float* stats, float* prm) {
    cudaMemsetAsync(stats, 0, 2 * Hh * sizeof(float), 0);
    col_stats_k<<<(Nn + ROWS_PER_BLK - 1) / ROWS_PER_BLK, Hh>>>(x, prescale, stats);
    bn_finalize_k<<<1, Hh>>>(stats, g, b, prm);
    bn_apply_k<<<(Nn * (Hh / 4) + 255) / 256, 256>>>(x, prm, prescale, y);
}

static void run_fuse(const float* Wupd, const float* Wdst, int ddst,
                     const float* Wsrc, int dsrc, const float* bdst,
                     const float* bsrc, const float* bupd, float* Wfd,
                     float* Wfs, float* bf) {
    fuse_w_k<<<Hh, ddst>>>(Wupd, 0, Wdst, ddst, Wfd);
    fuse_w_k<<<Hh, dsrc>>>(Wupd, Hh, Wsrc, dsrc, Wfs);
    fuse_bias_k<<<1, Hh>>>(Wupd, bdst, bsrc, bupd, bf);
}

extern "C" void kernel_launch(void* const* d_in, const int* in_sizes, int n_in,
                              void* d_out, int out_size) {
    const float* x_A = (const float*)d_in[0];
    const float* x_B = (const float*)d_in[1];
    const int* e_ab = (const int*)d_in[2];
    const int* e_ba = (const int*)d_in[3];
    const int* e_aa = (const int*)d_in[4];
    const float* ab_Wsrc1 = (const float*)d_in[5];
    const float* ab_bsrc1 = (const float*)d_in[6];
    const float* ab_Wdst1 = (const float*)d_in[7];
    const float* ab_bdst1 = (const float*)d_in[8];
    const float* ab_Wupd1 = (const float*)d_in[9];
    const float* ab_bupd1 = (const float*)d_in[10];
    const float* ba_Wsrc1 = (const float*)d_in[11];
    const float* ba_bsrc1 = (const float*)d_in[12];
    const float* ba_Wdst1 = (const float*)d_in[13];
    const float* ba_bdst1 = (const float*)d_in[14];
    const float* ba_Wupd1 = (const float*)d_in[15];
    const float* ba_bupd1 = (const float*)d_in[16];
    const float* aa_Wsrc1 = (const float*)d_in[17];
    const float* aa_bsrc1 = (const float*)d_in[18];
    const float* aa_Wdst1 = (const float*)d_in[19];
    const float* aa_bdst1 = (const float*)d_in[20];
    const float* aa_Wupd1 = (const float*)d_in[21];
    const float* aa_bupd1 = (const float*)d_in[22];
    const float* Wsrc2 = (const float*)d_in[23];
    const float* bsrc2 = (const float*)d_in[24];
    const float* Wdst2 = (const float*)d_in[25];
    const float* bdst2 = (const float*)d_in[26];
    const float* Wupd2 = (const float*)d_in[27];
    const float* bupd2 = (const float*)d_in[28];
    const float* bn_g = (const float*)d_in[29];
    const float* bn_b = (const float*)d_in[30];
    float* out = (float*)d_out;

    float *aggr, *eA, *eB, *hA, *hB, *inv, *Wf, *bf, *stats, *prm;
    cudaGetSymbolAddress((void**)&aggr, g_aggr);
    cudaGetSymbolAddress((void**)&eA, g_eA);
    cudaGetSymbolAddress((void**)&eB, g_eB);
    cudaGetSymbolAddress((void**)&hA, g_hA);
    cudaGetSymbolAddress((void**)&hB, g_hB);
    cudaGetSymbolAddress((void**)&inv, g_inv);
    cudaGetSymbolAddress((void**)&Wf, g_Wf);
    cudaGetSymbolAddress((void**)&bf, g_bf);
    cudaGetSymbolAddress((void**)&stats, g_stats);
    cudaGetSymbolAddress((void**)&prm, g_prm);

    float* inv_ab = inv + 0 * Nn;
    float* inv_ba = inv + 1 * Nn;
    float* inv_aa = inv + 2 * Nn;
#define WF(i) (Wf + (size_t)(i) * Hh * Hh)
#define BF(i) (bf + (size_t)(i) * Hh)

    // ---- degree counts -> inverse (per edge type, dst row = e + Ee) ----
    cudaMemsetAsync(inv, 0, 3 * Nn * sizeof(float), 0);
    count_k<<<(Ee + 255) / 256, 256>>>(e_ab + Ee, inv_ab);
    count_k<<<(Ee + 255) / 256, 256>>>(e_ba + Ee, inv_ba);
    count_k<<<(Ee + 255) / 256, 256>>>(e_aa + Ee, inv_aa);
    inv_k<<<(Nn + 255) / 256, 256>>>(inv_ab);
    inv_k<<<(Nn + 255) / 256, 256>>>(inv_ba);
    inv_k<<<(Nn + 255) / 256, 256>>>(inv_aa);

    // ---- weight fusion (dst-half and src-half of Wupd folded into W's) ----
    run_fuse(ab_Wupd1, ab_Wdst1, DBv, ab_Wsrc1, DAv, ab_bdst1, ab_bsrc1, ab_bupd1, WF(0), WF(1), BF(0));
    run_fuse(ba_Wupd1, ba_Wdst1, DAv, ba_Wsrc1, DBv, ba_bdst1, ba_bsrc1, ba_bupd1, WF(2), WF(3), BF(1));
    run_fuse(aa_Wupd1, aa_Wdst1, DAv, aa_Wsrc1, DAv, aa_bdst1, aa_bsrc1, aa_bupd1, WF(4), WF(5), BF(2));
    for (int i = 0; i < 3; i++) {
        run_fuse(Wupd2 + (size_t)i * Hh * 2 * Hh,
                 Wdst2 + (size_t)i * Hh * Hh, Hh,
                 Wsrc2 + (size_t)i * Hh * Hh, Hh,
                 bdst2 + (size_t)i * Hh, bsrc2 + (size_t)i * Hh,
                 bupd2 + (size_t)i * Hh, WF(6 + 2 * i), WF(7 + 2 * i), BF(3 + i));
    }

    // ---- layer 1 ----
    run_conv(x_A, DAv, x_B, DBv, e_ab, e_ab + Ee, inv_ab, WF(0), WF(1), BF(0), eB, 0, aggr);
    run_conv(x_B, DBv, x_A, DAv, e_ba, e_ba + Ee, inv_ba, WF(2), WF(3), BF(1), eA, 0, aggr);
    run_conv(x_A, DAv, x_A, DAv, e_aa, e_aa + Ee, inv_aa, WF(4), WF(5), BF(2), eA, 1, aggr);
    run_bn(eA, 0.5f, bn_g + 0 * Hh, bn_b + 0 * Hh, hA, stats, prm);
    run_bn(eB, 1.0f, bn_g + 1 * Hh, bn_b + 1 * Hh, hB, stats, prm);

    // ---- layer 2 ----
    run_conv(hA, Hh, hB, Hh, e_ab, e_ab + Ee, inv_ab, WF(6), WF(7), BF(3), eB, 0, aggr);
    run_conv(hB, Hh, hA, Hh, e_ba, e_ba + Ee, inv_ba, WF(8), WF(9), BF(4), eA, 0, aggr);
    run_conv(hA, Hh, hA, Hh, e_aa, e_aa + Ee, inv_aa, WF(10), WF(11), BF(5), eA, 1, aggr);
    run_bn(eA, 0.5f, bn_g + 2 * Hh, bn_b + 2 * Hh, out, stats, prm);
    run_bn(eB, 1.0f, bn_g + 3 * Hh, bn_b + 3 * Hh, out + (size_t)Nn * Hh, stats, prm);
}

// round 2
// speedup vs baseline: 1.3053x; 1.3053x over previous
#include <cuda_runtime.h>

#define Nn 50000
#define Ee 800000
#define DAv 256
#define DBv 128
#define Hh 256
#define EPSv 1e-5f
#define SLOPEv 0.01f

// ---------------- scratch (static device globals; no allocation) -------------
__device__ float g_aggr[6][(size_t)Nn * 256];   // one per conv (no WAR hazards)
__device__ float g_eA[(size_t)Nn * Hh];
__device__ float g_eB[(size_t)Nn * Hh];
__device__ float g_hA[(size_t)Nn * Hh];
__device__ float g_hB[(size_t)Nn * Hh];
__device__ float g_inv[3][Nn];                  // 1/max(cnt,1) per edge type
__device__ float g_Wf[12][Hh * Hh];             // fused weights
__device__ float g_bf[6][Hh];                   // fused biases
__device__ float g_stats[2 * Hh];               // BN column sums / sumsq
__device__ float g_prm[2 * Hh];                 // BN scale / shift

// ---------------- kernels ----------------------------------------------------

__global__ void count_k(const int* __restrict__ dst, float* __restrict__ cnt) {
    int i = blockIdx.x * blockDim.x + threadIdx.x;
    if (i < Ee) atomicAdd(&cnt[dst[i]], 1.0f);
}

__global__ void inv_k(float* __restrict__ c) {
    int i = blockIdx.x * blockDim.x + threadIdx.x;
    if (i < Nn) c[i] = 1.0f / fmaxf(c[i], 1.0f);
}

// scatter-add: aggr[dst] += x[src], one 16B vector-red per thread
__global__ void scatter_add_k(const float* __restrict__ x,
                              const int* __restrict__ src,
                              const int* __restrict__ dst,
                              float* __restrict__ aggr, int d) {
    int d4 = d >> 2;
    long i = (long)blockIdx.x * blockDim.x + threadIdx.x;
    long total = (long)Ee * d4;
    if (i >= total) return;
    int e = (int)(i / d4);
    int c = (int)(i % d4) * 4;
    int s = __ldg(src + e);
    int dn = __ldg(dst + e);
    float4 v = *(const float4*)(x + (size_t)s * d + c);
    float* p = aggr + (size_t)dn * d + c;
    asm volatile("red.global.add.v4.f32 [%0], {%1,%2,%3,%4};"
                 :: "l"(p), "f"(v.x), "f"(v.y), "f"(v.z), "f"(v.w)
                 : "memory");
}

// fused weight: out[o,k] = sum_j Wupd[o, off+j] * W[j,k], j in [0,H)
__global__ void fuse_w_k(const float* __restrict__ Wupd, int off,
                         const float* __restrict__ W, int dW,
                         float* __restrict__ out) {
    int o = blockIdx.x;          // 0..255
    int k = threadIdx.x;         // 0..dW-1
    const float* wrow = Wupd + (size_t)o * (2 * Hh) + off;
    float s = 0.0f;
#pragma unroll 8
    for (int j = 0; j < Hh; j++) s += wrow[j] * W[(size_t)j * dW + k];
    out[(size_t)o * dW + k] = s;
}

__global__ void fuse_bias_k(const float* __restrict__ Wupd,
                            const float* __restrict__ bdst,
                            const float* __restrict__ bsrc,
                            const float* __restrict__ bupd,
                            float* __restrict__ out) {
    int o = threadIdx.x;
    const float* wrow = Wupd + (size_t)o * (2 * Hh);
    float s = bupd[o];
#pragma unroll 8
    for (int j = 0; j < Hh; j++) s += wrow[j] * bdst[j] + wrow[Hh + j] * bsrc[j];
    out[o] = s;
}

// C[M x 256] (+)= A[M x K] (optionally row-scaled) @ W[256 x K]^T (+ bias)
#define BMt 64
#define BNt 64
#define BKt 16
__global__ void __launch_bounds__(256)
gemm_xwT_k(const float* __restrict__ A,
           const float* __restrict__ W,
           const float* __restrict__ bias,
           const float* __restrict__ rowscale,
           float* __restrict__ C, int M, int K, int accumulate) {
    __shared__ float As[BKt][BMt];
    __shared__ float Ws[BKt][BNt];
    int tid = threadIdx.x;
    int mBase = blockIdx.x * BMt;
    int nBase = blockIdx.y * BNt;
    int lr = tid >> 2;           // 0..63
    int lc = (tid & 3) * 4;      // 0,4,8,12
    int ty = tid >> 4;           // 0..15
    int tx = tid & 15;           // 0..15

    float acc[4][4];
#pragma unroll
    for (int i = 0; i < 4; i++)
#pragma unroll
        for (int j = 0; j < 4; j++) acc[i][j] = 0.0f;

    for (int k0 = 0; k0 < K; k0 += BKt) {
        int arow = mBase + lr;
        float4 av = make_float4(0.f, 0.f, 0.f, 0.f);
        if (arow < M) {
            av = *(const float4*)(A + (size_t)arow * K + k0 + lc);
            if (rowscale) {
                float s = rowscale[arow];
                av.x *= s; av.y *= s; av.z *= s; av.w *= s;
            }
        }
        As[lc + 0][lr] = av.x;
        As[lc + 1][lr] = av.y;
        As[lc + 2][lr] = av.z;
        As[lc + 3][lr] = av.w;
        float4 wv = *(const float4*)(W + (size_t)(nBase + lr) * K + k0 + lc);
        Ws[lc + 0][lr] = wv.x;
        Ws[lc + 1][lr] = wv.y;
        Ws[lc + 2][lr] = wv.z;
        Ws[lc + 3][lr] = wv.w;
        __syncthreads();
#pragma unroll
        for (int kk = 0; kk < BKt; kk++) {
            float4 a = *(const float4*)&As[kk][ty * 4];
            float4 b = *(const float4*)&Ws[kk][tx * 4];
            acc[0][0] += a.x * b.x; acc[0][1] += a.x * b.y; acc[0][2] += a.x * b.z; acc[0][3] += a.x * b.w;
            acc[1][0] += a.y * b.x; acc[1][1] += a.y * b.y; acc[1][2] += a.y * b.z; acc[1][3] += a.y * b.w;
            acc[2][0] += a.z * b.x; acc[2][1] += a.z * b.y; acc[2][2] += a.z * b.z; acc[2][3] += a.z * b.w;
            acc[3][0] += a.w * b.x; acc[3][1] += a.w * b.y; acc[3][2] += a.w * b.z; acc[3][3] += a.w * b.w;
        }
        __syncthreads();
    }

#pragma unroll
    for (int i = 0; i < 4; i++) {
        int row = mBase + ty * 4 + i;
        if (row >= M) continue;
        float* cp = C + (size_t)row * 256 + nBase + tx * 4;
        float4 r = make_float4(acc[i][0], acc[i][1], acc[i][2], acc[i][3]);
        if (bias) {
            float4 b = *(const float4*)(bias + nBase + tx * 4);
            r.x += b.x; r.y += b.y; r.z += b.z; r.w += b.w;
        }
        if (accumulate) {
            float4 o = *(const float4*)cp;
            r.x += o.x; r.y += o.y; r.z += o.z; r.w += o.w;
        }
        *(float4*)cp = r;
    }
}

// BN column stats
#define ROWS_PER_BLK 256
__global__ void col_stats_k(const float* __restrict__ x, float prescale,
                            float* __restrict__ sums) {
    int c = threadIdx.x;
    int r0 = blockIdx.x * ROWS_PER_BLK;
    int r1 = r0 + ROWS_PER_BLK;
    if (r1 > Nn) r1 = Nn;
    float s = 0.0f, s2 = 0.0f;
    for (int r = r0; r < r1; r++) {
        float v = x[(size_t)r * Hh + c] * prescale;
        s += v;
        s2 += v * v;
    }
    atomicAdd(&sums[c], s);
    atomicAdd(&sums[Hh + c], s2);
}

__global__ void bn_finalize_k(const float* __restrict__ sums,
                              const float* __restrict__ g,
                              const float* __restrict__ b,
                              float* __restrict__ prm) {
    int c = threadIdx.x;
    float mean = sums[c] / (float)Nn;
    float var = sums[Hh + c] / (float)Nn - mean * mean;
    float sc = g[c] * rsqrtf(var + EPSv);
    prm[c] = sc;
    prm[Hh + c] = b[c] - mean * sc;
}

__global__ void bn_apply_k(const float* __restrict__ x,
                           const float* __restrict__ prm, float prescale,
                           float* __restrict__ y) {
    int i = blockIdx.x * blockDim.x + threadIdx.x;
    if (i >= Nn * (Hh / 4)) return;
    int c = (i & 63) * 4;
    float4 v = *(const float4*)(x + (size_t)i * 4);
    float4 sc = *(const float4*)(prm + c);
    float4 sh = *(const float4*)(prm + Hh + c);
    float t0 = v.x * prescale * sc.x + sh.x;
    float t1 = v.y * prescale * sc.y + sh.y;
    float t2 = v.z * prescale * sc.z + sh.z;
    float t3 = v.w * prescale * sc.w + sh.w;
    float4 r;
    r.x = t0 >= 0.f ? t0 : SLOPEv * t0;
    r.y = t1 >= 0.f ? t1 : SLOPEv * t1;
    r.z = t2 >= 0.f ? t2 : SLOPEv * t2;
    r.w = t3 >= 0.f ? t3 : SLOPEv * t3;
    *(float4*)(y + (size_t)i * 4) = r;
}

// ---------------- host orchestration ----------------------------------------

static void run_gemm(cudaStream_t st, const float* A, const float* W,
                     const float* bias, const float* rs, float* C, int M, int K,
                     int acc) {
    dim3 grid((M + BMt - 1) / BMt, 256 / BNt);
    gemm_xwT_k<<<grid, 256, 0, st>>>(A, W, bias, rs, C, M, K, acc);
}

static void run_scatter(cudaStream_t st, const float* x, const int* src,
                        const int* dst, float* aggr, int d) {
    cudaMemsetAsync(aggr, 0, (size_t)Nn * d * sizeof(float), st);
    long total = (long)Ee * (d / 4);
    int blocks = (int)((total + 255) / 256);
    scatter_add_k<<<blocks, 256, 0, st>>>(x, src, dst, aggr, d);
}

static void run_bn(cudaStream_t st, const float* x, float prescale,
                   const float* g, const float* b, float* y, float* stats,
                   float* prm) {
    cudaMemsetAsync(stats, 0, 2 * Hh * sizeof(float), st);
    col_stats_k<<<(Nn + ROWS_PER_BLK - 1) / ROWS_PER_BLK, Hh, 0, st>>>(x, prescale, stats);
    bn_finalize_k<<<1, Hh, 0, st>>>(stats, g, b, prm);
    bn_apply_k<<<(Nn * (Hh / 4) + 255) / 256, 256, 0, st>>>(x, prm, prescale, y);
}

static void run_fuse(cudaStream_t st, const float* Wupd, const float* Wdst,
                     int ddst, const float* Wsrc, int dsrc, const float* bdst,
                     const float* bsrc, const float* bupd, float* Wfd,
                     float* Wfs, float* bf) {
    fuse_w_k<<<Hh, ddst, 0, st>>>(Wupd, 0, Wdst, ddst, Wfd);
    fuse_w_k<<<Hh, dsrc, 0, st>>>(Wupd, Hh, Wsrc, dsrc, Wfs);
    fuse_bias_k<<<1, Hh, 0, st>>>(Wupd, bdst, bsrc, bupd, bf);
}

extern "C" void kernel_launch(void* const* d_in, const int* in_sizes, int n_in,
                              void* d_out, int out_size) {
    const float* x_A = (const float*)d_in[0];
    const float* x_B = (const float*)d_in[1];
    const int* e_ab = (const int*)d_in[2];
    const int* e_ba = (const int*)d_in[3];
    const int* e_aa = (const int*)d_in[4];
    const float* ab_Wsrc1 = (const float*)d_in[5];
    const float* ab_bsrc1 = (const float*)d_in[6];
    const float* ab_Wdst1 = (const float*)d_in[7];
    const float* ab_bdst1 = (const float*)d_in[8];
    const float* ab_Wupd1 = (const float*)d_in[9];
    const float* ab_bupd1 = (const float*)d_in[10];
    const float* ba_Wsrc1 = (const float*)d_in[11];
    const float* ba_bsrc1 = (const float*)d_in[12];
    const float* ba_Wdst1 = (const float*)d_in[13];
    const float* ba_bdst1 = (const float*)d_in[14];
    const float* ba_Wupd1 = (const float*)d_in[15];
    const float* ba_bupd1 = (const float*)d_in[16];
    const float* aa_Wsrc1 = (const float*)d_in[17];
    const float* aa_bsrc1 = (const float*)d_in[18];
    const float* aa_Wdst1 = (const float*)d_in[19];
    const float* aa_bdst1 = (const float*)d_in[20];
    const float* aa_Wupd1 = (const float*)d_in[21];
    const float* aa_bupd1 = (const float*)d_in[22];
    const float* Wsrc2 = (const float*)d_in[23];
    const float* bsrc2 = (const float*)d_in[24];
    const float* Wdst2 = (const float*)d_in[25];
    const float* bdst2 = (const float*)d_in[26];
    const float* Wupd2 = (const float*)d_in[27];
    const float* bupd2 = (const float*)d_in[28];
    const float* bn_g = (const float*)d_in[29];
    const float* bn_b = (const float*)d_in[30];
    float* out = (float*)d_out;

    float *aggr, *eA, *eB, *hA, *hB, *inv, *Wf, *bf, *stats, *prm;
    cudaGetSymbolAddress((void**)&aggr, g_aggr);
    cudaGetSymbolAddress((void**)&eA, g_eA);
    cudaGetSymbolAddress((void**)&eB, g_eB);
    cudaGetSymbolAddress((void**)&hA, g_hA);
    cudaGetSymbolAddress((void**)&hB, g_hB);
    cudaGetSymbolAddress((void**)&inv, g_inv);
    cudaGetSymbolAddress((void**)&Wf, g_Wf);
    cudaGetSymbolAddress((void**)&bf, g_bf);
    cudaGetSymbolAddress((void**)&stats, g_stats);
    cudaGetSymbolAddress((void**)&prm, g_prm);

    float* inv_ab = inv + 0 * Nn;
    float* inv_ba = inv + 1 * Nn;
    float* inv_aa = inv + 2 * Nn;
#define WF(i) (Wf + (size_t)(i) * Hh * Hh)
#define BF(i) (bf + (size_t)(i) * Hh)
#define AGGR(i) (aggr + (size_t)(i) * Nn * 256)

    // lazily created side stream + events (first call is the uncaptured
    // correctness run, so these exist before graph capture begins)
    static cudaStream_t s1 = nullptr;
    static cudaEvent_t evFork, evS[3], evT[3], evHA, evHB;
    if (!s1) {
        cudaStreamCreateWithFlags(&s1, cudaStreamNonBlocking);
        cudaEventCreateWithFlags(&evFork, cudaEventDisableTiming);
        cudaEventCreateWithFlags(&evHA, cudaEventDisableTiming);
        cudaEventCreateWithFlags(&evHB, cudaEventDisableTiming);
        for (int i = 0; i < 3; i++) {
            cudaEventCreateWithFlags(&evS[i], cudaEventDisableTiming);
            cudaEventCreateWithFlags(&evT[i], cudaEventDisableTiming);
        }
    }
    cudaStream_t s0 = 0;

    // ---- fork side stream into the capture ----
    cudaEventRecord(evFork, s0);
    cudaStreamWaitEvent(s1, evFork, 0);

    // ================= side stream: degrees + layer-1 scatters =============
    cudaMemsetAsync(inv, 0, 3 * Nn * sizeof(float), s1);
    count_k<<<(Ee + 255) / 256, 256, 0, s1>>>(e_ab + Ee, inv_ab);
    count_k<<<(Ee + 255) / 256, 256, 0, s1>>>(e_ba + Ee, inv_ba);
    count_k<<<(Ee + 255) / 256, 256, 0, s1>>>(e_aa + Ee, inv_aa);
    inv_k<<<(Nn + 255) / 256, 256, 0, s1>>>(inv_ab);
    inv_k<<<(Nn + 255) / 256, 256, 0, s1>>>(inv_ba);
    inv_k<<<(Nn + 255) / 256, 256, 0, s1>>>(inv_aa);

    run_scatter(s1, x_A, e_ab, e_ab + Ee, AGGR(0), DAv);
    cudaEventRecord(evS[0], s1);
    run_scatter(s1, x_B, e_ba, e_ba + Ee, AGGR(1), DBv);
    cudaEventRecord(evS[1], s1);
    run_scatter(s1, x_A, e_aa, e_aa + Ee, AGGR(2), DAv);
    cudaEventRecord(evS[2], s1);

    // ================= main stream: weight fusion + layer-1 GEMMs ==========
    run_fuse(s0, ab_Wupd1, ab_Wdst1, DBv, ab_Wsrc1, DAv, ab_bdst1, ab_bsrc1, ab_bupd1, WF(0), WF(1), BF(0));
    run_fuse(s0, ba_Wupd1, ba_Wdst1, DAv, ba_Wsrc1, DBv, ba_bdst1, ba_bsrc1, ba_bupd1, WF(2), WF(3), BF(1));
    run_fuse(s0, aa_Wupd1, aa_Wdst1, DAv, aa_Wsrc1, DAv, aa_bdst1, aa_bsrc1, aa_bupd1, WF(4), WF(5), BF(2));
    for (int i = 0; i < 3; i++) {
        run_fuse(s0, Wupd2 + (size_t)i * Hh * 2 * Hh,
                 Wdst2 + (size_t)i * Hh * Hh, Hh,
                 Wsrc2 + (size_t)i * Hh * Hh, Hh,
                 bdst2 + (size_t)i * Hh, bsrc2 + (size_t)i * Hh,
                 bupd2 + (size_t)i * Hh, WF(6 + 2 * i), WF(7 + 2 * i), BF(3 + i));
    }

    // dst-side GEMMs (no scatter dependency)
    run_gemm(s0, x_A, WF(2), BF(1), nullptr, eA, Nn, DAv, 0);   // ba dst
    run_gemm(s0, x_A, WF(4), BF(2), nullptr, eA, Nn, DAv, 1);   // aa dst
    run_gemm(s0, x_B, WF(0), BF(0), nullptr, eB, Nn, DBv, 0);   // ab dst
    // src-side GEMMs (wait on matching scatter)
    cudaStreamWaitEvent(s0, evS[1], 0);
    run_gemm(s0, AGGR(1), WF(3), nullptr, inv_ba, eA, Nn, DBv, 1);
    cudaStreamWaitEvent(s0, evS[2], 0);
    run_gemm(s0, AGGR(2), WF(5), nullptr, inv_aa, eA, Nn, DAv, 1);
    run_bn(s0, eA, 0.5f, bn_g + 0 * Hh, bn_b + 0 * Hh, hA, stats, prm);
    cudaEventRecord(evHA, s0);
    cudaStreamWaitEvent(s0, evS[0], 0);
    run_gemm(s0, AGGR(0), WF(1), nullptr, inv_ab, eB, Nn, DAv, 1);
    run_bn(s0, eB, 1.0f, bn_g + 1 * Hh, bn_b + 1 * Hh, hB, stats, prm);
    cudaEventRecord(evHB, s0);

    // ================= side stream: layer-2 scatters =======================
    cudaStreamWaitEvent(s1, evHA, 0);
    run_scatter(s1, hA, e_ab, e_ab + Ee, AGGR(3), Hh);
    cudaEventRecord(evT[0], s1);
    run_scatter(s1, hA, e_aa, e_aa + Ee, AGGR(5), Hh);
    cudaEventRecord(evT[2], s1);
    cudaStreamWaitEvent(s1, evHB, 0);
    run_scatter(s1, hB, e_ba, e_ba + Ee, AGGR(4), Hh);
    cudaEventRecord(evT[1], s1);

    // ================= main stream: layer-2 GEMMs + BN =====================
    run_gemm(s0, hA, WF(8), BF(4), nullptr, eA, Nn, Hh, 0);     // ba dst
    run_gemm(s0, hA, WF(10), BF(5), nullptr, eA, Nn, Hh, 1);    // aa dst
    run_gemm(s0, hB, WF(6), BF(3), nullptr, eB, Nn, Hh, 0);     // ab dst
    cudaStreamWaitEvent(s0, evT[1], 0);
    run_gemm(s0, AGGR(4), WF(9), nullptr, inv_ba, eA, Nn, Hh, 1);
    cudaStreamWaitEvent(s0, evT[2], 0);
    run_gemm(s0, AGGR(5), WF(11), nullptr, inv_aa, eA, Nn, Hh, 1);
    run_bn(s0, eA, 0.5f, bn_g + 2 * Hh, bn_b + 2 * Hh, out, stats, prm);
    cudaStreamWaitEvent(s0, evT[0], 0);
    run_gemm(s0, AGGR(3), WF(7), nullptr, inv_ab, eB, Nn, Hh, 1);
    run_bn(s0, eB, 1.0f, bn_g + 3 * Hh, bn_b + 3 * Hh, out + (size_t)Nn * Hh, stats, prm);
}

// round 3
// speedup vs baseline: 1.7734x; 1.3586x over previous
#include <cuda_runtime.h>

#define Nn 50000
#define Ee 800000
#define DAv 256
#define DBv 128
#define Hh 256
#define EPSv 1e-5f
#define SLOPEv 0.01f

typedef unsigned long long ull;

// ---------------- scratch (static device globals; no allocation) -------------
__device__ float g_aggr[6][(size_t)Nn * 256];
__device__ float g_eA[(size_t)Nn * Hh];
__device__ float g_eB[(size_t)Nn * Hh];
__device__ float g_hA[(size_t)Nn * Hh];
__device__ float g_hB[(size_t)Nn * Hh];
__device__ float g_inv[3][Nn];
__device__ float g_Wf[12][Hh * Hh];
__device__ float g_bf[6][Hh];
__device__ float g_stats[2 * Hh];
__device__ float g_prm[2 * Hh];

// ---------------- small helpers ----------------------------------------------
__device__ __forceinline__ ull packf2(float lo, float hi) {
    ull r;
    asm("mov.b64 %0, {%1, %2};" : "=l"(r)
        : "r"(__float_as_uint(lo)), "r"(__float_as_uint(hi)));
    return r;
}
__device__ __forceinline__ void unpackf2(ull v, float& lo, float& hi) {
    unsigned a, b;
    asm("mov.b64 {%0, %1}, %2;" : "=r"(a), "=r"(b) : "l"(v));
    lo = __uint_as_float(a);
    hi = __uint_as_float(b);
}
__device__ __forceinline__ void ffma2(ull& d, ull a, ull b) {
    asm("fma.rn.f32x2 %0, %1, %2, %0;" : "+l"(d) : "l"(a), "l"(b));
}

// ---------------- kernels ----------------------------------------------------

__global__ void count_k(const int* __restrict__ dst, float* __restrict__ cnt) {
    int i = blockIdx.x * blockDim.x + threadIdx.x;
    if (i < Ee) atomicAdd(&cnt[dst[i]], 1.0f);
}

__global__ void inv_k(float* __restrict__ c) {
    int i = blockIdx.x * blockDim.x + threadIdx.x;
    if (i < Nn) c[i] = 1.0f / fmaxf(c[i], 1.0f);
}

// scatter-add: aggr[dst] += x[src], one 16B vector-red per thread
__global__ void scatter_add_k(const float* __restrict__ x,
                              const int* __restrict__ src,
                              const int* __restrict__ dst,
                              float* __restrict__ aggr, int d) {
    int d4 = d >> 2;
    long i = (long)blockIdx.x * blockDim.x + threadIdx.x;
    long total = (long)Ee * d4;
    if (i >= total) return;
    int e = (int)(i / d4);
    int c = (int)(i % d4) * 4;
    int s = __ldg(src + e);
    int dn = __ldg(dst + e);
    float4 v = *(const float4*)(x + (size_t)s * d + c);
    float* p = aggr + (size_t)dn * d + c;
    asm volatile("red.global.add.v4.f32 [%0], {%1,%2,%3,%4};"
                 :: "l"(p), "f"(v.x), "f"(v.y), "f"(v.z), "f"(v.w)
                 : "memory");
}

// ---- batched weight fusion: out[o,k] = sum_j Wupd[o,off+j] * W[j,k] ----
struct FuseWArgs {
    const float* Wupd[12];
    const float* W[12];
    int off[12];
    int dW[12];
    float* out[12];
};
__global__ void fuse_w_all_k(FuseWArgs a) {
    int z = blockIdx.y;
    int o = blockIdx.x;
    int k = threadIdx.x;
    int dW = a.dW[z];
    if (k >= dW) return;
    const float* wrow = a.Wupd[z] + (size_t)o * (2 * Hh) + a.off[z];
    const float* W = a.W[z];
    float s = 0.0f;
#pragma unroll 8
    for (int j = 0; j < Hh; j++) s += wrow[j] * W[(size_t)j * dW + k];
    a.out[z][(size_t)o * dW + k] = s;
}

struct FuseBArgs {
    const float* Wupd[6];
    const float* bdst[6];
    const float* bsrc[6];
    const float* bupd[6];
    float* out[6];
};
__global__ void fuse_bias_all_k(FuseBArgs a) {
    int z = blockIdx.x;
    int o = threadIdx.x;
    const float* wrow = a.Wupd[z] + (size_t)o * (2 * Hh);
    const float* bdst = a.bdst[z];
    const float* bsrc = a.bsrc[z];
    float s = a.bupd[z][o];
#pragma unroll 8
    for (int j = 0; j < Hh; j++) s += wrow[j] * bdst[j] + wrow[Hh + j] * bsrc[j];
    a.out[z][o] = s;
}

// ---- GEMM: C[M x 256] (+)= A[M x K] (row-scaled) @ W[256 x K]^T (+ bias) ----
// 128x128 tile, 256 threads, 8x8 per-thread, packed f32x2 FMA inner loop.
#define TMv 128
#define TNv 128
#define TKv 16
#define LDSD (TMv + 4)   // 132 floats: 528B row stride (16B aligned)
__global__ void __launch_bounds__(256, 2)
gemm_xwT_k(const float* __restrict__ A,
           const float* __restrict__ W,
           const float* __restrict__ bias,
           const float* __restrict__ rowscale,
           float* __restrict__ C, int M, int K, int accumulate) {
    __shared__ float As[TKv][LDSD];
    __shared__ float Ws[TKv][LDSD];
    int tid = threadIdx.x;
    int mBase = blockIdx.x * TMv;
    int nBase = blockIdx.y * TNv;
    int tx = tid & 15;           // n group
    int ty = tid >> 4;           // m group
    int lr = tid >> 2;           // 0..63 (row within half-tile)
    int lc = (tid & 3) * 4;      // k offset 0,4,8,12

    ull acc[8][4];
#pragma unroll
    for (int i = 0; i < 8; i++)
#pragma unroll
        for (int j = 0; j < 4; j++) acc[i][j] = 0ULL;

    for (int k0 = 0; k0 < K; k0 += TKv) {
#pragma unroll
        for (int h = 0; h < 2; h++) {
            int r = lr + h * 64;
            int arow = mBase + r;
            float4 av = make_float4(0.f, 0.f, 0.f, 0.f);
            if (arow < M) {
                av = *(const float4*)(A + (size_t)arow * K + k0 + lc);
                if (rowscale) {
                    float s = rowscale[arow];
                    av.x *= s; av.y *= s; av.z *= s; av.w *= s;
                }
            }
            As[lc + 0][r] = av.x;
            As[lc + 1][r] = av.y;
            As[lc + 2][r] = av.z;
            As[lc + 3][r] = av.w;
            float4 wv = *(const float4*)(W + (size_t)(nBase + r) * K + k0 + lc);
            Ws[lc + 0][r] = wv.x;
            Ws[lc + 1][r] = wv.y;
            Ws[lc + 2][r] = wv.z;
            Ws[lc + 3][r] = wv.w;
        }
        __syncthreads();
#pragma unroll
        for (int kk = 0; kk < TKv; kk++) {
            float4 a0 = *(const float4*)&As[kk][ty * 8];
            float4 a1 = *(const float4*)&As[kk][ty * 8 + 4];
            float4 b0 = *(const float4*)&Ws[kk][tx * 8];
            float4 b1 = *(const float4*)&Ws[kk][tx * 8 + 4];
            ull bp[4];
            bp[0] = packf2(b0.x, b0.y);
            bp[1] = packf2(b0.z, b0.w);
            bp[2] = packf2(b1.x, b1.y);
            bp[3] = packf2(b1.z, b1.w);
            float am[8] = {a0.x, a0.y, a0.z, a0.w, a1.x, a1.y, a1.z, a1.w};
#pragma unroll
            for (int i = 0; i < 8; i++) {
                ull ap = packf2(am[i], am[i]);
                ffma2(acc[i][0], ap, bp[0]);
                ffma2(acc[i][1], ap, bp[1]);
                ffma2(acc[i][2], ap, bp[2]);
                ffma2(acc[i][3], ap, bp[3]);
            }
        }
        __syncthreads();
    }

#pragma unroll
    for (int i = 0; i < 8; i++) {
        int row = mBase + ty * 8 + i;
        if (row >= M) continue;
        float r[8];
        unpackf2(acc[i][0], r[0], r[1]);
        unpackf2(acc[i][1], r[2], r[3]);
        unpackf2(acc[i][2], r[4], r[5]);
        unpackf2(acc[i][3], r[6], r[7]);
        float* cp = C + (size_t)row * 256 + nBase + tx * 8;
        if (bias) {
            const float* bp = bias + nBase + tx * 8;
            float4 b0 = *(const float4*)(bp);
            float4 b1 = *(const float4*)(bp + 4);
            r[0] += b0.x; r[1] += b0.y; r[2] += b0.z; r[3] += b0.w;
            r[4] += b1.x; r[5] += b1.y; r[6] += b1.z; r[7] += b1.w;
        }
        if (accumulate) {
            float4 o0 = *(const float4*)(cp);
            float4 o1 = *(const float4*)(cp + 4);
            r[0] += o0.x; r[1] += o0.y; r[2] += o0.z; r[3] += o0.w;
            r[4] += o1.x; r[5] += o1.y; r[6] += o1.z; r[7] += o1.w;
        }
        *(float4*)(cp) = make_float4(r[0], r[1], r[2], r[3]);
        *(float4*)(cp + 4) = make_float4(r[4], r[5], r[6], r[7]);
    }
}

// ---- BN ----
#define ROWS_PER_BLK 256
__global__ void col_stats_k(const float* __restrict__ x, float prescale,
                            float* __restrict__ sums) {
    int c = threadIdx.x;
    int r0 = blockIdx.x * ROWS_PER_BLK;
    int r1 = r0 + ROWS_PER_BLK;
    if (r1 > Nn) r1 = Nn;
    float s = 0.0f, s2 = 0.0f;
    for (int r = r0; r < r1; r++) {
        float v = x[(size_t)r * Hh + c] * prescale;
        s += v;
        s2 += v * v;
    }
    atomicAdd(&sums[c], s);
    atomicAdd(&sums[Hh + c], s2);
}

__global__ void bn_finalize_k(const float* __restrict__ sums,
                              const float* __restrict__ g,
                              const float* __restrict__ b,
                              float* __restrict__ prm) {
    int c = threadIdx.x;
    float mean = sums[c] / (float)Nn;
    float var = sums[Hh + c] / (float)Nn - mean * mean;
    float sc = g[c] * rsqrtf(var + EPSv);
    prm[c] = sc;
    prm[Hh + c] = b[c] - mean * sc;
}

__global__ void bn_apply_k(const float* __restrict__ x,
                           const float* __restrict__ prm, float prescale,
                           float* __restrict__ y) {
    int i = blockIdx.x * blockDim.x + threadIdx.x;
    if (i >= Nn * (Hh / 4)) return;
    int c = (i & 63) * 4;
    float4 v = *(const float4*)(x + (size_t)i * 4);
    float4 sc = *(const float4*)(prm + c);
    float4 sh = *(const float4*)(prm + Hh + c);
    float t0 = v.x * prescale * sc.x + sh.x;
    float t1 = v.y * prescale * sc.y + sh.y;
    float t2 = v.z * prescale * sc.z + sh.z;
    float t3 = v.w * prescale * sc.w + sh.w;
    float4 r;
    r.x = t0 >= 0.f ? t0 : SLOPEv * t0;
    r.y = t1 >= 0.f ? t1 : SLOPEv * t1;
    r.z = t2 >= 0.f ? t2 : SLOPEv * t2;
    r.w = t3 >= 0.f ? t3 : SLOPEv * t3;
    *(float4*)(y + (size_t)i * 4) = r;
}

// ---------------- host orchestration ----------------------------------------

static void run_gemm(cudaStream_t st, const float* A, const float* W,
                     const float* bias, const float* rs, float* C, int M, int K,
                     int acc) {
    dim3 grid((M + TMv - 1) / TMv, 256 / TNv);
    gemm_xwT_k<<<grid, 256, 0, st>>>(A, W, bias, rs, C, M, K, acc);
}

static void run_scatter(cudaStream_t st, const float* x, const int* src,
                        const int* dst, float* aggr, int d) {
    cudaMemsetAsync(aggr, 0, (size_t)Nn * d * sizeof(float), st);
    long total = (long)Ee * (d / 4);
    int blocks = (int)((total + 255) / 256);
    scatter_add_k<<<blocks, 256, 0, st>>>(x, src, dst, aggr, d);
}

static void run_bn(cudaStream_t st, const float* x, float prescale,
                   const float* g, const float* b, float* y, float* stats,
                   float* prm) {
    cudaMemsetAsync(stats, 0, 2 * Hh * sizeof(float), st);
    col_stats_k<<<(Nn + ROWS_PER_BLK - 1) / ROWS_PER_BLK, Hh, 0, st>>>(x, prescale, stats);
    bn_finalize_k<<<1, Hh, 0, st>>>(stats, g, b, prm);
    bn_apply_k<<<(Nn * (Hh / 4) + 255) / 256, 256, 0, st>>>(x, prm, prescale, y);
}

extern "C" void kernel_launch(void* const* d_in, const int* in_sizes, int n_in,
                              void* d_out, int out_size) {
    const float* x_A = (const float*)d_in[0];
    const float* x_B = (const float*)d_in[1];
    const int* e_ab = (const int*)d_in[2];
    const int* e_ba = (const int*)d_in[3];
    const int* e_aa = (const int*)d_in[4];
    const float* ab_Wsrc1 = (const float*)d_in[5];
    const float* ab_bsrc1 = (const float*)d_in[6];
    const float* ab_Wdst1 = (const float*)d_in[7];
    const float* ab_bdst1 = (const float*)d_in[8];
    const float* ab_Wupd1 = (const float*)d_in[9];
    const float* ab_bupd1 = (const float*)d_in[10];
    const float* ba_Wsrc1 = (const float*)d_in[11];
    const float* ba_bsrc1 = (const float*)d_in[12];
    const float* ba_Wdst1 = (const float*)d_in[13];
    const float* ba_bdst1 = (const float*)d_in[14];
    const float* ba_Wupd1 = (const float*)d_in[15];
    const float* ba_bupd1 = (const float*)d_in[16];
    const float* aa_Wsrc1 = (const float*)d_in[17];
    const float* aa_bsrc1 = (const float*)d_in[18];
    const float* aa_Wdst1 = (const float*)d_in[19];
    const float* aa_bdst1 = (const float*)d_in[20];
    const float* aa_Wupd1 = (const float*)d_in[21];
    const float* aa_bupd1 = (const float*)d_in[22];
    const float* Wsrc2 = (const float*)d_in[23];
    const float* bsrc2 = (const float*)d_in[24];
    const float* Wdst2 = (const float*)d_in[25];
    const float* bdst2 = (const float*)d_in[26];
    const float* Wupd2 = (const float*)d_in[27];
    const float* bupd2 = (const float*)d_in[28];
    const float* bn_g = (const float*)d_in[29];
    const float* bn_b = (const float*)d_in[30];
    float* out = (float*)d_out;

    float *aggr, *eA, *eB, *hA, *hB, *inv, *Wf, *bf, *stats, *prm;
    cudaGetSymbolAddress((void**)&aggr, g_aggr);
    cudaGetSymbolAddress((void**)&eA, g_eA);
    cudaGetSymbolAddress((void**)&eB, g_eB);
    cudaGetSymbolAddress((void**)&hA, g_hA);
    cudaGetSymbolAddress((void**)&hB, g_hB);
    cudaGetSymbolAddress((void**)&inv, g_inv);
    cudaGetSymbolAddress((void**)&Wf, g_Wf);
    cudaGetSymbolAddress((void**)&bf, g_bf);
    cudaGetSymbolAddress((void**)&stats, g_stats);
    cudaGetSymbolAddress((void**)&prm, g_prm);

    float* inv_ab = inv + 0 * Nn;
    float* inv_ba = inv + 1 * Nn;
    float* inv_aa = inv + 2 * Nn;
#define WF(i) (Wf + (size_t)(i) * Hh * Hh)
#define BF(i) (bf + (size_t)(i) * Hh)
#define AGGR(i) (aggr + (size_t)(i) * Nn * 256)

    static cudaStream_t s1 = nullptr;
    static cudaEvent_t evFork, evS[3], evT[3], evHA, evHB;
    if (!s1) {
        cudaStreamCreateWithFlags(&s1, cudaStreamNonBlocking);
        cudaEventCreateWithFlags(&evFork, cudaEventDisableTiming);
        cudaEventCreateWithFlags(&evHA, cudaEventDisableTiming);
        cudaEventCreateWithFlags(&evHB, cudaEventDisableTiming);
        for (int i = 0; i < 3; i++) {
            cudaEventCreateWithFlags(&evS[i], cudaEventDisableTiming);
            cudaEventCreateWithFlags(&evT[i], cudaEventDisableTiming);
        }
    }
    cudaStream_t s0 = 0;

    cudaEventRecord(evFork, s0);
    cudaStreamWaitEvent(s1, evFork, 0);

    // ================= side stream: degrees + layer-1 scatters =============
    cudaMemsetAsync(inv, 0, 3 * Nn * sizeof(float), s1);
    count_k<<<(Ee + 255) / 256, 256, 0, s1>>>(e_ab + Ee, inv_ab);
    count_k<<<(Ee + 255) / 256, 256, 0, s1>>>(e_ba + Ee, inv_ba);
    count_k<<<(Ee + 255) / 256, 256, 0, s1>>>(e_aa + Ee, inv_aa);
    inv_k<<<(Nn + 255) / 256, 256, 0, s1>>>(inv_ab);
    inv_k<<<(Nn + 255) / 256, 256, 0, s1>>>(inv_ba);
    inv_k<<<(Nn + 255) / 256, 256, 0, s1>>>(inv_aa);

    run_scatter(s1, x_A, e_ab, e_ab + Ee, AGGR(0), DAv);
    cudaEventRecord(evS[0], s1);
    run_scatter(s1, x_B, e_ba, e_ba + Ee, AGGR(1), DBv);
    cudaEventRecord(evS[1], s1);
    run_scatter(s1, x_A, e_aa, e_aa + Ee, AGGR(2), DAv);
    cudaEventRecord(evS[2], s1);

    // ================= main stream: batched weight fusion ==================
    {
        FuseWArgs fw;
        const float* wu[6] = {ab_Wupd1, ba_Wupd1, aa_Wupd1,
                              Wupd2 + 0 * (size_t)Hh * 2 * Hh,
                              Wupd2 + 1 * (size_t)Hh * 2 * Hh,
                              Wupd2 + 2 * (size_t)Hh * 2 * Hh};
        const float* wd[6] = {ab_Wdst1, ba_Wdst1, aa_Wdst1,
                              Wdst2 + 0 * (size_t)Hh * Hh,
                              Wdst2 + 1 * (size_t)Hh * Hh,
                              Wdst2 + 2 * (size_t)Hh * Hh};
        const float* ws[6] = {ab_Wsrc1, ba_Wsrc1, aa_Wsrc1,
                              Wsrc2 + 0 * (size_t)Hh * Hh,
                              Wsrc2 + 1 * (size_t)Hh * Hh,
                              Wsrc2 + 2 * (size_t)Hh * Hh};
        int dd[6] = {DBv, DAv, DAv, Hh, Hh, Hh};
        int ds[6] = {DAv, DBv, DAv, Hh, Hh, Hh};
        for (int c = 0; c < 6; c++) {
            fw.Wupd[2 * c] = wu[c]; fw.W[2 * c] = wd[c];
            fw.off[2 * c] = 0;      fw.dW[2 * c] = dd[c];
            fw.out[2 * c] = WF(2 * c);
            fw.Wupd[2 * c + 1] = wu[c]; fw.W[2 * c + 1] = ws[c];
            fw.off[2 * c + 1] = Hh;     fw.dW[2 * c + 1] = ds[c];
            fw.out[2 * c + 1] = WF(2 * c + 1);
        }
        fuse_w_all_k<<<dim3(Hh, 12), 256, 0, s0>>>(fw);

        FuseBArgs fb;
        const float* bd[6] = {ab_bdst1, ba_bdst1, aa_bdst1,
                              bdst2 + 0 * Hh, bdst2 + 1 * Hh, bdst2 + 2 * Hh};
        const float* bs[6] = {ab_bsrc1, ba_bsrc1, aa_bsrc1,
                              bsrc2 + 0 * Hh, bsrc2 + 1 * Hh, bsrc2 + 2 * Hh};
        const float* bu[6] = {ab_bupd1, ba_bupd1, aa_bupd1,
                              bupd2 + 0 * Hh, bupd2 + 1 * Hh, bupd2 + 2 * Hh};
        for (int c = 0; c < 6; c++) {
            fb.Wupd[c] = wu[c]; fb.bdst[c] = bd[c]; fb.bsrc[c] = bs[c];
            fb.bupd[c] = bu[c]; fb.out[c] = BF(c);
        }
        fuse_bias_all_k<<<6, Hh, 0, s0>>>(fb);
    }

    // ================= main stream: layer-1 GEMMs + BN =====================
    run_gemm(s0, x_A, WF(2), BF(1), nullptr, eA, Nn, DAv, 0);   // ba dst
    run_gemm(s0, x_A, WF(4), BF(2), nullptr, eA, Nn, DAv, 1);   // aa dst
    run_gemm(s0, x_B, WF(0), BF(0), nullptr, eB, Nn, DBv, 0);   // ab dst
    cudaStreamWaitEvent(s0, evS[1], 0);
    run_gemm(s0, AGGR(1), WF(3), nullptr, inv_ba, eA, Nn, DBv, 1);
    cudaStreamWaitEvent(s0, evS[2], 0);
    run_gemm(s0, AGGR(2), WF(5), nullptr, inv_aa, eA, Nn, DAv, 1);
    run_bn(s0, eA, 0.5f, bn_g + 0 * Hh, bn_b + 0 * Hh, hA, stats, prm);
    cudaEventRecord(evHA, s0);
    cudaStreamWaitEvent(s0, evS[0], 0);
    run_gemm(s0, AGGR(0), WF(1), nullptr, inv_ab, eB, Nn, DAv, 1);
    run_bn(s0, eB, 1.0f, bn_g + 1 * Hh, bn_b + 1 * Hh, hB, stats, prm);
    cudaEventRecord(evHB, s0);

    // ================= side stream: layer-2 scatters =======================
    cudaStreamWaitEvent(s1, evHA, 0);
    run_scatter(s1, hA, e_ab, e_ab + Ee, AGGR(3), Hh);
    cudaEventRecord(evT[0], s1);
    run_scatter(s1, hA, e_aa, e_aa + Ee, AGGR(5), Hh);
    cudaEventRecord(evT[2], s1);
    cudaStreamWaitEvent(s1, evHB, 0);
    run_scatter(s1, hB, e_ba, e_ba + Ee, AGGR(4), Hh);
    cudaEventRecord(evT[1], s1);

    // ================= main stream: layer-2 GEMMs + BN =====================
    run_gemm(s0, hA, WF(8), BF(4), nullptr, eA, Nn, Hh, 0);     // ba dst
    run_gemm(s0, hA, WF(10), BF(5), nullptr, eA, Nn, Hh, 1);    // aa dst
    run_gemm(s0, hB, WF(6), BF(3), nullptr, eB, Nn, Hh, 0);     // ab dst
    cudaStreamWaitEvent(s0, evT[1], 0);
    run_gemm(s0, AGGR(4), WF(9), nullptr, inv_ba, eA, Nn, Hh, 1);
    cudaStreamWaitEvent(s0, evT[2], 0);
    run_gemm(s0, AGGR(5), WF(11), nullptr, inv_aa, eA, Nn, Hh, 1);
    run_bn(s0, eA, 0.5f, bn_g + 2 * Hh, bn_b + 2 * Hh, out, stats, prm);
    cudaStreamWaitEvent(s0, evT[0], 0);
    run_gemm(s0, AGGR(3), WF(7), nullptr, inv_ab, eB, Nn, Hh, 1);
    run_bn(s0, eB, 1.0f, bn_g + 3 * Hh, bn_b + 3 * Hh, out + (size_t)Nn * Hh, stats, prm);
}

// round 4
// speedup vs baseline: 1.8247x; 1.0289x over previous
#include <cuda_runtime.h>

#define Nn 50000
#define Ee 800000
#define DAv 256
#define DBv 128
#define Hh 256
#define EPSv 1e-5f
#define SLOPEv 0.01f

typedef unsigned long long ull;

// ---------------- scratch (static device globals; no allocation) -------------
__device__ float g_aggr[6][(size_t)Nn * 256];
__device__ float g_eA[(size_t)Nn * Hh];
__device__ float g_eB[(size_t)Nn * Hh];
__device__ float g_hA[(size_t)Nn * Hh];
__device__ float g_hB[(size_t)Nn * Hh];
__device__ float g_cnt[3][Nn];                  // dst-degree per edge type
__device__ float g_Wf[12][Hh * Hh];
__device__ float g_bf[6][Hh];
__device__ float g_stats[2 * Hh];
__device__ float g_prm[2 * Hh];

// ---------------- small helpers ----------------------------------------------
__device__ __forceinline__ ull packf2(float lo, float hi) {
    ull r;
    asm("mov.b64 %0, {%1, %2};" : "=l"(r)
        : "r"(__float_as_uint(lo)), "r"(__float_as_uint(hi)));
    return r;
}
__device__ __forceinline__ void unpackf2(ull v, float& lo, float& hi) {
    unsigned a, b;
    asm("mov.b64 {%0, %1}, %2;" : "=r"(a), "=r"(b) : "l"(v));
    lo = __uint_as_float(a);
    hi = __uint_as_float(b);
}
__device__ __forceinline__ void ffma2(ull& d, ull a, ull b) {
    asm("fma.rn.f32x2 %0, %1, %2, %0;" : "+l"(d) : "l"(a), "l"(b));
}

// ---------------- kernels ----------------------------------------------------

// zero a float4 span (grid-stride)
__global__ void zero_k(float4* __restrict__ p, long n4) {
    long i = (long)blockIdx.x * blockDim.x + threadIdx.x;
    long stride = (long)gridDim.x * blockDim.x;
    float4 z = make_float4(0.f, 0.f, 0.f, 0.f);
    for (; i < n4; i += stride) p[i] = z;
}

// scatter-add: aggr[dst] += x[src]; optionally count dst degrees
template <int D, bool COUNT>
__global__ void scatter_k(const float* __restrict__ x,
                          const int* __restrict__ src,
                          const int* __restrict__ dst,
                          float* __restrict__ aggr,
                          float* __restrict__ cnt) {
    constexpr int D4 = D / 4;
    long i = (long)blockIdx.x * blockDim.x + threadIdx.x;
    if (i >= (long)Ee * D4) return;
    int e = (int)(i / D4);
    int c = ((int)i & (D4 - 1)) * 4;
    int s = __ldg(src + e);
    int dn = __ldg(dst + e);
    if (COUNT && c == 0) atomicAdd(cnt + dn, 1.0f);
    float4 v = *(const float4*)(x + (size_t)s * D + c);
    float* p = aggr + (size_t)dn * D + c;
    asm volatile("red.global.add.v4.f32 [%0], {%1,%2,%3,%4};"
                 :: "l"(p), "f"(v.x), "f"(v.y), "f"(v.z), "f"(v.w)
                 : "memory");
}

// ---- batched weight fusion ----
struct FuseWArgs {
    const float* Wupd[12];
    const float* W[12];
    int off[12];
    int dW[12];
    float* out[12];
};
__global__ void fuse_w_all_k(FuseWArgs a) {
    int z = blockIdx.y;
    int o = blockIdx.x;
    int k = threadIdx.x;
    int dW = a.dW[z];
    if (k >= dW) return;
    const float* wrow = a.Wupd[z] + (size_t)o * (2 * Hh) + a.off[z];
    const float* W = a.W[z];
    float s = 0.0f;
#pragma unroll 8
    for (int j = 0; j < Hh; j++) s += wrow[j] * W[(size_t)j * dW + k];
    a.out[z][(size_t)o * dW + k] = s;
}

struct FuseBArgs {
    const float* Wupd[6];
    const float* bdst[6];
    const float* bsrc[6];
    const float* bupd[6];
    float* out[6];
};
__global__ void fuse_bias_all_k(FuseBArgs a) {
    int z = blockIdx.x;
    int o = threadIdx.x;
    const float* wrow = a.Wupd[z] + (size_t)o * (2 * Hh);
    const float* bdst = a.bdst[z];
    const float* bsrc = a.bsrc[z];
    float s = a.bupd[z][o];
#pragma unroll 8
    for (int j = 0; j < Hh; j++) s += wrow[j] * bdst[j] + wrow[Hh + j] * bsrc[j];
    a.out[z][o] = s;
}

// ---- GEMM: C[M x 256] (+)= A[M x K] (row-scaled by 1/max(cnt,1)) @ W^T (+bias)
// 128x128 tile, 256 threads, 8x8 micro-tile, f32x2 FMA, double-buffered smem.
#define TMv 128
#define TNv 128
#define TKv 16
#define LDSD (TMv + 4)
#define GEMM_SMEM (2 * 2 * TKv * LDSD * 4)
__global__ void __launch_bounds__(256, 2)
gemm_xwT_k(const float* __restrict__ A,
           const float* __restrict__ W,
           const float* __restrict__ bias,
           const float* __restrict__ cnt,
           float* __restrict__ C, int M, int K, int accumulate) {
    extern __shared__ float sm[];
    const int BUF = 2 * TKv * LDSD;      // one buffer = As + Ws
    int tid = threadIdx.x;
    int mBase = blockIdx.x * TMv;
    int nBase = blockIdx.y * TNv;
    int tx = tid & 15;
    int ty = tid >> 4;
    int lr = tid >> 2;
    int lc = (tid & 3) * 4;

    ull acc[8][4];
#pragma unroll
    for (int i = 0; i < 8; i++)
#pragma unroll
        for (int j = 0; j < 4; j++) acc[i][j] = 0ULL;

    float4 avr[2], wvr[2];
    auto gload = [&](int k0) {
#pragma unroll
        for (int h = 0; h < 2; h++) {
            int r = lr + h * 64;
            int arow = mBase + r;
            float4 av = make_float4(0.f, 0.f, 0.f, 0.f);
            if (arow < M) {
                av = *(const float4*)(A + (size_t)arow * K + k0 + lc);
                if (cnt) {
                    float s = 1.0f / fmaxf(cnt[arow], 1.0f);
                    av.x *= s; av.y *= s; av.z *= s; av.w *= s;
                }
            }
            avr[h] = av;
            wvr[h] = *(const float4*)(W + (size_t)(nBase + r) * K + k0 + lc);
        }
    };
    auto sstore = [&](int b) {
        float* As = sm + b * BUF;
        float* Ws = As + TKv * LDSD;
#pragma unroll
        for (int h = 0; h < 2; h++) {
            int r = lr + h * 64;
            As[(lc + 0) * LDSD + r] = avr[h].x;
            As[(lc + 1) * LDSD + r] = avr[h].y;
            As[(lc + 2) * LDSD + r] = avr[h].z;
            As[(lc + 3) * LDSD + r] = avr[h].w;
            Ws[(lc + 0) * LDSD + r] = wvr[h].x;
            Ws[(lc + 1) * LDSD + r] = wvr[h].y;
            Ws[(lc + 2) * LDSD + r] = wvr[h].z;
            Ws[(lc + 3) * LDSD + r] = wvr[h].w;
        }
    };

    gload(0);
    sstore(0);
    __syncthreads();

    int nslabs = K / TKv;
    for (int s = 0; s < nslabs; s++) {
        int cur = s & 1;
        if (s + 1 < nslabs) gload((s + 1) * TKv);
        const float* As = sm + cur * BUF;
        const float* Ws = As + TKv * LDSD;
#pragma unroll
        for (int kk = 0; kk < TKv; kk++) {
            const float* arow = As + kk * LDSD + ty * 8;
            const float* wrow = Ws + kk * LDSD + tx * 8;
            float4 a0 = *(const float4*)(arow);
            float4 a1 = *(const float4*)(arow + 4);
            ulonglong2 w01 = *(const ulonglong2*)(wrow);
            ulonglong2 w23 = *(const ulonglong2*)(wrow + 4);
            float am[8] = {a0.x, a0.y, a0.z, a0.w, a1.x, a1.y, a1.z, a1.w};
#pragma unroll
            for (int i = 0; i < 8; i++) {
                ull ap = packf2(am[i], am[i]);
                ffma2(acc[i][0], ap, w01.x);
                ffma2(acc[i][1], ap, w01.y);
                ffma2(acc[i][2], ap, w23.x);
                ffma2(acc[i][3], ap, w23.y);
            }
        }
        if (s + 1 < nslabs) sstore((s + 1) & 1);
        __syncthreads();
    }

#pragma unroll
    for (int i = 0; i < 8; i++) {
        int row = mBase + ty * 8 + i;
        if (row >= M) continue;
        float r[8];
        unpackf2(acc[i][0], r[0], r[1]);
        unpackf2(acc[i][1], r[2], r[3]);
        unpackf2(acc[i][2], r[4], r[5]);
        unpackf2(acc[i][3], r[6], r[7]);
        float* cp = C + (size_t)row * 256 + nBase + tx * 8;
        if (bias) {
            const float* bp = bias + nBase + tx * 8;
            float4 b0 = *(const float4*)(bp);
            float4 b1 = *(const float4*)(bp + 4);
            r[0] += b0.x; r[1] += b0.y; r[2] += b0.z; r[3] += b0.w;
            r[4] += b1.x; r[5] += b1.y; r[6] += b1.z; r[7] += b1.w;
        }
        if (accumulate) {
            float4 o0 = *(const float4*)(cp);
            float4 o1 = *(const float4*)(cp + 4);
            r[0] += o0.x; r[1] += o0.y; r[2] += o0.z; r[3] += o0.w;
            r[4] += o1.x; r[5] += o1.y; r[6] += o1.z; r[7] += o1.w;
        }
        *(float4*)(cp) = make_float4(r[0], r[1], r[2], r[3]);
        *(float4*)(cp + 4) = make_float4(r[4], r[5], r[6], r[7]);
    }
}

// ---- BN ----
#define ROWS_PER_BLK 256
__global__ void col_stats_k(const float* __restrict__ x, float prescale,
                            float* __restrict__ sums) {
    int c = threadIdx.x;
    int r0 = blockIdx.x * ROWS_PER_BLK;
    int r1 = r0 + ROWS_PER_BLK;
    if (r1 > Nn) r1 = Nn;
    float s = 0.0f, s2 = 0.0f;
    for (int r = r0; r < r1; r++) {
        float v = x[(size_t)r * Hh + c] * prescale;
        s += v;
        s2 += v * v;
    }
    atomicAdd(&sums[c], s);
    atomicAdd(&sums[Hh + c], s2);
}

__global__ void bn_finalize_k(const float* __restrict__ sums,
                              const float* __restrict__ g,
                              const float* __restrict__ b,
                              float* __restrict__ prm) {
    int c = threadIdx.x;
    float mean = sums[c] / (float)Nn;
    float var = sums[Hh + c] / (float)Nn - mean * mean;
    float sc = g[c] * rsqrtf(var + EPSv);
    prm[c] = sc;
    prm[Hh + c] = b[c] - mean * sc;
}

__global__ void bn_apply_k(const float* __restrict__ x,
                           const float* __restrict__ prm, float prescale,
                           float* __restrict__ y) {
    int i = blockIdx.x * blockDim.x + threadIdx.x;
    if (i >= Nn * (Hh / 4)) return;
    int c = (i & 63) * 4;
    float4 v = *(const float4*)(x + (size_t)i * 4);
    float4 sc = *(const float4*)(prm + c);
    float4 sh = *(const float4*)(prm + Hh + c);
    float t0 = v.x * prescale * sc.x + sh.x;
    float t1 = v.y * prescale * sc.y + sh.y;
    float t2 = v.z * prescale * sc.z + sh.z;
    float t3 = v.w * prescale * sc.w + sh.w;
    float4 r;
    r.x = t0 >= 0.f ? t0 : SLOPEv * t0;
    r.y = t1 >= 0.f ? t1 : SLOPEv * t1;
    r.z = t2 >= 0.f ? t2 : SLOPEv * t2;
    r.w = t3 >= 0.f ? t3 : SLOPEv * t3;
    *(float4*)(y + (size_t)i * 4) = r;
}

// ---------------- host orchestration ----------------------------------------

static void run_gemm(cudaStream_t st, const float* A, const float* W,
                     const float* bias, const float* cnt, float* C, int M,
                     int K, int acc) {
    dim3 grid((M + TMv - 1) / TMv, 256 / TNv);
    gemm_xwT_k<<<grid, 256, GEMM_SMEM, st>>>(A, W, bias, cnt, C, M, K, acc);
}

template <int D, bool COUNT>
static void run_scatter(cudaStream_t st, const float* x, const int* src,
                        const int* dst, float* aggr, float* cnt) {
    long total = (long)Ee * (D / 4);
    int blocks = (int)((total + 255) / 256);
    scatter_k<D, COUNT><<<blocks, 256, 0, st>>>(x, src, dst, aggr, cnt);
}

static void run_bn(cudaStream_t st, const float* x, float prescale,
                   const float* g, const float* b, float* y, float* stats,
                   float* prm) {
    cudaMemsetAsync(stats, 0, 2 * Hh * sizeof(float), st);
    col_stats_k<<<(Nn + ROWS_PER_BLK - 1) / ROWS_PER_BLK, Hh, 0, st>>>(x, prescale, stats);
    bn_finalize_k<<<1, Hh, 0, st>>>(stats, g, b, prm);
    bn_apply_k<<<(Nn * (Hh / 4) + 255) / 256, 256, 0, st>>>(x, prm, prescale, y);
}

extern "C" void kernel_launch(void* const* d_in, const int* in_sizes, int n_in,
                              void* d_out, int out_size) {
    const float* x_A = (const float*)d_in[0];
    const float* x_B = (const float*)d_in[1];
    const int* e_ab = (const int*)d_in[2];
    const int* e_ba = (const int*)d_in[3];
    const int* e_aa = (const int*)d_in[4];
    const float* ab_Wsrc1 = (const float*)d_in[5];
    const float* ab_bsrc1 = (const float*)d_in[6];
    const float* ab_Wdst1 = (const float*)d_in[7];
    const float* ab_bdst1 = (const float*)d_in[8];
    const float* ab_Wupd1 = (const float*)d_in[9];
    const float* ab_bupd1 = (const float*)d_in[10];
    const float* ba_Wsrc1 = (const float*)d_in[11];
    const float* ba_bsrc1 = (const float*)d_in[12];
    const float* ba_Wdst1 = (const float*)d_in[13];
    const float* ba_bdst1 = (const float*)d_in[14];
    const float* ba_Wupd1 = (const float*)d_in[15];
    const float* ba_bupd1 = (const float*)d_in[16];
    const float* aa_Wsrc1 = (const float*)d_in[17];
    const float* aa_bsrc1 = (const float*)d_in[18];
    const float* aa_Wdst1 = (const float*)d_in[19];
    const float* aa_bdst1 = (const float*)d_in[20];
    const float* aa_Wupd1 = (const float*)d_in[21];
    const float* aa_bupd1 = (const float*)d_in[22];
    const float* Wsrc2 = (const float*)d_in[23];
    const float* bsrc2 = (const float*)d_in[24];
    const float* Wdst2 = (const float*)d_in[25];
    const float* bdst2 = (const float*)d_in[26];
    const float* Wupd2 = (const float*)d_in[27];
    const float* bupd2 = (const float*)d_in[28];
    const float* bn_g = (const float*)d_in[29];
    const float* bn_b = (const float*)d_in[30];
    float* out = (float*)d_out;

    float *aggr, *eA, *eB, *hA, *hB, *cnt, *Wf, *bf, *stats, *prm;
    cudaGetSymbolAddress((void**)&aggr, g_aggr);
    cudaGetSymbolAddress((void**)&eA, g_eA);
    cudaGetSymbolAddress((void**)&eB, g_eB);
    cudaGetSymbolAddress((void**)&hA, g_hA);
    cudaGetSymbolAddress((void**)&hB, g_hB);
    cudaGetSymbolAddress((void**)&cnt, g_cnt);
    cudaGetSymbolAddress((void**)&Wf, g_Wf);
    cudaGetSymbolAddress((void**)&bf, g_bf);
    cudaGetSymbolAddress((void**)&stats, g_stats);
    cudaGetSymbolAddress((void**)&prm, g_prm);

    float* cnt_ab = cnt + 0 * Nn;
    float* cnt_ba = cnt + 1 * Nn;
    float* cnt_aa = cnt + 2 * Nn;
#define WF(i) (Wf + (size_t)(i) * Hh * Hh)
#define BF(i) (bf + (size_t)(i) * Hh)
#define AGGR(i) (aggr + (size_t)(i) * Nn * 256)

    static cudaStream_t s1 = nullptr;
    static cudaEvent_t evFork, evS0, evS1, evS2, evHA, evHB, evTba, evTaa, evTab;
    if (!s1) {
        cudaStreamCreateWithFlags(&s1, cudaStreamNonBlocking);
        cudaEventCreateWithFlags(&evFork, cudaEventDisableTiming);
        cudaEventCreateWithFlags(&evS0, cudaEventDisableTiming);
        cudaEventCreateWithFlags(&evS1, cudaEventDisableTiming);
        cudaEventCreateWithFlags(&evS2, cudaEventDisableTiming);
        cudaEventCreateWithFlags(&evHA, cudaEventDisableTiming);
        cudaEventCreateWithFlags(&evHB, cudaEventDisableTiming);
        cudaEventCreateWithFlags(&evTba, cudaEventDisableTiming);
        cudaEventCreateWithFlags(&evTaa, cudaEventDisableTiming);
        cudaEventCreateWithFlags(&evTab, cudaEventDisableTiming);
        cudaFuncSetAttribute(gemm_xwT_k,
                             cudaFuncAttributeMaxDynamicSharedMemorySize,
                             GEMM_SMEM);
    }
    cudaStream_t s0 = 0;

    cudaEventRecord(evFork, s0);
    cudaStreamWaitEvent(s1, evFork, 0);

    // ===== main stream: batched weight fusion (kernels #1, #2) =============
    {
        FuseWArgs fw;
        const float* wu[6] = {ab_Wupd1, ba_Wupd1, aa_Wupd1,
                              Wupd2 + 0 * (size_t)Hh * 2 * Hh,
                              Wupd2 + 1 * (size_t)Hh * 2 * Hh,
                              Wupd2 + 2 * (size_t)Hh * 2 * Hh};
        const float* wd[6] = {ab_Wdst1, ba_Wdst1, aa_Wdst1,
                              Wdst2 + 0 * (size_t)Hh * Hh,
                              Wdst2 + 1 * (size_t)Hh * Hh,
                              Wdst2 + 2 * (size_t)Hh * Hh};
        const float* ws[6] = {ab_Wsrc1, ba_Wsrc1, aa_Wsrc1,
                              Wsrc2 + 0 * (size_t)Hh * Hh,
                              Wsrc2 + 1 * (size_t)Hh * Hh,
                              Wsrc2 + 2 * (size_t)Hh * Hh};
        int dd[6] = {DBv, DAv, DAv, Hh, Hh, Hh};
        int ds[6] = {DAv, DBv, DAv, Hh, Hh, Hh};
        for (int c = 0; c < 6; c++) {
            fw.Wupd[2 * c] = wu[c]; fw.W[2 * c] = wd[c];
            fw.off[2 * c] = 0;      fw.dW[2 * c] = dd[c];
            fw.out[2 * c] = WF(2 * c);
            fw.Wupd[2 * c + 1] = wu[c]; fw.W[2 * c + 1] = ws[c];
            fw.off[2 * c + 1] = Hh;     fw.dW[2 * c + 1] = ds[c];
            fw.out[2 * c + 1] = WF(2 * c + 1);
        }
        fuse_w_all_k<<<dim3(Hh, 12), 256, 0, s0>>>(fw);

        FuseBArgs fb;
        const float* bd[6] = {ab_bdst1, ba_bdst1, aa_bdst1,
                              bdst2 + 0 * Hh, bdst2 + 1 * Hh, bdst2 + 2 * Hh};
        const float* bs[6] = {ab_bsrc1, ba_bsrc1, aa_bsrc1,
                              bsrc2 + 0 * Hh, bsrc2 + 1 * Hh, bsrc2 + 2 * Hh};
        const float* bu[6] = {ab_bupd1, ba_bupd1, aa_bupd1,
                              bupd2 + 0 * Hh, bupd2 + 1 * Hh, bupd2 + 2 * Hh};
        for (int c = 0; c < 6; c++) {
            fb.Wupd[c] = wu[c]; fb.bdst[c] = bd[c]; fb.bsrc[c] = bs[c];
            fb.bupd[c] = bu[c]; fb.out[c] = BF(c);
        }
        fuse_bias_all_k<<<6, Hh, 0, s0>>>(fb);
    }

    // ===== side stream: zero + L1 scatters (kernels #3..#6) ================
    {
        long n4 = ((long)3 * Nn + (long)3 * Nn * 256) / 4;  // cnt + aggr0..2
        zero_k<<<4096, 256, 0, s1>>>((float4*)cnt, (3L * Nn) / 4);
        zero_k<<<8192, 256, 0, s1>>>((float4*)AGGR(0), (3L * Nn * 256) / 4);
        (void)n4;
    }
    run_scatter<DAv, true>(s1, x_A, e_ab, e_ab + Ee, AGGR(0), cnt_ab);
    cudaEventRecord(evS0, s1);
    run_scatter<DBv, true>(s1, x_B, e_ba, e_ba + Ee, AGGR(1), cnt_ba);
    cudaEventRecord(evS1, s1);
    run_scatter<DAv, true>(s1, x_A, e_aa, e_aa + Ee, AGGR(2), cnt_aa);
    cudaEventRecord(evS2, s1);
    zero_k<<<8192, 256, 0, s1>>>((float4*)AGGR(3), (3L * Nn * 256) / 4);

    // ===== main stream: hB first ===========================================
    run_gemm(s0, x_B, WF(0), BF(0), nullptr, eB, Nn, DBv, 0);   // ab dst
    cudaStreamWaitEvent(s0, evS0, 0);
    run_gemm(s0, AGGR(0), WF(1), nullptr, cnt_ab, eB, Nn, DAv, 1);
    run_bn(s0, eB, 1.0f, bn_g + 1 * Hh, bn_b + 1 * Hh, hB, stats, prm);
    cudaEventRecord(evHB, s0);

    // ===== main stream: hA =================================================
    run_gemm(s0, x_A, WF(2), BF(1), nullptr, eA, Nn, DAv, 0);   // ba dst
    run_gemm(s0, x_A, WF(4), BF(2), nullptr, eA, Nn, DAv, 1);   // aa dst
    cudaStreamWaitEvent(s0, evS1, 0);
    run_gemm(s0, AGGR(1), WF(3), nullptr, cnt_ba, eA, Nn, DBv, 1);
    cudaStreamWaitEvent(s0, evS2, 0);
    run_gemm(s0, AGGR(2), WF(5), nullptr, cnt_aa, eA, Nn, DAv, 1);
    run_bn(s0, eA, 0.5f, bn_g + 0 * Hh, bn_b + 0 * Hh, hA, stats, prm);
    cudaEventRecord(evHA, s0);

    // ===== side stream: L2 scatters (ba first, ab last) ====================
    cudaStreamWaitEvent(s1, evHB, 0);
    run_scatter<Hh, false>(s1, hB, e_ba, e_ba + Ee, AGGR(4), nullptr);
    cudaEventRecord(evTba, s1);
    cudaStreamWaitEvent(s1, evHA, 0);
    run_scatter<Hh, false>(s1, hA, e_aa, e_aa + Ee, AGGR(5), nullptr);
    cudaEventRecord(evTaa, s1);
    run_scatter<Hh, false>(s1, hA, e_ab, e_ab + Ee, AGGR(3), nullptr);
    cudaEventRecord(evTab, s1);

    // ===== main stream: layer-2 GEMMs + BN =================================
    run_gemm(s0, hA, WF(8), BF(4), nullptr, eA, Nn, Hh, 0);     // ba dst
    run_gemm(s0, hA, WF(10), BF(5), nullptr, eA, Nn, Hh, 1);    // aa dst
    run_gemm(s0, hB, WF(6), BF(3), nullptr, eB, Nn, Hh, 0);     // ab dst
    cudaStreamWaitEvent(s0, evTba, 0);
    run_gemm(s0, AGGR(4), WF(9), nullptr, cnt_ba, eA, Nn, Hh, 1);
    cudaStreamWaitEvent(s0, evTaa, 0);
    run_gemm(s0, AGGR(5), WF(11), nullptr, cnt_aa, eA, Nn, Hh, 1);
    run_bn(s0, eA, 0.5f, bn_g + 2 * Hh, bn_b + 2 * Hh, out, stats, prm);
    cudaStreamWaitEvent(s0, evTab, 0);
    run_gemm(s0, AGGR(3), WF(7), nullptr, cnt_ab, eB, Nn, Hh, 1);
    run_bn(s0, eB, 1.0f, bn_g + 3 * Hh, bn_b + 3 * Hh, out + (size_t)Nn * Hh, stats, prm);
}

// round 5
// speedup vs baseline: 1.8800x; 1.0303x over previous
#include <cuda_runtime.h>

#define Nn 50000
#define Ee 800000
#define DAv 256
#define DBv 128
#define Hh 256
#define EPSv 1e-5f
#define SLOPEv 0.01f

typedef unsigned long long ull;

// ---------------- scratch (static device globals; no allocation) -------------
__device__ float g_t[6][(size_t)Nn * 256];      // per-conv transformed src feats
__device__ float g_aggr[4][(size_t)Nn * 256];   // A1, B1, A2, B2 scatter sums
__device__ float g_eA[(size_t)Nn * Hh];
__device__ float g_eB[(size_t)Nn * Hh];
__device__ float g_hA[(size_t)Nn * Hh];
__device__ float g_hB[(size_t)Nn * Hh];
__device__ float g_inv[3][Nn];                  // 1/max(deg,1) per edge type
__device__ float g_Wf[12][Hh * Hh];
__device__ float g_bf[6][Hh];
__device__ float g_Wc[2][Hh * Hh];              // combined dst weights (L1, L2)
__device__ float g_bc[2][Hh];
__device__ float g_stats[2 * Hh];
__device__ float g_prm[2 * Hh];

// ---------------- small helpers ----------------------------------------------
__device__ __forceinline__ ull packf2(float lo, float hi) {
    ull r;
    asm("mov.b64 %0, {%1, %2};" : "=l"(r)
        : "r"(__float_as_uint(lo)), "r"(__float_as_uint(hi)));
    return r;
}
__device__ __forceinline__ void unpackf2(ull v, float& lo, float& hi) {
    unsigned a, b;
    asm("mov.b64 {%0, %1}, %2;" : "=r"(a), "=r"(b) : "l"(v));
    lo = __uint_as_float(a);
    hi = __uint_as_float(b);
}
__device__ __forceinline__ void ffma2(ull& d, ull a, ull b) {
    asm("fma.rn.f32x2 %0, %1, %2, %0;" : "+l"(d) : "l"(a), "l"(b));
}

// ---------------- kernels ----------------------------------------------------

__global__ void zero_k(float4* __restrict__ p, long n4) {
    long i = (long)blockIdx.x * blockDim.x + threadIdx.x;
    long stride = (long)gridDim.x * blockDim.x;
    float4 z = make_float4(0.f, 0.f, 0.f, 0.f);
    for (; i < n4; i += stride) p[i] = z;
}

__global__ void count_k(const int* __restrict__ dst, float* __restrict__ cnt) {
    int i = blockIdx.x * blockDim.x + threadIdx.x;
    if (i < Ee) atomicAdd(&cnt[dst[i]], 1.0f);
}

__global__ void inv_k(float* __restrict__ c, int n) {
    int i = blockIdx.x * blockDim.x + threadIdx.x;
    if (i < n) c[i] = 1.0f / fmaxf(c[i], 1.0f);
}

// scatter: aggr[dst] += t[src] * inv[dst]   (prescaled mean contribution)
__global__ void scatter_pre_k(const float* __restrict__ t,
                              const int* __restrict__ src,
                              const int* __restrict__ dst,
                              const float* __restrict__ inv,
                              float* __restrict__ aggr) {
    long i = (long)blockIdx.x * blockDim.x + threadIdx.x;
    if (i >= (long)Ee * 64) return;
    int e = (int)(i >> 6);
    int c = ((int)i & 63) * 4;
    int s = __ldg(src + e);
    int dn = __ldg(dst + e);
    float w = __ldg(inv + dn);
    float4 v = *(const float4*)(t + (size_t)s * 256 + c);
    v.x *= w; v.y *= w; v.z *= w; v.w *= w;
    float* p = aggr + (size_t)dn * 256 + c;
    asm volatile("red.global.add.v4.f32 [%0], {%1,%2,%3,%4};"
                 :: "l"(p), "f"(v.x), "f"(v.y), "f"(v.z), "f"(v.w)
                 : "memory");
}

// ---- batched weight fusion ----
struct FuseWArgs {
    const float* Wupd[12];
    const float* W[12];
    int off[12];
    int dW[12];
    float* out[12];
};
__global__ void fuse_w_all_k(FuseWArgs a) {
    int z = blockIdx.y;
    int o = blockIdx.x;
    int k = threadIdx.x;
    int dW = a.dW[z];
    if (k >= dW) return;
    const float* wrow = a.Wupd[z] + (size_t)o * (2 * Hh) + a.off[z];
    const float* W = a.W[z];
    float s = 0.0f;
#pragma unroll 8
    for (int j = 0; j < Hh; j++) s += wrow[j] * W[(size_t)j * dW + k];
    a.out[z][(size_t)o * dW + k] = s;
}

struct FuseBArgs {
    const float* Wupd[6];
    const float* bdst[6];
    const float* bsrc[6];
    const float* bupd[6];
    float* out[6];
};
__global__ void fuse_bias_all_k(FuseBArgs a) {
    int z = blockIdx.x;
    int o = threadIdx.x;
    const float* wrow = a.Wupd[z] + (size_t)o * (2 * Hh);
    const float* bdst = a.bdst[z];
    const float* bsrc = a.bsrc[z];
    float s = a.bupd[z][o];
#pragma unroll 8
    for (int j = 0; j < Hh; j++) s += wrow[j] * bdst[j] + wrow[Hh + j] * bsrc[j];
    a.out[z][o] = s;
}

// combine dst weights/biases for the two convs feeding node type A
// Wc[0]=WF2+WF4, bc[0]=BF1+BF2 ; Wc[1]=WF8+WF10, bc[1]=BF4+BF5
__global__ void wadd_k(const float* __restrict__ Wf, const float* __restrict__ bf,
                       float* __restrict__ Wc, float* __restrict__ bc) {
    int z = blockIdx.y;
    int i = blockIdx.x * blockDim.x + threadIdx.x;
    const float* a = Wf + (size_t)(z ? 8 : 2) * Hh * Hh;
    const float* b = Wf + (size_t)(z ? 10 : 4) * Hh * Hh;
    if (i < Hh * Hh) Wc[(size_t)z * Hh * Hh + i] = a[i] + b[i];
    if (i < Hh) bc[z * Hh + i] = bf[(z ? 4 : 1) * Hh + i] + bf[(z ? 5 : 2) * Hh + i];
}

// ---- GEMM: C[M x 256] = A[M x K] @ W[256 x K]^T (+ bias) ----
#define TMv 128
#define TNv 128
#define TKv 16
#define LDSD (TMv + 4)
#define GEMM_SMEM (2 * 2 * TKv * LDSD * 4)
__global__ void __launch_bounds__(256, 2)
gemm_xwT_k(const float* __restrict__ A,
           const float* __restrict__ W,
           const float* __restrict__ bias,
           float* __restrict__ C, int M, int K) {
    extern __shared__ float sm[];
    const int BUF = 2 * TKv * LDSD;
    int tid = threadIdx.x;
    int mBase = blockIdx.x * TMv;
    int nBase = blockIdx.y * TNv;
    int tx = tid & 15;
    int ty = tid >> 4;
    int lr = tid >> 2;
    int lc = (tid & 3) * 4;

    ull acc[8][4];
#pragma unroll
    for (int i = 0; i < 8; i++)
#pragma unroll
        for (int j = 0; j < 4; j++) acc[i][j] = 0ULL;

    float4 avr[2], wvr[2];
    auto gload = [&](int k0) {
#pragma unroll
        for (int h = 0; h < 2; h++) {
            int r = lr + h * 64;
            int arow = mBase + r;
            float4 av = make_float4(0.f, 0.f, 0.f, 0.f);
            if (arow < M) av = *(const float4*)(A + (size_t)arow * K + k0 + lc);
            avr[h] = av;
            wvr[h] = *(const float4*)(W + (size_t)(nBase + r) * K + k0 + lc);
        }
    };
    auto sstore = [&](int b) {
        float* As = sm + b * BUF;
        float* Ws = As + TKv * LDSD;
#pragma unroll
        for (int h = 0; h < 2; h++) {
            int r = lr + h * 64;
            As[(lc + 0) * LDSD + r] = avr[h].x;
            As[(lc + 1) * LDSD + r] = avr[h].y;
            As[(lc + 2) * LDSD + r] = avr[h].z;
            As[(lc + 3) * LDSD + r] = avr[h].w;
            Ws[(lc + 0) * LDSD + r] = wvr[h].x;
            Ws[(lc + 1) * LDSD + r] = wvr[h].y;
            Ws[(lc + 2) * LDSD + r] = wvr[h].z;
            Ws[(lc + 3) * LDSD + r] = wvr[h].w;
        }
    };

    gload(0);
    sstore(0);
    __syncthreads();

    int nslabs = K / TKv;
    for (int s = 0; s < nslabs; s++) {
        int cur = s & 1;
        if (s + 1 < nslabs) gload((s + 1) * TKv);
        const float* As = sm + cur * BUF;
        const float* Ws = As + TKv * LDSD;
#pragma unroll
        for (int kk = 0; kk < TKv; kk++) {
            const float* arow = As + kk * LDSD + ty * 8;
            const float* wrow = Ws + kk * LDSD + tx * 8;
            float4 a0 = *(const float4*)(arow);
            float4 a1 = *(const float4*)(arow + 4);
            ulonglong2 w01 = *(const ulonglong2*)(wrow);
            ulonglong2 w23 = *(const ulonglong2*)(wrow + 4);
            float am[8] = {a0.x, a0.y, a0.z, a0.w, a1.x, a1.y, a1.z, a1.w};
#pragma unroll
            for (int i = 0; i < 8; i++) {
                ull ap = packf2(am[i], am[i]);
                ffma2(acc[i][0], ap, w01.x);
                ffma2(acc[i][1], ap, w01.y);
                ffma2(acc[i][2], ap, w23.x);
                ffma2(acc[i][3], ap, w23.y);
            }
        }
        if (s + 1 < nslabs) sstore((s + 1) & 1);
        __syncthreads();
    }

#pragma unroll
    for (int i = 0; i < 8; i++) {
        int row = mBase + ty * 8 + i;
        if (row >= M) continue;
        float r[8];
        unpackf2(acc[i][0], r[0], r[1]);
        unpackf2(acc[i][1], r[2], r[3]);
        unpackf2(acc[i][2], r[4], r[5]);
        unpackf2(acc[i][3], r[6], r[7]);
        float* cp = C + (size_t)row * 256 + nBase + tx * 8;
        if (bias) {
            const float* bp = bias + nBase + tx * 8;
            float4 b0 = *(const float4*)(bp);
            float4 b1 = *(const float4*)(bp + 4);
            r[0] += b0.x; r[1] += b0.y; r[2] += b0.z; r[3] += b0.w;
            r[4] += b1.x; r[5] += b1.y; r[6] += b1.z; r[7] += b1.w;
        }
        *(float4*)(cp) = make_float4(r[0], r[1], r[2], r[3]);
        *(float4*)(cp + 4) = make_float4(r[4], r[5], r[6], r[7]);
    }
}

// ---- BN (fused add of scatter sums) ----
#define ROWS_PER_BLK 256
__global__ void col_stats2_k(const float* __restrict__ x,
                             const float* __restrict__ agg, float prescale,
                             float* __restrict__ sums) {
    int c = threadIdx.x;
    int r0 = blockIdx.x * ROWS_PER_BLK;
    int r1 = r0 + ROWS_PER_BLK;
    if (r1 > Nn) r1 = Nn;
    float s = 0.0f, s2 = 0.0f;
    for (int r = r0; r < r1; r++) {
        size_t idx = (size_t)r * Hh + c;
        float v = (x[idx] + agg[idx]) * prescale;
        s += v;
        s2 += v * v;
    }
    atomicAdd(&sums[c], s);
    atomicAdd(&sums[Hh + c], s2);
}

__global__ void bn_finalize_k(const float* __restrict__ sums,
                              const float* __restrict__ g,
                              const float* __restrict__ b,
                              float* __restrict__ prm) {
    int c = threadIdx.x;
    float mean = sums[c] / (float)Nn;
    float var = sums[Hh + c] / (float)Nn - mean * mean;
    float sc = g[c] * rsqrtf(var + EPSv);
    prm[c] = sc;
    prm[Hh + c] = b[c] - mean * sc;
}

__global__ void bn_apply2_k(const float* __restrict__ x,
                            const float* __restrict__ agg,
                            const float* __restrict__ prm, float prescale,
                            float* __restrict__ y) {
    int i = blockIdx.x * blockDim.x + threadIdx.x;
    if (i >= Nn * (Hh / 4)) return;
    int c = (i & 63) * 4;
    float4 v = *(const float4*)(x + (size_t)i * 4);
    float4 g4 = *(const float4*)(agg + (size_t)i * 4);
    float4 sc = *(const float4*)(prm + c);
    float4 sh = *(const float4*)(prm + Hh + c);
    float t0 = (v.x + g4.x) * prescale * sc.x + sh.x;
    float t1 = (v.y + g4.y) * prescale * sc.y + sh.y;
    float t2 = (v.z + g4.z) * prescale * sc.z + sh.z;
    float t3 = (v.w + g4.w) * prescale * sc.w + sh.w;
    float4 r;
    r.x = t0 >= 0.f ? t0 : SLOPEv * t0;
    r.y = t1 >= 0.f ? t1 : SLOPEv * t1;
    r.z = t2 >= 0.f ? t2 : SLOPEv * t2;
    r.w = t3 >= 0.f ? t3 : SLOPEv * t3;
    *(float4*)(y + (size_t)i * 4) = r;
}

// ---------------- host orchestration ----------------------------------------

static void run_gemm(cudaStream_t st, const float* A, const float* W,
                     const float* bias, float* C, int M, int K) {
    dim3 grid((M + TMv - 1) / TMv, 256 / TNv);
    gemm_xwT_k<<<grid, 256, GEMM_SMEM, st>>>(A, W, bias, C, M, K);
}

static void run_scatter(cudaStream_t st, const float* t, const int* edge,
                        const float* inv, float* aggr) {
    long total = (long)Ee * 64;
    int blocks = (int)((total + 255) / 256);
    scatter_pre_k<<<blocks, 256, 0, st>>>(t, edge, edge + Ee, inv, aggr);
}

static void run_bn(cudaStream_t st, const float* x, const float* agg,
                   float prescale, const float* g, const float* b, float* y,
                   float* stats, float* prm) {
    cudaMemsetAsync(stats, 0, 2 * Hh * sizeof(float), st);
    col_stats2_k<<<(Nn + ROWS_PER_BLK - 1) / ROWS_PER_BLK, Hh, 0, st>>>(x, agg, prescale, stats);
    bn_finalize_k<<<1, Hh, 0, st>>>(stats, g, b, prm);
    bn_apply2_k<<<(Nn * (Hh / 4) + 255) / 256, 256, 0, st>>>(x, agg, prm, prescale, y);
}

extern "C" void kernel_launch(void* const* d_in, const int* in_sizes, int n_in,
                              void* d_out, int out_size) {
    const float* x_A = (const float*)d_in[0];
    const float* x_B = (const float*)d_in[1];
    const int* e_ab = (const int*)d_in[2];
    const int* e_ba = (const int*)d_in[3];
    const int* e_aa = (const int*)d_in[4];
    const float* ab_Wsrc1 = (const float*)d_in[5];
    const float* ab_bsrc1 = (const float*)d_in[6];
    const float* ab_Wdst1 = (const float*)d_in[7];
    const float* ab_bdst1 = (const float*)d_in[8];
    const float* ab_Wupd1 = (const float*)d_in[9];
    const float* ab_bupd1 = (const float*)d_in[10];
    const float* ba_Wsrc1 = (const float*)d_in[11];
    const float* ba_bsrc1 = (const float*)d_in[12];
    const float* ba_Wdst1 = (const float*)d_in[13];
    const float* ba_bdst1 = (const float*)d_in[14];
    const float* ba_Wupd1 = (const float*)d_in[15];
    const float* ba_bupd1 = (const float*)d_in[16];
    const float* aa_Wsrc1 = (const float*)d_in[17];
    const float* aa_bsrc1 = (const float*)d_in[18];
    const float* aa_Wdst1 = (const float*)d_in[19];
    const float* aa_bdst1 = (const float*)d_in[20];
    const float* aa_Wupd1 = (const float*)d_in[21];
    const float* aa_bupd1 = (const float*)d_in[22];
    const float* Wsrc2 = (const float*)d_in[23];
    const float* bsrc2 = (const float*)d_in[24];
    const float* Wdst2 = (const float*)d_in[25];
    const float* bdst2 = (const float*)d_in[26];
    const float* Wupd2 = (const float*)d_in[27];
    const float* bupd2 = (const float*)d_in[28];
    const float* bn_g = (const float*)d_in[29];
    const float* bn_b = (const float*)d_in[30];
    float* out = (float*)d_out;

    float *tb, *aggr, *eA, *eB, *hA, *hB, *inv, *Wf, *bf, *Wc, *bc, *stats, *prm;
    cudaGetSymbolAddress((void**)&tb, g_t);
    cudaGetSymbolAddress((void**)&aggr, g_aggr);
    cudaGetSymbolAddress((void**)&eA, g_eA);
    cudaGetSymbolAddress((void**)&eB, g_eB);
    cudaGetSymbolAddress((void**)&hA, g_hA);
    cudaGetSymbolAddress((void**)&hB, g_hB);
    cudaGetSymbolAddress((void**)&inv, g_inv);
    cudaGetSymbolAddress((void**)&Wf, g_Wf);
    cudaGetSymbolAddress((void**)&bf, g_bf);
    cudaGetSymbolAddress((void**)&Wc, g_Wc);
    cudaGetSymbolAddress((void**)&bc, g_bc);
    cudaGetSymbolAddress((void**)&stats, g_stats);
    cudaGetSymbolAddress((void**)&prm, g_prm);

    float* inv_ab = inv + 0 * Nn;
    float* inv_ba = inv + 1 * Nn;
    float* inv_aa = inv + 2 * Nn;
#define WF(i) (Wf + (size_t)(i) * Hh * Hh)
#define BF(i) (bf + (size_t)(i) * Hh)
#define WC(i) (Wc + (size_t)(i) * Hh * Hh)
#define BC(i) (bc + (size_t)(i) * Hh)
#define TT(i) (tb + (size_t)(i) * Nn * 256)
#define AGGR(i) (aggr + (size_t)(i) * Nn * 256)
    float* aggrA1 = AGGR(0);
    float* aggrB1 = AGGR(1);
    float* aggrA2 = AGGR(2);
    float* aggrB2 = AGGR(3);

    static cudaStream_t s1 = nullptr;
    static cudaEvent_t evFork, evT0, evT1, evT2, evSab, evSba, evSaa;
    static cudaEvent_t evHA, evHB, evUab, evUba, evUaa, evSab2, evSba2, evSaa2;
    if (!s1) {
        cudaStreamCreateWithFlags(&s1, cudaStreamNonBlocking);
        cudaEvent_t* evs[] = {&evFork, &evT0, &evT1, &evT2, &evSab, &evSba,
                              &evSaa, &evHA, &evHB, &evUab, &evUba, &evUaa,
                              &evSab2, &evSba2, &evSaa2};
        for (auto e : evs) cudaEventCreateWithFlags(e, cudaEventDisableTiming);
        cudaFuncSetAttribute(gemm_xwT_k,
                             cudaFuncAttributeMaxDynamicSharedMemorySize,
                             GEMM_SMEM);
    }
    cudaStream_t s0 = 0;

    cudaEventRecord(evFork, s0);
    cudaStreamWaitEvent(s1, evFork, 0);

    // ===== main stream: weight prep (#1-#3) then src-transform GEMMs =======
    {
        FuseWArgs fw;
        const float* wu[6] = {ab_Wupd1, ba_Wupd1, aa_Wupd1,
                              Wupd2 + 0 * (size_t)Hh * 2 * Hh,
                              Wupd2 + 1 * (size_t)Hh * 2 * Hh,
                              Wupd2 + 2 * (size_t)Hh * 2 * Hh};
        const float* wd[6] = {ab_Wdst1, ba_Wdst1, aa_Wdst1,
                              Wdst2 + 0 * (size_t)Hh * Hh,
                              Wdst2 + 1 * (size_t)Hh * Hh,
                              Wdst2 + 2 * (size_t)Hh * Hh};
        const float* ws[6] = {ab_Wsrc1, ba_Wsrc1, aa_Wsrc1,
                              Wsrc2 + 0 * (size_t)Hh * Hh,
                              Wsrc2 + 1 * (size_t)Hh * Hh,
                              Wsrc2 + 2 * (size_t)Hh * Hh};
        int dd[6] = {DBv, DAv, DAv, Hh, Hh, Hh};
        int ds[6] = {DAv, DBv, DAv, Hh, Hh, Hh};
        for (int c = 0; c < 6; c++) {
            fw.Wupd[2 * c] = wu[c]; fw.W[2 * c] = wd[c];
            fw.off[2 * c] = 0;      fw.dW[2 * c] = dd[c];
            fw.out[2 * c] = WF(2 * c);
            fw.Wupd[2 * c + 1] = wu[c]; fw.W[2 * c + 1] = ws[c];
            fw.off[2 * c + 1] = Hh;     fw.dW[2 * c + 1] = ds[c];
            fw.out[2 * c + 1] = WF(2 * c + 1);
        }
        fuse_w_all_k<<<dim3(Hh, 12), 256, 0, s0>>>(fw);        // #1

        FuseBArgs fb;
        const float* bd[6] = {ab_bdst1, ba_bdst1, aa_bdst1,
                              bdst2 + 0 * Hh, bdst2 + 1 * Hh, bdst2 + 2 * Hh};
        const float* bs[6] = {ab_bsrc1, ba_bsrc1, aa_bsrc1,
                              bsrc2 + 0 * Hh, bsrc2 + 1 * Hh, bsrc2 + 2 * Hh};
        const float* bu[6] = {ab_bupd1, ba_bupd1, aa_bupd1,
                              bupd2 + 0 * Hh, bupd2 + 1 * Hh, bupd2 + 2 * Hh};
        for (int c = 0; c < 6; c++) {
            fb.Wupd[c] = wu[c]; fb.bdst[c] = bd[c]; fb.bsrc[c] = bs[c];
            fb.bupd[c] = bu[c]; fb.out[c] = BF(c);
        }
        fuse_bias_all_k<<<6, Hh, 0, s0>>>(fb);                 // #2
        wadd_k<<<dim3(256, 2), 256, 0, s0>>>(Wf, bf, Wc, bc);  // #3
    }

    // src transforms (layer 1): t = x @ Wsrc_fused
    run_gemm(s0, x_A, WF(1), nullptr, TT(0), Nn, DAv);  // #4 t_ab
    cudaEventRecord(evT0, s0);
    run_gemm(s0, x_B, WF(3), nullptr, TT(1), Nn, DBv);  // #5 t_ba
    cudaEventRecord(evT1, s0);
    run_gemm(s0, x_A, WF(5), nullptr, TT(2), Nn, DAv);  // #6 t_aa  <- ncu target
    cudaEventRecord(evT2, s0);
    // dst GEMMs (layer 1)
    run_gemm(s0, x_B, WF(0), BF(0), eB, Nn, DBv);       // #7
    run_gemm(s0, x_A, WC(0), BC(0), eA, Nn, DAv);       // #8 combined ba+aa dst

    // ===== side stream: degrees + zero + layer-1 scatters ==================
    zero_k<<<2048, 256, 0, s1>>>((float4*)inv, (3L * Nn) / 4);
    zero_k<<<8192, 256, 0, s1>>>((float4*)aggr, (4L * Nn * 256) / 4);
    count_k<<<(Ee + 255) / 256, 256, 0, s1>>>(e_ab + Ee, inv_ab);
    count_k<<<(Ee + 255) / 256, 256, 0, s1>>>(e_ba + Ee, inv_ba);
    count_k<<<(Ee + 255) / 256, 256, 0, s1>>>(e_aa + Ee, inv_aa);
    inv_k<<<(3 * Nn + 255) / 256, 256, 0, s1>>>(inv, 3 * Nn);

    cudaStreamWaitEvent(s1, evT0, 0);
    run_scatter(s1, TT(0), e_ab, inv_ab, aggrB1);
    cudaEventRecord(evSab, s1);
    cudaStreamWaitEvent(s1, evT1, 0);
    run_scatter(s1, TT(1), e_ba, inv_ba, aggrA1);
    cudaEventRecord(evSba, s1);
    cudaStreamWaitEvent(s1, evT2, 0);
    run_scatter(s1, TT(2), e_aa, inv_aa, aggrA1);
    cudaEventRecord(evSaa, s1);

    // ===== main stream: BN layer 1 =========================================
    cudaStreamWaitEvent(s0, evSab, 0);
    run_bn(s0, eB, aggrB1, 1.0f, bn_g + 1 * Hh, bn_b + 1 * Hh, hB, stats, prm);
    cudaEventRecord(evHB, s0);
    // hB-derived transform early (frees the ba2 scatter to start)
    run_gemm(s0, hB, WF(9), nullptr, TT(4), Nn, Hh);    // t2_ba
    cudaEventRecord(evUba, s0);
    cudaStreamWaitEvent(s0, evSba, 0);
    cudaStreamWaitEvent(s0, evSaa, 0);
    run_bn(s0, eA, aggrA1, 0.5f, bn_g + 0 * Hh, bn_b + 0 * Hh, hA, stats, prm);
    cudaEventRecord(evHA, s0);

    // layer-2 transforms + dst GEMMs
    run_gemm(s0, hA, WF(11), nullptr, TT(5), Nn, Hh);   // t2_aa
    cudaEventRecord(evUaa, s0);
    run_gemm(s0, hA, WF(7), nullptr, TT(3), Nn, Hh);    // t2_ab
    cudaEventRecord(evUab, s0);
    run_gemm(s0, hB, WF(6), BF(3), eB, Nn, Hh);
    run_gemm(s0, hA, WC(1), BC(1), eA, Nn, Hh);

    // ===== side stream: layer-2 scatters ===================================
    cudaStreamWaitEvent(s1, evUba, 0);
    run_scatter(s1, TT(4), e_ba, inv_ba, aggrA2);
    cudaEventRecord(evSba2, s1);
    cudaStreamWaitEvent(s1, evUaa, 0);
    run_scatter(s1, TT(5), e_aa, inv_aa, aggrA2);
    cudaEventRecord(evSaa2, s1);
    cudaStreamWaitEvent(s1, evUab, 0);
    run_scatter(s1, TT(3), e_ab, inv_ab, aggrB2);
    cudaEventRecord(evSab2, s1);

    // ===== main stream: output BNs =========================================
    cudaStreamWaitEvent(s0, evSba2, 0);
    cudaStreamWaitEvent(s0, evSaa2, 0);
    run_bn(s0, eA, aggrA2, 0.5f, bn_g + 2 * Hh, bn_b + 2 * Hh, out, stats, prm);
    cudaStreamWaitEvent(s0, evSab2, 0);
    run_bn(s0, eB, aggrB2, 1.0f, bn_g + 3 * Hh, bn_b + 3 * Hh,
           out + (size_t)Nn * Hh, stats, prm);
}

// round 6
// speedup vs baseline: 2.6406x; 1.4046x over previous
#include <cuda_runtime.h>

#define Nn 50000
#define Ee 800000
#define DAv 256
#define DBv 128
#define Hh 256
#define EPSv 1e-5f
#define SLOPEv 0.01f

typedef unsigned long long ull;

// ---------------- scratch (static device globals; no allocation) -------------
__device__ float g_t[6][(size_t)Nn * 256];      // transformed src feats per conv
__device__ float g_aggr[6][(size_t)Nn * 256];   // B1, A1a, A1b, B2, A2a, A2b
__device__ float g_eA[(size_t)Nn * Hh];
__device__ float g_eB[(size_t)Nn * Hh];
__device__ float g_hA[(size_t)Nn * Hh];
__device__ float g_hB[(size_t)Nn * Hh];
__device__ int g_deg[3][Nn];
__device__ int g_base[3][Nn + 1];
__device__ int g_cursor[3][Nn];
__device__ int g_csr[3][Ee];
__device__ float g_Wf[12][Hh * Hh];
__device__ float g_bf[6][Hh];
__device__ float g_Wc[2][Hh * Hh];
__device__ float g_bc[2][Hh];
__device__ float g_stats[2 * Hh];
__device__ float g_prm[2 * Hh];

// ---------------- small helpers ----------------------------------------------
__device__ __forceinline__ ull packf2(float lo, float hi) {
    ull r;
    asm("mov.b64 %0, {%1, %2};" : "=l"(r)
        : "r"(__float_as_uint(lo)), "r"(__float_as_uint(hi)));
    return r;
}
__device__ __forceinline__ void unpackf2(ull v, float& lo, float& hi) {
    unsigned a, b;
    asm("mov.b64 {%0, %1}, %2;" : "=r"(a), "=r"(b) : "l"(v));
    lo = __uint_as_float(a);
    hi = __uint_as_float(b);
}
__device__ __forceinline__ void ffma2(ull& d, ull a, ull b) {
    asm("fma.rn.f32x2 %0, %1, %2, %0;" : "+l"(d) : "l"(a), "l"(b));
}

// ---------------- CSR build ---------------------------------------------------

__global__ void hist_k(const int* __restrict__ dst, int* __restrict__ deg) {
    int i = blockIdx.x * blockDim.x + threadIdx.x;
    if (i < Ee) atomicAdd(&deg[dst[i]], 1);
}

#define SCAN_T 1024
__global__ void scan_k(const int* __restrict__ deg_all,
                       int* __restrict__ base_all,
                       int* __restrict__ cur_all) {
    int z = blockIdx.x;
    const int* deg = deg_all + (size_t)z * Nn;
    int* base = base_all + (size_t)z * (Nn + 1);
    int* cur = cur_all + (size_t)z * Nn;
    __shared__ int sb[SCAN_T];
    int tid = threadIdx.x;
    const int CH = (Nn + SCAN_T - 1) / SCAN_T;
    int lo = tid * CH;
    int hi = lo + CH < Nn ? lo + CH : Nn;
    if (lo > Nn) lo = Nn;
    int s = 0;
    for (int i = lo; i < hi; i++) s += deg[i];
    sb[tid] = s;
    __syncthreads();
    for (int d = 1; d < SCAN_T; d <<= 1) {
        int v = (tid >= d) ? sb[tid - d] : 0;
        __syncthreads();
        sb[tid] += v;
        __syncthreads();
    }
    int run = sb[tid] - s;   // exclusive prefix of this chunk
    for (int i = lo; i < hi; i++) {
        base[i] = run;
        cur[i] = run;
        run += deg[i];
    }
    if (tid == SCAN_T - 1) base[Nn] = run;
}

__global__ void permute_k(const int* __restrict__ src,
                          const int* __restrict__ dst,
                          int* __restrict__ cur, int* __restrict__ csr) {
    int i = blockIdx.x * blockDim.x + threadIdx.x;
    if (i >= Ee) return;
    int d = dst[i];
    int p = atomicAdd(&cur[d], 1);
    csr[p] = src[i];
}

// ---- gather-mean: out[node] = (1/max(deg,1)) * sum_{e in seg} t[csr[e]] ----
// 64 threads per node (one float4 column each), 4 nodes per 256-thread block.
__global__ void __launch_bounds__(256)
gather_sum_k(const float* __restrict__ t, const int* __restrict__ csr,
             const int* __restrict__ base, float* __restrict__ out) {
    int node = blockIdx.x * 4 + (threadIdx.x >> 6);
    int c4 = threadIdx.x & 63;
    if (node >= Nn) return;
    int s0 = __ldg(base + node);
    int s1 = __ldg(base + node + 1);
    float4 acc = make_float4(0.f, 0.f, 0.f, 0.f);
    int i = s0;
    for (; i + 4 <= s1; i += 4) {
        int a0 = __ldg(csr + i), a1 = __ldg(csr + i + 1);
        int a2 = __ldg(csr + i + 2), a3 = __ldg(csr + i + 3);
        float4 v0 = *(const float4*)(t + (size_t)a0 * 256 + c4 * 4);
        float4 v1 = *(const float4*)(t + (size_t)a1 * 256 + c4 * 4);
        float4 v2 = *(const float4*)(t + (size_t)a2 * 256 + c4 * 4);
        float4 v3 = *(const float4*)(t + (size_t)a3 * 256 + c4 * 4);
        acc.x += v0.x + v1.x + v2.x + v3.x;
        acc.y += v0.y + v1.y + v2.y + v3.y;
        acc.z += v0.z + v1.z + v2.z + v3.z;
        acc.w += v0.w + v1.w + v2.w + v3.w;
    }
    for (; i < s1; i++) {
        int a = __ldg(csr + i);
        float4 v = *(const float4*)(t + (size_t)a * 256 + c4 * 4);
        acc.x += v.x; acc.y += v.y; acc.z += v.z; acc.w += v.w;
    }
    float w = 1.0f / fmaxf((float)(s1 - s0), 1.0f);
    acc.x *= w; acc.y *= w; acc.z *= w; acc.w *= w;
    *(float4*)(out + (size_t)node * 256 + c4 * 4) = acc;
}

// ---- batched weight fusion ----
struct FuseWArgs {
    const float* Wupd[12];
    const float* W[12];
    int off[12];
    int dW[12];
    float* out[12];
};
__global__ void fuse_w_all_k(FuseWArgs a) {
    int z = blockIdx.y;
    int o = blockIdx.x;
    int k = threadIdx.x;
    int dW = a.dW[z];
    if (k >= dW) return;
    const float* wrow = a.Wupd[z] + (size_t)o * (2 * Hh) + a.off[z];
    const float* W = a.W[z];
    float s = 0.0f;
#pragma unroll 8
    for (int j = 0; j < Hh; j++) s += wrow[j] * W[(size_t)j * dW + k];
    a.out[z][(size_t)o * dW + k] = s;
}

struct FuseBArgs {
    const float* Wupd[6];
    const float* bdst[6];
    const float* bsrc[6];
    const float* bupd[6];
    float* out[6];
};
__global__ void fuse_bias_all_k(FuseBArgs a) {
    int z = blockIdx.x;
    int o = threadIdx.x;
    const float* wrow = a.Wupd[z] + (size_t)o * (2 * Hh);
    const float* bdst = a.bdst[z];
    const float* bsrc = a.bsrc[z];
    float s = a.bupd[z][o];
#pragma unroll 8
    for (int j = 0; j < Hh; j++) s += wrow[j] * bdst[j] + wrow[Hh + j] * bsrc[j];
    a.out[z][o] = s;
}

__global__ void wadd_k(const float* __restrict__ Wf, const float* __restrict__ bf,
                       float* __restrict__ Wc, float* __restrict__ bc) {
    int z = blockIdx.y;
    int i = blockIdx.x * blockDim.x + threadIdx.x;
    const float* a = Wf + (size_t)(z ? 8 : 2) * Hh * Hh;
    const float* b = Wf + (size_t)(z ? 10 : 4) * Hh * Hh;
    if (i < Hh * Hh) Wc[(size_t)z * Hh * Hh + i] = a[i] + b[i];
    if (i < Hh) bc[z * Hh + i] = bf[(z ? 4 : 1) * Hh + i] + bf[(z ? 5 : 2) * Hh + i];
}

// ---- GEMM: C[M x 256] = A[M x K] @ W[256 x K]^T (+ bias) ----
#define TMv 128
#define TNv 128
#define TKv 16
#define LDSD (TMv + 4)
#define GEMM_SMEM (2 * 2 * TKv * LDSD * 4)
__global__ void __launch_bounds__(256, 2)
gemm_xwT_k(const float* __restrict__ A,
           const float* __restrict__ W,
           const float* __restrict__ bias,
           float* __restrict__ C, int M, int K) {
    extern __shared__ float sm[];
    const int BUF = 2 * TKv * LDSD;
    int tid = threadIdx.x;
    int mBase = blockIdx.x * TMv;
    int nBase = blockIdx.y * TNv;
    int tx = tid & 15;
    int ty = tid >> 4;
    int lr = tid >> 2;
    int lc = (tid & 3) * 4;

    ull acc[8][4];
#pragma unroll
    for (int i = 0; i < 8; i++)
#pragma unroll
        for (int j = 0; j < 4; j++) acc[i][j] = 0ULL;

    float4 avr[2], wvr[2];
    auto gload = [&](int k0) {
#pragma unroll
        for (int h = 0; h < 2; h++) {
            int r = lr + h * 64;
            int arow = mBase + r;
            float4 av = make_float4(0.f, 0.f, 0.f, 0.f);
            if (arow < M) av = *(const float4*)(A + (size_t)arow * K + k0 + lc);
            avr[h] = av;
            wvr[h] = *(const float4*)(W + (size_t)(nBase + r) * K + k0 + lc);
        }
    };
    auto sstore = [&](int b) {
        float* As = sm + b * BUF;
        float* Ws = As + TKv * LDSD;
#pragma unroll
        for (int h = 0; h < 2; h++) {
            int r = lr + h * 64;
            As[(lc + 0) * LDSD + r] = avr[h].x;
            As[(lc + 1) * LDSD + r] = avr[h].y;
            As[(lc + 2) * LDSD + r] = avr[h].z;
            As[(lc + 3) * LDSD + r] = avr[h].w;
            Ws[(lc + 0) * LDSD + r] = wvr[h].x;
            Ws[(lc + 1) * LDSD + r] = wvr[h].y;
            Ws[(lc + 2) * LDSD + r] = wvr[h].z;
            Ws[(lc + 3) * LDSD + r] = wvr[h].w;
        }
    };

    gload(0);
    sstore(0);
    __syncthreads();

    int nslabs = K / TKv;
    for (int s = 0; s < nslabs; s++) {
        int cur = s & 1;
        if (s + 1 < nslabs) gload((s + 1) * TKv);
        const float* As = sm + cur * BUF;
        const float* Ws = As + TKv * LDSD;
#pragma unroll
        for (int kk = 0; kk < TKv; kk++) {
            const float* arow = As + kk * LDSD + ty * 8;
            const float* wrow = Ws + kk * LDSD + tx * 8;
            float4 a0 = *(const float4*)(arow);
            float4 a1 = *(const float4*)(arow + 4);
            ulonglong2 w01 = *(const ulonglong2*)(wrow);
            ulonglong2 w23 = *(const ulonglong2*)(wrow + 4);
            float am[8] = {a0.x, a0.y, a0.z, a0.w, a1.x, a1.y, a1.z, a1.w};
#pragma unroll
            for (int i = 0; i < 8; i++) {
                ull ap = packf2(am[i], am[i]);
                ffma2(acc[i][0], ap, w01.x);
                ffma2(acc[i][1], ap, w01.y);
                ffma2(acc[i][2], ap, w23.x);
                ffma2(acc[i][3], ap, w23.y);
            }
        }
        if (s + 1 < nslabs) sstore((s + 1) & 1);
        __syncthreads();
    }

#pragma unroll
    for (int i = 0; i < 8; i++) {
        int row = mBase + ty * 8 + i;
        if (row >= M) continue;
        float r[8];
        unpackf2(acc[i][0], r[0], r[1]);
        unpackf2(acc[i][1], r[2], r[3]);
        unpackf2(acc[i][2], r[4], r[5]);
        unpackf2(acc[i][3], r[6], r[7]);
        float* cp = C + (size_t)row * 256 + nBase + tx * 8;
        if (bias) {
            const float* bp = bias + nBase + tx * 8;
            float4 b0 = *(const float4*)(bp);
            float4 b1 = *(const float4*)(bp + 4);
            r[0] += b0.x; r[1] += b0.y; r[2] += b0.z; r[3] += b0.w;
            r[4] += b1.x; r[5] += b1.y; r[6] += b1.z; r[7] += b1.w;
        }
        *(float4*)(cp) = make_float4(r[0], r[1], r[2], r[3]);
        *(float4*)(cp + 4) = make_float4(r[4], r[5], r[6], r[7]);
    }
}

// ---- BN (fused add of 1-2 aggregate buffers) ----
#define ROWS_PER_BLK 256
__global__ void col_stats3_k(const float* __restrict__ x,
                             const float* __restrict__ a1,
                             const float* __restrict__ a2, float prescale,
                             float* __restrict__ sums) {
    int c = threadIdx.x;
    int r0 = blockIdx.x * ROWS_PER_BLK;
    int r1 = r0 + ROWS_PER_BLK;
    if (r1 > Nn) r1 = Nn;
    float s = 0.0f, s2 = 0.0f;
    for (int r = r0; r < r1; r++) {
        size_t idx = (size_t)r * Hh + c;
        float v = x[idx] + a1[idx];
        if (a2) v += a2[idx];
        v *= prescale;
        s += v;
        s2 += v * v;
    }
    atomicAdd(&sums[c], s);
    atomicAdd(&sums[Hh + c], s2);
}

__global__ void bn_finalize_k(const float* __restrict__ sums,
                              const float* __restrict__ g,
                              const float* __restrict__ b,
                              float* __restrict__ prm) {
    int c = threadIdx.x;
    float mean = sums[c] / (float)Nn;
    float var = sums[Hh + c] / (float)Nn - mean * mean;
    float sc = g[c] * rsqrtf(var + EPSv);
    prm[c] = sc;
    prm[Hh + c] = b[c] - mean * sc;
}

__global__ void bn_apply3_k(const float* __restrict__ x,
                            const float* __restrict__ a1,
                            const float* __restrict__ a2,
                            const float* __restrict__ prm, float prescale,
                            float* __restrict__ y) {
    int i = blockIdx.x * blockDim.x + threadIdx.x;
    if (i >= Nn * (Hh / 4)) return;
    int c = (i & 63) * 4;
    float4 v = *(const float4*)(x + (size_t)i * 4);
    float4 g1 = *(const float4*)(a1 + (size_t)i * 4);
    if (a2) {
        float4 g2 = *(const float4*)(a2 + (size_t)i * 4);
        v.x += g2.x; v.y += g2.y; v.z += g2.z; v.w += g2.w;
    }
    float4 sc = *(const float4*)(prm + c);
    float4 sh = *(const float4*)(prm + Hh + c);
    float t0 = (v.x + g1.x) * prescale * sc.x + sh.x;
    float t1 = (v.y + g1.y) * prescale * sc.y + sh.y;
    float t2 = (v.z + g1.z) * prescale * sc.z + sh.z;
    float t3 = (v.w + g1.w) * prescale * sc.w + sh.w;
    float4 r;
    r.x = t0 >= 0.f ? t0 : SLOPEv * t0;
    r.y = t1 >= 0.f ? t1 : SLOPEv * t1;
    r.z = t2 >= 0.f ? t2 : SLOPEv * t2;
    r.w = t3 >= 0.f ? t3 : SLOPEv * t3;
    *(float4*)(y + (size_t)i * 4) = r;
}

// ---------------- host orchestration ----------------------------------------

static void run_gemm(cudaStream_t st, const float* A, const float* W,
                     const float* bias, float* C, int M, int K) {
    dim3 grid((M + TMv - 1) / TMv, 256 / TNv);
    gemm_xwT_k<<<grid, 256, GEMM_SMEM, st>>>(A, W, bias, C, M, K);
}

static void run_gather(cudaStream_t st, const float* t, const int* csr,
                       const int* base, float* out) {
    gather_sum_k<<<(Nn + 3) / 4, 256, 0, st>>>(t, csr, base, out);
}

static void run_bn(cudaStream_t st, const float* x, const float* a1,
                   const float* a2, float prescale, const float* g,
                   const float* b, float* y, float* stats, float* prm) {
    cudaMemsetAsync(stats, 0, 2 * Hh * sizeof(float), st);
    col_stats3_k<<<(Nn + ROWS_PER_BLK - 1) / ROWS_PER_BLK, Hh, 0, st>>>(x, a1, a2, prescale, stats);
    bn_finalize_k<<<1, Hh, 0, st>>>(stats, g, b, prm);
    bn_apply3_k<<<(Nn * (Hh / 4) + 255) / 256, 256, 0, st>>>(x, a1, a2, prm, prescale, y);
}

extern "C" void kernel_launch(void* const* d_in, const int* in_sizes, int n_in,
                              void* d_out, int out_size) {
    const float* x_A = (const float*)d_in[0];
    const float* x_B = (const float*)d_in[1];
    const int* e_ab = (const int*)d_in[2];
    const int* e_ba = (const int*)d_in[3];
    const int* e_aa = (const int*)d_in[4];
    const float* ab_Wsrc1 = (const float*)d_in[5];
    const float* ab_bsrc1 = (const float*)d_in[6];
    const float* ab_Wdst1 = (const float*)d_in[7];
    const float* ab_bdst1 = (const float*)d_in[8];
    const float* ab_Wupd1 = (const float*)d_in[9];
    const float* ab_bupd1 = (const float*)d_in[10];
    const float* ba_Wsrc1 = (const float*)d_in[11];
    const float* ba_bsrc1 = (const float*)d_in[12];
    const float* ba_Wdst1 = (const float*)d_in[13];
    const float* ba_bdst1 = (const float*)d_in[14];
    const float* ba_Wupd1 = (const float*)d_in[15];
    const float* ba_bupd1 = (const float*)d_in[16];
    const float* aa_Wsrc1 = (const float*)d_in[17];
    const float* aa_bsrc1 = (const float*)d_in[18];
    const float* aa_Wdst1 = (const float*)d_in[19];
    const float* aa_bdst1 = (const float*)d_in[20];
    const float* aa_Wupd1 = (const float*)d_in[21];
    const float* aa_bupd1 = (const float*)d_in[22];
    const float* Wsrc2 = (const float*)d_in[23];
    const float* bsrc2 = (const float*)d_in[24];
    const float* Wdst2 = (const float*)d_in[25];
    const float* bdst2 = (const float*)d_in[26];
    const float* Wupd2 = (const float*)d_in[27];
    const float* bupd2 = (const float*)d_in[28];
    const float* bn_g = (const float*)d_in[29];
    const float* bn_b = (const float*)d_in[30];
    float* out = (float*)d_out;

    float *tb, *aggr, *eA, *eB, *hA, *hB, *Wf, *bf, *Wc, *bc, *stats, *prm;
    int *deg, *base, *cursor, *csr;
    cudaGetSymbolAddress((void**)&tb, g_t);
    cudaGetSymbolAddress((void**)&aggr, g_aggr);
    cudaGetSymbolAddress((void**)&eA, g_eA);
    cudaGetSymbolAddress((void**)&eB, g_eB);
    cudaGetSymbolAddress((void**)&hA, g_hA);
    cudaGetSymbolAddress((void**)&hB, g_hB);
    cudaGetSymbolAddress((void**)&deg, g_deg);
    cudaGetSymbolAddress((void**)&base, g_base);
    cudaGetSymbolAddress((void**)&cursor, g_cursor);
    cudaGetSymbolAddress((void**)&csr, g_csr);
    cudaGetSymbolAddress((void**)&Wf, g_Wf);
    cudaGetSymbolAddress((void**)&bf, g_bf);
    cudaGetSymbolAddress((void**)&Wc, g_Wc);
    cudaGetSymbolAddress((void**)&bc, g_bc);
    cudaGetSymbolAddress((void**)&stats, g_stats);
    cudaGetSymbolAddress((void**)&prm, g_prm);

#define WF(i) (Wf + (size_t)(i) * Hh * Hh)
#define BF(i) (bf + (size_t)(i) * Hh)
#define WC(i) (Wc + (size_t)(i) * Hh * Hh)
#define BC(i) (bc + (size_t)(i) * Hh)
#define TT(i) (tb + (size_t)(i) * Nn * 256)
#define AGGR(i) (aggr + (size_t)(i) * Nn * 256)
#define DEG(z) (deg + (size_t)(z) * Nn)
#define BASE(z) (base + (size_t)(z) * (Nn + 1))
#define CUR(z) (cursor + (size_t)(z) * Nn)
#define CSR(z) (csr + (size_t)(z) * Ee)
    // aggr roles
    float* aB1 = AGGR(0);
    float* aA1a = AGGR(1);
    float* aA1b = AGGR(2);
    float* aB2 = AGGR(3);
    float* aA2a = AGGR(4);
    float* aA2b = AGGR(5);

    static cudaStream_t s1 = nullptr;
    static cudaEvent_t evFork, evT0, evT1, evT2, evSab, evSba, evSaa;
    static cudaEvent_t evHA, evHB, evUab, evUba, evUaa, evSab2, evSba2, evSaa2;
    if (!s1) {
        cudaStreamCreateWithFlags(&s1, cudaStreamNonBlocking);
        cudaEvent_t* evs[] = {&evFork, &evT0, &evT1, &evT2, &evSab, &evSba,
                              &evSaa, &evHA, &evHB, &evUab, &evUba, &evUaa,
                              &evSab2, &evSba2, &evSaa2};
        for (auto e : evs) cudaEventCreateWithFlags(e, cudaEventDisableTiming);
        cudaFuncSetAttribute(gemm_xwT_k,
                             cudaFuncAttributeMaxDynamicSharedMemorySize,
                             GEMM_SMEM);
    }
    cudaStream_t s0 = 0;

    cudaEventRecord(evFork, s0);
    cudaStreamWaitEvent(s1, evFork, 0);

    // ===== main stream: weight prep then GEMMs =============================
    {
        FuseWArgs fw;
        const float* wu[6] = {ab_Wupd1, ba_Wupd1, aa_Wupd1,
                              Wupd2 + 0 * (size_t)Hh * 2 * Hh,
                              Wupd2 + 1 * (size_t)Hh * 2 * Hh,
                              Wupd2 + 2 * (size_t)Hh * 2 * Hh};
        const float* wd[6] = {ab_Wdst1, ba_Wdst1, aa_Wdst1,
                              Wdst2 + 0 * (size_t)Hh * Hh,
                              Wdst2 + 1 * (size_t)Hh * Hh,
                              Wdst2 + 2 * (size_t)Hh * Hh};
        const float* ws[6] = {ab_Wsrc1, ba_Wsrc1, aa_Wsrc1,
                              Wsrc2 + 0 * (size_t)Hh * Hh,
                              Wsrc2 + 1 * (size_t)Hh * Hh,
                              Wsrc2 + 2 * (size_t)Hh * Hh};
        int dd[6] = {DBv, DAv, DAv, Hh, Hh, Hh};
        int ds[6] = {DAv, DBv, DAv, Hh, Hh, Hh};
        for (int c = 0; c < 6; c++) {
            fw.Wupd[2 * c] = wu[c]; fw.W[2 * c] = wd[c];
            fw.off[2 * c] = 0;      fw.dW[2 * c] = dd[c];
            fw.out[2 * c] = WF(2 * c);
            fw.Wupd[2 * c + 1] = wu[c]; fw.W[2 * c + 1] = ws[c];
            fw.off[2 * c + 1] = Hh;     fw.dW[2 * c + 1] = ds[c];
            fw.out[2 * c + 1] = WF(2 * c + 1);
        }
        fuse_w_all_k<<<dim3(Hh, 12), 256, 0, s0>>>(fw);

        FuseBArgs fb;
        const float* bd[6] = {ab_bdst1, ba_bdst1, aa_bdst1,
                              bdst2 + 0 * Hh, bdst2 + 1 * Hh, bdst2 + 2 * Hh};
        const float* bs[6] = {ab_bsrc1, ba_bsrc1, aa_bsrc1,
                              bsrc2 + 0 * Hh, bsrc2 + 1 * Hh, bsrc2 + 2 * Hh};
        const float* bu[6] = {ab_bupd1, ba_bupd1, aa_bupd1,
                              bupd2 + 0 * Hh, bupd2 + 1 * Hh, bupd2 + 2 * Hh};
        for (int c = 0; c < 6; c++) {
            fb.Wupd[c] = wu[c]; fb.bdst[c] = bd[c]; fb.bsrc[c] = bs[c];
            fb.bupd[c] = bu[c]; fb.out[c] = BF(c);
        }
        fuse_bias_all_k<<<6, Hh, 0, s0>>>(fb);
        wadd_k<<<dim3(256, 2), 256, 0, s0>>>(Wf, bf, Wc, bc);
    }

    // src transforms (layer 1)
    run_gemm(s0, x_A, WF(1), nullptr, TT(0), Nn, DAv);  // t_ab
    cudaEventRecord(evT0, s0);
    run_gemm(s0, x_B, WF(3), nullptr, TT(1), Nn, DBv);  // t_ba
    cudaEventRecord(evT1, s0);
    run_gemm(s0, x_A, WF(5), nullptr, TT(2), Nn, DAv);  // t_aa
    cudaEventRecord(evT2, s0);
    // dst GEMMs (layer 1)
    run_gemm(s0, x_B, WF(0), BF(0), eB, Nn, DBv);
    run_gemm(s0, x_A, WC(0), BC(0), eA, Nn, DAv);

    // ===== side stream: CSR build + layer-1 gathers ========================
    cudaMemsetAsync(deg, 0, 3 * Nn * sizeof(int), s1);
    hist_k<<<(Ee + 255) / 256, 256, 0, s1>>>(e_ab + Ee, DEG(0));
    hist_k<<<(Ee + 255) / 256, 256, 0, s1>>>(e_ba + Ee, DEG(1));
    hist_k<<<(Ee + 255) / 256, 256, 0, s1>>>(e_aa + Ee, DEG(2));
    scan_k<<<3, SCAN_T, 0, s1>>>(deg, base, cursor);
    permute_k<<<(Ee + 255) / 256, 256, 0, s1>>>(e_ab, e_ab + Ee, CUR(0), CSR(0));
    permute_k<<<(Ee + 255) / 256, 256, 0, s1>>>(e_ba, e_ba + Ee, CUR(1), CSR(1));
    permute_k<<<(Ee + 255) / 256, 256, 0, s1>>>(e_aa, e_aa + Ee, CUR(2), CSR(2));

    cudaStreamWaitEvent(s1, evT0, 0);
    run_gather(s1, TT(0), CSR(0), BASE(0), aB1);
    cudaEventRecord(evSab, s1);
    cudaStreamWaitEvent(s1, evT1, 0);
    run_gather(s1, TT(1), CSR(1), BASE(1), aA1a);
    cudaEventRecord(evSba, s1);
    cudaStreamWaitEvent(s1, evT2, 0);
    run_gather(s1, TT(2), CSR(2), BASE(2), aA1b);
    cudaEventRecord(evSaa, s1);

    // ===== main stream: BN layer 1 =========================================
    cudaStreamWaitEvent(s0, evSab, 0);
    run_bn(s0, eB, aB1, nullptr, 1.0f, bn_g + 1 * Hh, bn_b + 1 * Hh, hB, stats, prm);
    run_gemm(s0, hB, WF(9), nullptr, TT(4), Nn, Hh);    // t2_ba
    cudaEventRecord(evUba, s0);
    cudaStreamWaitEvent(s0, evSba, 0);
    cudaStreamWaitEvent(s0, evSaa, 0);
    run_bn(s0, eA, aA1a, aA1b, 0.5f, bn_g + 0 * Hh, bn_b + 0 * Hh, hA, stats, prm);

    // layer-2 transforms + dst GEMMs
    run_gemm(s0, hA, WF(11), nullptr, TT(5), Nn, Hh);   // t2_aa
    cudaEventRecord(evUaa, s0);
    run_gemm(s0, hA, WF(7), nullptr, TT(3), Nn, Hh);    // t2_ab
    cudaEventRecord(evUab, s0);
    run_gemm(s0, hB, WF(6), BF(3), eB, Nn, Hh);
    run_gemm(s0, hA, WC(1), BC(1), eA, Nn, Hh);

    // ===== side stream: layer-2 gathers ====================================
    cudaStreamWaitEvent(s1, evUba, 0);
    run_gather(s1, TT(4), CSR(1), BASE(1), aA2a);
    cudaEventRecord(evSba2, s1);
    cudaStreamWaitEvent(s1, evUaa, 0);
    run_gather(s1, TT(5), CSR(2), BASE(2), aA2b);
    cudaEventRecord(evSaa2, s1);
    cudaStreamWaitEvent(s1, evUab, 0);
    run_gather(s1, TT(3), CSR(0), BASE(0), aB2);
    cudaEventRecord(evSab2, s1);

    // ===== main stream: output BNs =========================================
    cudaStreamWaitEvent(s0, evSba2, 0);
    cudaStreamWaitEvent(s0, evSaa2, 0);
    run_bn(s0, eA, aA2a, aA2b, 0.5f, bn_g + 2 * Hh, bn_b + 2 * Hh, out, stats, prm);
    cudaStreamWaitEvent(s0, evSab2, 0);
    run_bn(s0, eB, aB2, nullptr, 1.0f, bn_g + 3 * Hh, bn_b + 3 * Hh,
           out + (size_t)Nn * Hh, stats, prm);
}

// round 7
// speedup vs baseline: 2.8229x; 1.0690x over previous
#include <cuda_runtime.h>

#define Nn 50000
#define Ee 800000
#define DAv 256
#define DBv 128
#define Hh 256
#define EPSv 1e-5f
#define SLOPEv 0.01f

typedef unsigned long long ull;

// ---------------- scratch (static device globals; no allocation) -------------
__device__ float g_TtA[(size_t)Nn * 512];    // [t_ab | t_aa]
__device__ float g_TB1[(size_t)Nn * 512];    // [t_ba | eB]
__device__ float g_TdA[(size_t)Nn * 256];    // eA
__device__ float g_TB2[(size_t)Nn * 512];    // [t2_ba | eB2]
__device__ float g_TtA2[(size_t)Nn * 512];   // [t2_aa | t2_ab]
__device__ float g_TdA2[(size_t)Nn * 256];   // eA2
__device__ float g_aggr[6][(size_t)Nn * 256];
__device__ float g_hA[(size_t)Nn * Hh];
__device__ float g_hB[(size_t)Nn * Hh];
__device__ int g_deg[3][Nn];
__device__ int g_base[3][Nn + 1];
__device__ int g_cursor[3][Nn];
__device__ int g_csr[3][Ee];
// merged weights
__device__ float g_WtA[512 * 256];
__device__ float g_WB1[512 * 128];
__device__ float g_WdA[256 * 256];
__device__ float g_WB2[512 * 256];
__device__ float g_WtA2[512 * 256];
__device__ float g_WdA2[256 * 256];
__device__ float g_biasB1[512];
__device__ float g_biasB2[512];
__device__ float g_bdA[256];
__device__ float g_bdA2[256];
__device__ float g_Wtmp[4][256 * 256];
__device__ float g_btmp[4][256];
__device__ float g_stats[2 * Hh];
__device__ float g_prm[2 * Hh];

// ---------------- small helpers ----------------------------------------------
__device__ __forceinline__ ull packf2(float lo, float hi) {
    ull r;
    asm("mov.b64 %0, {%1, %2};" : "=l"(r)
        : "r"(__float_as_uint(lo)), "r"(__float_as_uint(hi)));
    return r;
}
__device__ __forceinline__ void unpackf2(ull v, float& lo, float& hi) {
    unsigned a, b;
    asm("mov.b64 {%0, %1}, %2;" : "=r"(a), "=r"(b) : "l"(v));
    lo = __uint_as_float(a);
    hi = __uint_as_float(b);
}
__device__ __forceinline__ void ffma2(ull& d, ull a, ull b) {
    asm("fma.rn.f32x2 %0, %1, %2, %0;" : "+l"(d) : "l"(a), "l"(b));
}

// ---------------- CSR build ---------------------------------------------------

__global__ void hist_k(const int* __restrict__ dst, int* __restrict__ deg) {
    int i = blockIdx.x * blockDim.x + threadIdx.x;
    if (i < Ee) atomicAdd(&deg[dst[i]], 1);
}

#define SCAN_T 1024
__global__ void scan_k(const int* __restrict__ deg_all,
                       int* __restrict__ base_all,
                       int* __restrict__ cur_all) {
    int z = blockIdx.x;
    const int* deg = deg_all + (size_t)z * Nn;
    int* base = base_all + (size_t)z * (Nn + 1);
    int* cur = cur_all + (size_t)z * Nn;
    __shared__ int sb[SCAN_T];
    int tid = threadIdx.x;
    const int CH = (Nn + SCAN_T - 1) / SCAN_T;
    int lo = tid * CH;
    int hi = lo + CH < Nn ? lo + CH : Nn;
    if (lo > Nn) lo = Nn;
    int s = 0;
    for (int i = lo; i < hi; i++) s += deg[i];
    sb[tid] = s;
    __syncthreads();
    for (int d = 1; d < SCAN_T; d <<= 1) {
        int v = (tid >= d) ? sb[tid - d] : 0;
        __syncthreads();
        sb[tid] += v;
        __syncthreads();
    }
    int run = sb[tid] - s;
    for (int i = lo; i < hi; i++) {
        base[i] = run;
        cur[i] = run;
        run += deg[i];
    }
    if (tid == SCAN_T - 1) base[Nn] = run;
}

__global__ void permute_k(const int* __restrict__ src,
                          const int* __restrict__ dst,
                          int* __restrict__ cur, int* __restrict__ csr) {
    int i = blockIdx.x * blockDim.x + threadIdx.x;
    if (i >= Ee) return;
    int d = dst[i];
    int p = atomicAdd(&cur[d], 1);
    csr[p] = src[i];
}

// ---- gather-mean from a strided source block --------------------------------
__global__ void __launch_bounds__(256)
gather_sum_k(const float* __restrict__ t, int ldt, const int* __restrict__ csr,
             const int* __restrict__ base, float* __restrict__ out) {
    int node = blockIdx.x * 4 + (threadIdx.x >> 6);
    int c4 = threadIdx.x & 63;
    if (node >= Nn) return;
    int s0 = __ldg(base + node);
    int s1 = __ldg(base + node + 1);
    float4 acc = make_float4(0.f, 0.f, 0.f, 0.f);
    int i = s0;
    for (; i + 4 <= s1; i += 4) {
        int a0 = __ldg(csr + i), a1 = __ldg(csr + i + 1);
        int a2 = __ldg(csr + i + 2), a3 = __ldg(csr + i + 3);
        float4 v0 = *(const float4*)(t + (size_t)a0 * ldt + c4 * 4);
        float4 v1 = *(const float4*)(t + (size_t)a1 * ldt + c4 * 4);
        float4 v2 = *(const float4*)(t + (size_t)a2 * ldt + c4 * 4);
        float4 v3 = *(const float4*)(t + (size_t)a3 * ldt + c4 * 4);
        acc.x += v0.x + v1.x + v2.x + v3.x;
        acc.y += v0.y + v1.y + v2.y + v3.y;
        acc.z += v0.z + v1.z + v2.z + v3.z;
        acc.w += v0.w + v1.w + v2.w + v3.w;
    }
    for (; i < s1; i++) {
        int a = __ldg(csr + i);
        float4 v = *(const float4*)(t + (size_t)a * ldt + c4 * 4);
        acc.x += v.x; acc.y += v.y; acc.z += v.z; acc.w += v.w;
    }
    float w = 1.0f / fmaxf((float)(s1 - s0), 1.0f);
    acc.x *= w; acc.y *= w; acc.z *= w; acc.w *= w;
    *(float4*)(out + (size_t)node * 256 + c4 * 4) = acc;
}

// ---- batched weight fusion ----
struct FuseWArgs {
    const float* Wupd[12];
    const float* W[12];
    int off[12];
    int dW[12];
    float* out[12];
};
__global__ void fuse_w_all_k(FuseWArgs a) {
    int z = blockIdx.y;
    int o = blockIdx.x;
    int k = threadIdx.x;
    int dW = a.dW[z];
    if (k >= dW) return;
    const float* wrow = a.Wupd[z] + (size_t)o * (2 * Hh) + a.off[z];
    const float* W = a.W[z];
    float s = 0.0f;
#pragma unroll 8
    for (int j = 0; j < Hh; j++) s += wrow[j] * W[(size_t)j * dW + k];
    a.out[z][(size_t)o * dW + k] = s;
}

struct FuseBArgs {
    const float* Wupd[6];
    const float* bdst[6];
    const float* bsrc[6];
    const float* bupd[6];
    float* out[6];
};
__global__ void fuse_bias_all_k(FuseBArgs a) {
    int z = blockIdx.x;
    int o = threadIdx.x;
    const float* wrow = a.Wupd[z] + (size_t)o * (2 * Hh);
    const float* bdst = a.bdst[z];
    const float* bsrc = a.bsrc[z];
    float s = a.bupd[z][o];
#pragma unroll 8
    for (int j = 0; j < Hh; j++) s += wrow[j] * bdst[j] + wrow[Hh + j] * bsrc[j];
    a.out[z][o] = s;
}

// combine the two dst weight/bias halves for node-type A; zero merged-bias prefix
__global__ void assemble_k(const float* __restrict__ Wtmp,
                           const float* __restrict__ btmp,
                           float* __restrict__ WdA, float* __restrict__ WdA2,
                           float* __restrict__ bdA, float* __restrict__ bdA2,
                           float* __restrict__ biasB1, float* __restrict__ biasB2) {
    int z = blockIdx.y;
    int i = blockIdx.x * blockDim.x + threadIdx.x;
    const float* a = Wtmp + (size_t)(z * 2) * 65536;
    const float* b = Wtmp + (size_t)(z * 2 + 1) * 65536;
    float* W = z ? WdA2 : WdA;
    if (i < 65536) W[i] = a[i] + b[i];
    if (i < 256) {
        (z ? bdA2 : bdA)[i] = btmp[(z * 2) * 256 + i] + btmp[(z * 2 + 1) * 256 + i];
        (z ? biasB2 : biasB1)[i] = 0.f;
    }
}

// ---- GEMM: C[M x N] = A[M x K] @ W[N x K]^T (+ bias); N = gridDim.y*128 ----
#define TMv 128
#define TNv 128
#define TKv 16
#define LDSD (TMv + 4)
#define GEMM_SMEM (2 * 2 * TKv * LDSD * 4)
__global__ void __launch_bounds__(256, 2)
gemm_xwT_k(const float* __restrict__ A,
           const float* __restrict__ W,
           const float* __restrict__ bias,
           float* __restrict__ C, int M, int K) {
    extern __shared__ float sm[];
    const int BUF = 2 * TKv * LDSD;
    int ldc = gridDim.y * TNv;
    int tid = threadIdx.x;
    int mBase = blockIdx.x * TMv;
    int nBase = blockIdx.y * TNv;
    int tx = tid & 15;
    int ty = tid >> 4;
    int lr = tid >> 2;
    int lc = (tid & 3) * 4;

    ull acc[8][4];
#pragma unroll
    for (int i = 0; i < 8; i++)
#pragma unroll
        for (int j = 0; j < 4; j++) acc[i][j] = 0ULL;

    float4 avr[2], wvr[2];
    auto gload = [&](int k0) {
#pragma unroll
        for (int h = 0; h < 2; h++) {
            int r = lr + h * 64;
            int arow = mBase + r;
            float4 av = make_float4(0.f, 0.f, 0.f, 0.f);
            if (arow < M) av = *(const float4*)(A + (size_t)arow * K + k0 + lc);
            avr[h] = av;
            wvr[h] = *(const float4*)(W + (size_t)(nBase + r) * K + k0 + lc);
        }
    };
    auto sstore = [&](int b) {
        float* As = sm + b * BUF;
        float* Ws = As + TKv * LDSD;
#pragma unroll
        for (int h = 0; h < 2; h++) {
            int r = lr + h * 64;
            As[(lc + 0) * LDSD + r] = avr[h].x;
            As[(lc + 1) * LDSD + r] = avr[h].y;
            As[(lc + 2) * LDSD + r] = avr[h].z;
            As[(lc + 3) * LDSD + r] = avr[h].w;
            Ws[(lc + 0) * LDSD + r] = wvr[h].x;
            Ws[(lc + 1) * LDSD + r] = wvr[h].y;
            Ws[(lc + 2) * LDSD + r] = wvr[h].z;
            Ws[(lc + 3) * LDSD + r] = wvr[h].w;
        }
    };

    gload(0);
    sstore(0);
    __syncthreads();

    int nslabs = K / TKv;
    for (int s = 0; s < nslabs; s++) {
        int cur = s & 1;
        if (s + 1 < nslabs) gload((s + 1) * TKv);
        const float* As = sm + cur * BUF;
        const float* Ws = As + TKv * LDSD;
#pragma unroll
        for (int kk = 0; kk < TKv; kk++) {
            const float* arow = As + kk * LDSD + ty * 8;
            const float* wrow = Ws + kk * LDSD + tx * 8;
            float4 a0 = *(const float4*)(arow);
            float4 a1 = *(const float4*)(arow + 4);
            ulonglong2 w01 = *(const ulonglong2*)(wrow);
            ulonglong2 w23 = *(const ulonglong2*)(wrow + 4);
            float am[8] = {a0.x, a0.y, a0.z, a0.w, a1.x, a1.y, a1.z, a1.w};
#pragma unroll
            for (int i = 0; i < 8; i++) {
                ull ap = packf2(am[i], am[i]);
                ffma2(acc[i][0], ap, w01.x);
                ffma2(acc[i][1], ap, w01.y);
                ffma2(acc[i][2], ap, w23.x);
                ffma2(acc[i][3], ap, w23.y);
            }
        }
        if (s + 1 < nslabs) sstore((s + 1) & 1);
        __syncthreads();
    }

#pragma unroll
    for (int i = 0; i < 8; i++) {
        int row = mBase + ty * 8 + i;
        if (row >= M) continue;
        float r[8];
        unpackf2(acc[i][0], r[0], r[1]);
        unpackf2(acc[i][1], r[2], r[3]);
        unpackf2(acc[i][2], r[4], r[5]);
        unpackf2(acc[i][3], r[6], r[7]);
        float* cp = C + (size_t)row * ldc + nBase + tx * 8;
        if (bias) {
            const float* bp = bias + nBase + tx * 8;
            float4 b0 = *(const float4*)(bp);
            float4 b1 = *(const float4*)(bp + 4);
            r[0] += b0.x; r[1] += b0.y; r[2] += b0.z; r[3] += b0.w;
            r[4] += b1.x; r[5] += b1.y; r[6] += b1.z; r[7] += b1.w;
        }
        *(float4*)(cp) = make_float4(r[0], r[1], r[2], r[3]);
        *(float4*)(cp + 4) = make_float4(r[4], r[5], r[6], r[7]);
    }
}

// ---- BN (strided x, fused add of 1-2 aggregate buffers) ----
#define ROWS_PER_BLK 256
__global__ void col_stats3_k(const float* __restrict__ x, int ldx,
                             const float* __restrict__ a1,
                             const float* __restrict__ a2, float prescale,
                             float* __restrict__ sums) {
    int c = threadIdx.x;
    int r0 = blockIdx.x * ROWS_PER_BLK;
    int r1 = r0 + ROWS_PER_BLK;
    if (r1 > Nn) r1 = Nn;
    float s = 0.0f, s2 = 0.0f;
    for (int r = r0; r < r1; r++) {
        float v = x[(size_t)r * ldx + c] + a1[(size_t)r * 256 + c];
        if (a2) v += a2[(size_t)r * 256 + c];
        v *= prescale;
        s += v;
        s2 += v * v;
    }
    atomicAdd(&sums[c], s);
    atomicAdd(&sums[Hh + c], s2);
}

__global__ void bn_finalize_k(const float* __restrict__ sums,
                              const float* __restrict__ g,
                              const float* __restrict__ b,
                              float* __restrict__ prm) {
    int c = threadIdx.x;
    float mean = sums[c] / (float)Nn;
    float var = sums[Hh + c] / (float)Nn - mean * mean;
    float sc = g[c] * rsqrtf(var + EPSv);
    prm[c] = sc;
    prm[Hh + c] = b[c] - mean * sc;
}

__global__ void bn_apply3_k(const float* __restrict__ x, int ldx,
                            const float* __restrict__ a1,
                            const float* __restrict__ a2,
                            const float* __restrict__ prm, float prescale,
                            float* __restrict__ y) {
    int i = blockIdx.x * blockDim.x + threadIdx.x;
    if (i >= Nn * (Hh / 4)) return;
    int r = i >> 6;
    int c = (i & 63) * 4;
    float4 v = *(const float4*)(x + (size_t)r * ldx + c);
    float4 g1 = *(const float4*)(a1 + (size_t)r * 256 + c);
    if (a2) {
        float4 g2 = *(const float4*)(a2 + (size_t)r * 256 + c);
        v.x += g2.x; v.y += g2.y; v.z += g2.z; v.w += g2.w;
    }
    float4 sc = *(const float4*)(prm + c);
    float4 sh = *(const float4*)(prm + Hh + c);
    float t0 = (v.x + g1.x) * prescale * sc.x + sh.x;
    float t1 = (v.y + g1.y) * prescale * sc.y + sh.y;
    float t2 = (v.z + g1.z) * prescale * sc.z + sh.z;
    float t3 = (v.w + g1.w) * prescale * sc.w + sh.w;
    float4 r4;
    r4.x = t0 >= 0.f ? t0 : SLOPEv * t0;
    r4.y = t1 >= 0.f ? t1 : SLOPEv * t1;
    r4.z = t2 >= 0.f ? t2 : SLOPEv * t2;
    r4.w = t3 >= 0.f ? t3 : SLOPEv * t3;
    *(float4*)(y + (size_t)r * 256 + c) = r4;
}

// ---------------- host orchestration ----------------------------------------

static void run_gemm(cudaStream_t st, const float* A, const float* W,
                     const float* bias, float* C, int M, int K, int N) {
    dim3 grid((M + TMv - 1) / TMv, N / TNv);
    gemm_xwT_k<<<grid, 256, GEMM_SMEM, st>>>(A, W, bias, C, M, K);
}

static void run_gather(cudaStream_t st, const float* t, int ldt, const int* csr,
                       const int* base, float* out) {
    gather_sum_k<<<(Nn + 3) / 4, 256, 0, st>>>(t, ldt, csr, base, out);
}

static void run_bn(cudaStream_t st, const float* x, int ldx, const float* a1,
                   const float* a2, float prescale, const float* g,
                   const float* b, float* y, float* stats, float* prm) {
    cudaMemsetAsync(stats, 0, 2 * Hh * sizeof(float), st);
    col_stats3_k<<<(Nn + ROWS_PER_BLK - 1) / ROWS_PER_BLK, Hh, 0, st>>>(x, ldx, a1, a2, prescale, stats);
    bn_finalize_k<<<1, Hh, 0, st>>>(stats, g, b, prm);
    bn_apply3_k<<<(Nn * (Hh / 4) + 255) / 256, 256, 0, st>>>(x, ldx, a1, a2, prm, prescale, y);
}

extern "C" void kernel_launch(void* const* d_in, const int* in_sizes, int n_in,
                              void* d_out, int out_size) {
    const float* x_A = (const float*)d_in[0];
    const float* x_B = (const float*)d_in[1];
    const int* e_ab = (const int*)d_in[2];
    const int* e_ba = (const int*)d_in[3];
    const int* e_aa = (const int*)d_in[4];
    const float* ab_Wsrc1 = (const float*)d_in[5];
    const float* ab_bsrc1 = (const float*)d_in[6];
    const float* ab_Wdst1 = (const float*)d_in[7];
    const float* ab_bdst1 = (const float*)d_in[8];
    const float* ab_Wupd1 = (const float*)d_in[9];
    const float* ab_bupd1 = (const float*)d_in[10];
    const float* ba_Wsrc1 = (const float*)d_in[11];
    const float* ba_bsrc1 = (const float*)d_in[12];
    const float* ba_Wdst1 = (const float*)d_in[13];
    const float* ba_bdst1 = (const float*)d_in[14];
    const float* ba_Wupd1 = (const float*)d_in[15];
    const float* ba_bupd1 = (const float*)d_in[16];
    const float* aa_Wsrc1 = (const float*)d_in[17];
    const float* aa_bsrc1 = (const float*)d_in[18];
    const float* aa_Wdst1 = (const float*)d_in[19];
    const float* aa_bdst1 = (const float*)d_in[20];
    const float* aa_Wupd1 = (const float*)d_in[21];
    const float* aa_bupd1 = (const float*)d_in[22];
    const float* Wsrc2 = (const float*)d_in[23];
    const float* bsrc2 = (const float*)d_in[24];
    const float* Wdst2 = (const float*)d_in[25];
    const float* bdst2 = (const float*)d_in[26];
    const float* Wupd2 = (const float*)d_in[27];
    const float* bupd2 = (const float*)d_in[28];
    const float* bn_g = (const float*)d_in[29];
    const float* bn_b = (const float*)d_in[30];
    float* out = (float*)d_out;

    float *TtA, *TB1, *TdA, *TB2, *TtA2, *TdA2, *aggr, *hA, *hB;
    float *WtA, *WB1, *WdA, *WB2, *WtA2, *WdA2;
    float *biasB1, *biasB2, *bdA, *bdA2, *Wtmp, *btmp, *stats, *prm;
    int *deg, *base, *cursor, *csr;
    cudaGetSymbolAddress((void**)&TtA, g_TtA);
    cudaGetSymbolAddress((void**)&TB1, g_TB1);
    cudaGetSymbolAddress((void**)&TdA, g_TdA);
    cudaGetSymbolAddress((void**)&TB2, g_TB2);
    cudaGetSymbolAddress((void**)&TtA2, g_TtA2);
    cudaGetSymbolAddress((void**)&TdA2, g_TdA2);
    cudaGetSymbolAddress((void**)&aggr, g_aggr);
    cudaGetSymbolAddress((void**)&hA, g_hA);
    cudaGetSymbolAddress((void**)&hB, g_hB);
    cudaGetSymbolAddress((void**)&WtA, g_WtA);
    cudaGetSymbolAddress((void**)&WB1, g_WB1);
    cudaGetSymbolAddress((void**)&WdA, g_WdA);
    cudaGetSymbolAddress((void**)&WB2, g_WB2);
    cudaGetSymbolAddress((void**)&WtA2, g_WtA2);
    cudaGetSymbolAddress((void**)&WdA2, g_WdA2);
    cudaGetSymbolAddress((void**)&biasB1, g_biasB1);
    cudaGetSymbolAddress((void**)&biasB2, g_biasB2);
    cudaGetSymbolAddress((void**)&bdA, g_bdA);
    cudaGetSymbolAddress((void**)&bdA2, g_bdA2);
    cudaGetSymbolAddress((void**)&Wtmp, g_Wtmp);
    cudaGetSymbolAddress((void**)&btmp, g_btmp);
    cudaGetSymbolAddress((void**)&stats, g_stats);
    cudaGetSymbolAddress((void**)&prm, g_prm);
    cudaGetSymbolAddress((void**)&deg, g_deg);
    cudaGetSymbolAddress((void**)&base, g_base);
    cudaGetSymbolAddress((void**)&cursor, g_cursor);
    cudaGetSymbolAddress((void**)&csr, g_csr);

#define AGGR(i) (aggr + (size_t)(i) * Nn * 256)
#define BASE(z) (base + (size_t)(z) * (Nn + 1))
#define CUR(z) (cursor + (size_t)(z) * Nn)
#define CSR(z) (csr + (size_t)(z) * Ee)

    static cudaStream_t s1 = nullptr, s2 = nullptr;
    static cudaEvent_t evFork, evFuse, evTA, evB1, evB1g, evA1a, evA1b, evHB,
        evB2, evTA2, evA2a, evA2b, evB2g;
    if (!s1) {
        cudaStreamCreateWithFlags(&s1, cudaStreamNonBlocking);
        cudaStreamCreateWithFlags(&s2, cudaStreamNonBlocking);
        cudaEvent_t* evs[] = {&evFork, &evFuse, &evTA, &evB1, &evB1g, &evA1a,
                              &evA1b, &evHB, &evB2, &evTA2, &evA2a, &evA2b,
                              &evB2g};
        for (auto e : evs) cudaEventCreateWithFlags(e, cudaEventDisableTiming);
        cudaFuncSetAttribute(gemm_xwT_k,
                             cudaFuncAttributeMaxDynamicSharedMemorySize,
                             GEMM_SMEM);
    }
    cudaStream_t s0 = 0;

    cudaEventRecord(evFork, s0);
    cudaStreamWaitEvent(s1, evFork, 0);
    cudaStreamWaitEvent(s2, evFork, 0);

    // ===== s0: weight fusion into merged buffers ===========================
    {
        FuseWArgs fw;
        const float* wu2[3] = {Wupd2 + 0 * (size_t)Hh * 2 * Hh,
                               Wupd2 + 1 * (size_t)Hh * 2 * Hh,
                               Wupd2 + 2 * (size_t)Hh * 2 * Hh};
        // z0: t_ab   z1: t_aa   -> WtA
        fw.Wupd[0] = ab_Wupd1; fw.W[0] = ab_Wsrc1; fw.off[0] = Hh; fw.dW[0] = DAv; fw.out[0] = WtA;
        fw.Wupd[1] = aa_Wupd1; fw.W[1] = aa_Wsrc1; fw.off[1] = Hh; fw.dW[1] = DAv; fw.out[1] = WtA + 256 * 256;
        // z2: t_ba   z3: eB dst -> WB1
        fw.Wupd[2] = ba_Wupd1; fw.W[2] = ba_Wsrc1; fw.off[2] = Hh; fw.dW[2] = DBv; fw.out[2] = WB1;
        fw.Wupd[3] = ab_Wupd1; fw.W[3] = ab_Wdst1; fw.off[3] = 0;  fw.dW[3] = DBv; fw.out[3] = WB1 + 256 * 128;
        // z4/z5: ba/aa dst -> temps (assembled into WdA)
        fw.Wupd[4] = ba_Wupd1; fw.W[4] = ba_Wdst1; fw.off[4] = 0; fw.dW[4] = DAv; fw.out[4] = Wtmp + 0 * 65536;
        fw.Wupd[5] = aa_Wupd1; fw.W[5] = aa_Wdst1; fw.off[5] = 0; fw.dW[5] = DAv; fw.out[5] = Wtmp + 1 * 65536;
        // z6: t2_ba  z7: eB2 dst -> WB2
        fw.Wupd[6] = wu2[1]; fw.W[6] = Wsrc2 + 1 * (size_t)Hh * Hh; fw.off[6] = Hh; fw.dW[6] = Hh; fw.out[6] = WB2;
        fw.Wupd[7] = wu2[0]; fw.W[7] = Wdst2 + 0 * (size_t)Hh * Hh; fw.off[7] = 0;  fw.dW[7] = Hh; fw.out[7] = WB2 + 256 * 256;
        // z8: t2_aa  z9: t2_ab -> WtA2
        fw.Wupd[8] = wu2[2]; fw.W[8] = Wsrc2 + 2 * (size_t)Hh * Hh; fw.off[8] = Hh; fw.dW[8] = Hh; fw.out[8] = WtA2;
        fw.Wupd[9] = wu2[0]; fw.W[9] = Wsrc2 + 0 * (size_t)Hh * Hh; fw.off[9] = Hh; fw.dW[9] = Hh; fw.out[9] = WtA2 + 256 * 256;
        // z10/z11: ba2/aa2 dst -> temps (assembled into WdA2)
        fw.Wupd[10] = wu2[1]; fw.W[10] = Wdst2 + 1 * (size_t)Hh * Hh; fw.off[10] = 0; fw.dW[10] = Hh; fw.out[10] = Wtmp + 2 * 65536;
        fw.Wupd[11] = wu2[2]; fw.W[11] = Wdst2 + 2 * (size_t)Hh * Hh; fw.off[11] = 0; fw.dW[11] = Hh; fw.out[11] = Wtmp + 3 * 65536;
        fuse_w_all_k<<<dim3(Hh, 12), 256, 0, s0>>>(fw);

        FuseBArgs fb;
        // conv ab -> biasB1[256:512]
        fb.Wupd[0] = ab_Wupd1; fb.bdst[0] = ab_bdst1; fb.bsrc[0] = ab_bsrc1; fb.bupd[0] = ab_bupd1; fb.out[0] = biasB1 + 256;
        // conv ba, aa -> temps
        fb.Wupd[1] = ba_Wupd1; fb.bdst[1] = ba_bdst1; fb.bsrc[1] = ba_bsrc1; fb.bupd[1] = ba_bupd1; fb.out[1] = btmp + 0 * 256;
        fb.Wupd[2] = aa_Wupd1; fb.bdst[2] = aa_bdst1; fb.bsrc[2] = aa_bsrc1; fb.bupd[2] = aa_bupd1; fb.out[2] = btmp + 1 * 256;
        // conv ab2 -> biasB2[256:512]
        fb.Wupd[3] = wu2[0]; fb.bdst[3] = bdst2 + 0 * Hh; fb.bsrc[3] = bsrc2 + 0 * Hh; fb.bupd[3] = bupd2 + 0 * Hh; fb.out[3] = biasB2 + 256;
        // conv ba2, aa2 -> temps
        fb.Wupd[4] = wu2[1]; fb.bdst[4] = bdst2 + 1 * Hh; fb.bsrc[4] = bsrc2 + 1 * Hh; fb.bupd[4] = bupd2 + 1 * Hh; fb.out[4] = btmp + 2 * 256;
        fb.Wupd[5] = wu2[2]; fb.bdst[5] = bdst2 + 2 * Hh; fb.bsrc[5] = bsrc2 + 2 * Hh; fb.bupd[5] = bupd2 + 2 * Hh; fb.out[5] = btmp + 3 * 256;
        fuse_bias_all_k<<<6, Hh, 0, s0>>>(fb);
        assemble_k<<<dim3(256, 2), 256, 0, s0>>>(Wtmp, btmp, WdA, WdA2, bdA,
                                                 bdA2, biasB1, biasB2);
    }
    cudaEventRecord(evFuse, s0);

    // ===== s0: x_A family ==================================================
    run_gemm(s0, x_A, WtA, nullptr, TtA, Nn, DAv, 512);   // [t_ab | t_aa]
    cudaEventRecord(evTA, s0);
    run_gemm(s0, x_A, WdA, bdA, TdA, Nn, DAv, 256);       // eA

    // ===== s1: CSR build then x_B family ===================================
    cudaMemsetAsync(deg, 0, 3 * Nn * sizeof(int), s1);
    hist_k<<<(Ee + 255) / 256, 256, 0, s1>>>(e_ab + Ee, deg + 0 * Nn);
    hist_k<<<(Ee + 255) / 256, 256, 0, s1>>>(e_ba + Ee, deg + 1 * Nn);
    hist_k<<<(Ee + 255) / 256, 256, 0, s1>>>(e_aa + Ee, deg + 2 * Nn);
    scan_k<<<3, SCAN_T, 0, s1>>>(deg, base, cursor);
    permute_k<<<(Ee + 255) / 256, 256, 0, s1>>>(e_ab, e_ab + Ee, CUR(0), CSR(0));
    permute_k<<<(Ee + 255) / 256, 256, 0, s1>>>(e_ba, e_ba + Ee, CUR(1), CSR(1));
    permute_k<<<(Ee + 255) / 256, 256, 0, s1>>>(e_aa, e_aa + Ee, CUR(2), CSR(2));
    cudaStreamWaitEvent(s1, evFuse, 0);
    run_gemm(s1, x_B, WB1, biasB1, TB1, Nn, DBv, 512);    // [t_ba | eB]
    cudaEventRecord(evB1, s1);

    // ===== layer-1 gathers =================================================
    run_gather(s1, TB1, 512, CSR(1), BASE(1), AGGR(1));   // aA1a (t_ba)
    cudaEventRecord(evA1a, s1);
    cudaStreamWaitEvent(s2, evTA, 0);
    run_gather(s2, TtA, 512, CSR(0), BASE(0), AGGR(0));   // aB1 (t_ab)
    cudaEventRecord(evB1g, s2);
    cudaStreamWaitEvent(s1, evTA, 0);
    run_gather(s1, TtA + 256, 512, CSR(2), BASE(2), AGGR(2));  // aA1b (t_aa)
    cudaEventRecord(evA1b, s1);

    // ===== s0: BN_B1 -> hB; s1: hB family ==================================
    cudaStreamWaitEvent(s0, evB1, 0);
    cudaStreamWaitEvent(s0, evB1g, 0);
    run_bn(s0, TB1 + 256, 512, AGGR(0), nullptr, 1.0f, bn_g + 1 * Hh,
           bn_b + 1 * Hh, hB, stats, prm);
    cudaEventRecord(evHB, s0);
    cudaStreamWaitEvent(s1, evHB, 0);
    run_gemm(s1, hB, WB2, biasB2, TB2, Nn, Hh, 512);      // [t2_ba | eB2]
    cudaEventRecord(evB2, s1);

    // ===== s0: BN_A1 -> hA; hA family ======================================
    cudaStreamWaitEvent(s0, evA1a, 0);
    cudaStreamWaitEvent(s0, evA1b, 0);
    run_bn(s0, TdA, 256, AGGR(1), AGGR(2), 0.5f, bn_g + 0 * Hh, bn_b + 0 * Hh,
           hA, stats, prm);
    run_gemm(s0, hA, WtA2, nullptr, TtA2, Nn, Hh, 512);   // [t2_aa | t2_ab]
    cudaEventRecord(evTA2, s0);
    run_gemm(s0, hA, WdA2, bdA2, TdA2, Nn, Hh, 256);      // eA2

    // ===== layer-2 gathers (parallel on s1/s2) =============================
    cudaStreamWaitEvent(s2, evB2, 0);
    run_gather(s2, TB2, 512, CSR(1), BASE(1), AGGR(3));   // aA2a (t2_ba)
    cudaEventRecord(evA2a, s2);
    cudaStreamWaitEvent(s1, evTA2, 0);
    run_gather(s1, TtA2, 512, CSR(2), BASE(2), AGGR(4));  // aA2b (t2_aa)
    cudaEventRecord(evA2b, s1);
    cudaStreamWaitEvent(s2, evTA2, 0);
    run_gather(s2, TtA2 + 256, 512, CSR(0), BASE(0), AGGR(5));  // aB2 (t2_ab)
    cudaEventRecord(evB2g, s2);

    // ===== s0: output BNs ==================================================
    cudaStreamWaitEvent(s0, evA2a, 0);
    cudaStreamWaitEvent(s0, evA2b, 0);
    run_bn(s0, TdA2, 256, AGGR(3), AGGR(4), 0.5f, bn_g + 2 * Hh, bn_b + 2 * Hh,
           out, stats, prm);
    cudaStreamWaitEvent(s0, evB2, 0);
    cudaStreamWaitEvent(s0, evB2g, 0);
    run_bn(s0, TB2 + 256, 512, AGGR(5), nullptr, 1.0f, bn_g + 3 * Hh,
           bn_b + 3 * Hh, out + (size_t)Nn * Hh, stats, prm);
}

// round 9
// speedup vs baseline: 3.1795x; 1.1263x over previous
#include <cuda_runtime.h>
#include <cstdint>

#define Nn 50000
#define Ee 800000
#define DAv 256
#define DBv 128
#define Hh 256
#define EPSv 1e-5f
#define SLOPEv 0.01f

// ---------------- scratch (static device globals; no allocation) -------------
__device__ float g_TtA[(size_t)Nn * 512];    // [t_ab | t_aa]
__device__ float g_TB1[(size_t)Nn * 512];    // [t_ba | eB]
__device__ float g_TdA[(size_t)Nn * 256];    // eA
__device__ float g_TB2[(size_t)Nn * 512];    // [t2_ba | eB2]
__device__ float g_TtA2[(size_t)Nn * 512];   // [t2_aa | t2_ab]
__device__ float g_TdA2[(size_t)Nn * 256];   // eA2
__device__ float g_aggr[6][(size_t)Nn * 256];
__device__ float g_hA[(size_t)Nn * Hh];
__device__ float g_hB[(size_t)Nn * Hh];
__device__ int g_deg[3][Nn];
__device__ int g_base[3][Nn + 1];
__device__ int g_cursor[3][Nn];
__device__ int g_csr[3][Ee];
// merged weights
__device__ float g_WtA[512 * 256];
__device__ float g_WB1[512 * 128];
__device__ float g_WdA[256 * 256];
__device__ float g_WB2[512 * 256];
__device__ float g_WtA2[512 * 256];
__device__ float g_WdA2[256 * 256];
__device__ float g_biasB1[512];
__device__ float g_biasB2[512];
__device__ float g_bdA[256];
__device__ float g_bdA2[256];
__device__ float g_Wtmp[4][256 * 256];
__device__ float g_btmp[4][256];
__device__ float g_stats[2 * Hh];
__device__ float g_prm[2 * Hh];

// ---------------- mma helpers -------------------------------------------------
__device__ __forceinline__ uint32_t tf32u(float x) {
    uint32_t u;
    asm("cvt.rna.tf32.f32 %0, %1;" : "=r"(u) : "f"(x));
    return u;
}
__device__ __forceinline__ void mma8(float* d, const uint32_t* a,
                                     const uint32_t* b) {
    asm volatile(
        "mma.sync.aligned.m16n8k8.row.col.f32.tf32.tf32.f32 "
        "{%0,%1,%2,%3}, {%4,%5,%6,%7}, {%8,%9}, {%0,%1,%2,%3};"
        : "+f"(d[0]), "+f"(d[1]), "+f"(d[2]), "+f"(d[3])
        : "r"(a[0]), "r"(a[1]), "r"(a[2]), "r"(a[3]), "r"(b[0]), "r"(b[1]));
}

// ---- tensor-core GEMM: C[M x N] = A[M x K] @ W[N x K]^T (+bias), 3xTF32 ----
// 128x128 tile, 8 warps (2x4), warp tile 64x32, m16n8k8 frags, K-chunk 32.
#define SROW 133
#define TBUF (32 * SROW)
#define GM_BUF (2 * TBUF)
#define GM_SMEM (2 * GM_BUF * 4)
__global__ void __launch_bounds__(256, 1)
gemm_mma_k(const float* __restrict__ A, const float* __restrict__ W,
           const float* __restrict__ bias, float* __restrict__ C, int M,
           int K) {
    extern __shared__ float sm[];
    int tid = threadIdx.x;
    int wid = tid >> 5;
    int lane = tid & 31;
    int mBase = blockIdx.x * 128;
    int nBase = blockIdx.y * 128;
    int ldc = (int)gridDim.y * 128;
    int warp_m = wid >> 2;
    int warp_n = wid & 3;

    float d[4][4][4];
#pragma unroll
    for (int i = 0; i < 4; i++)
#pragma unroll
        for (int j = 0; j < 4; j++)
#pragma unroll
            for (int q = 0; q < 4; q++) d[i][j][q] = 0.f;

    int lrow = tid >> 2;         // 0..63
    int lcc = (tid & 3) * 8;     // 0,8,16,24

    float4 sa[4], sw[4];
    auto gload = [&](int k0) {
#pragma unroll
        for (int h = 0; h < 2; h++) {
            int row = lrow + h * 64;
            int arow = mBase + row;
            if (arow < M) {
                const float* ap = A + (size_t)arow * K + k0 + lcc;
                sa[2 * h] = *(const float4*)ap;
                sa[2 * h + 1] = *(const float4*)(ap + 4);
            } else {
                sa[2 * h] = make_float4(0.f, 0.f, 0.f, 0.f);
                sa[2 * h + 1] = make_float4(0.f, 0.f, 0.f, 0.f);
            }
            const float* wp = W + (size_t)(nBase + row) * K + k0 + lcc;
            sw[2 * h] = *(const float4*)wp;
            sw[2 * h + 1] = *(const float4*)(wp + 4);
        }
    };
    auto sstore = [&](int b) {
        float* As = sm + b * GM_BUF;
        float* Ws = As + TBUF;
#pragma unroll
        for (int h = 0; h < 2; h++) {
            int row = lrow + h * 64;
            const float* a0 = (const float*)&sa[2 * h];
            const float* a1 = (const float*)&sa[2 * h + 1];
            const float* w0 = (const float*)&sw[2 * h];
            const float* w1 = (const float*)&sw[2 * h + 1];
#pragma unroll
            for (int j = 0; j < 4; j++) {
                As[(lcc + j) * SROW + row] = a0[j];
                As[(lcc + 4 + j) * SROW + row] = a1[j];
                Ws[(lcc + j) * SROW + row] = w0[j];
                Ws[(lcc + 4 + j) * SROW + row] = w1[j];
            }
        }
    };

    gload(0);
    sstore(0);
    __syncthreads();

    int nc = K >> 5;
    for (int c = 0; c < nc; c++) {
        int b = c & 1;
        if (c + 1 < nc) gload((c + 1) * 32);
        const float* As = sm + b * GM_BUF;
        const float* Ws = As + TBUF;
#pragma unroll
        for (int ks = 0; ks < 4; ks++) {
            int krow = ks * 8 + (lane & 3);
            uint32_t ah[4][4], al[4][4], bh[4][2], bl[4][2];
            int r0 = warp_m * 64 + (lane >> 2);
#pragma unroll
            for (int mf = 0; mf < 4; mf++) {
                int rb = r0 + mf * 16;
                float v0 = As[krow * SROW + rb];
                float v1 = As[krow * SROW + rb + 8];
                float v2 = As[(krow + 4) * SROW + rb];
                float v3 = As[(krow + 4) * SROW + rb + 8];
                ah[mf][0] = tf32u(v0);
                al[mf][0] = tf32u(v0 - __uint_as_float(ah[mf][0]));
                ah[mf][1] = tf32u(v1);
                al[mf][1] = tf32u(v1 - __uint_as_float(ah[mf][1]));
                ah[mf][2] = tf32u(v2);
                al[mf][2] = tf32u(v2 - __uint_as_float(ah[mf][2]));
                ah[mf][3] = tf32u(v3);
                al[mf][3] = tf32u(v3 - __uint_as_float(ah[mf][3]));
            }
            int c0 = warp_n * 32 + (lane >> 2);
#pragma unroll
            for (int nf = 0; nf < 4; nf++) {
                float v0 = Ws[krow * SROW + c0 + nf * 8];
                float v1 = Ws[(krow + 4) * SROW + c0 + nf * 8];
                bh[nf][0] = tf32u(v0);
                bl[nf][0] = tf32u(v0 - __uint_as_float(bh[nf][0]));
                bh[nf][1] = tf32u(v1);
                bl[nf][1] = tf32u(v1 - __uint_as_float(bh[nf][1]));
            }
#pragma unroll
            for (int mf = 0; mf < 4; mf++)
#pragma unroll
                for (int nf = 0; nf < 4; nf++) mma8(d[mf][nf], ah[mf], bh[nf]);
#pragma unroll
            for (int mf = 0; mf < 4; mf++)
#pragma unroll
                for (int nf = 0; nf < 4; nf++) mma8(d[mf][nf], ah[mf], bl[nf]);
#pragma unroll
            for (int mf = 0; mf < 4; mf++)
#pragma unroll
                for (int nf = 0; nf < 4; nf++) mma8(d[mf][nf], al[mf], bh[nf]);
        }
        if (c + 1 < nc) sstore((c + 1) & 1);
        __syncthreads();
    }

    // epilogue
#pragma unroll
    for (int mf = 0; mf < 4; mf++) {
        int row0 = mBase + warp_m * 64 + mf * 16 + (lane >> 2);
#pragma unroll
        for (int nf = 0; nf < 4; nf++) {
            int col = nBase + warp_n * 32 + nf * 8 + (lane & 3) * 2;
            float b0 = 0.f, b1 = 0.f;
            if (bias) {
                b0 = bias[col];
                b1 = bias[col + 1];
            }
            if (row0 < M) {
                float2 v = make_float2(d[mf][nf][0] + b0, d[mf][nf][1] + b1);
                *(float2*)(C + (size_t)row0 * ldc + col) = v;
            }
            if (row0 + 8 < M) {
                float2 v = make_float2(d[mf][nf][2] + b0, d[mf][nf][3] + b1);
                *(float2*)(C + (size_t)(row0 + 8) * ldc + col) = v;
            }
        }
    }
}

// ---------------- CSR build ---------------------------------------------------

__global__ void hist_k(const int* __restrict__ dst, int* __restrict__ deg) {
    int i = blockIdx.x * blockDim.x + threadIdx.x;
    if (i < Ee) atomicAdd(&deg[dst[i]], 1);
}

#define SCAN_T 1024
__global__ void scan_k(const int* __restrict__ deg_all,
                       int* __restrict__ base_all,
                       int* __restrict__ cur_all) {
    int z = blockIdx.x;
    const int* deg = deg_all + (size_t)z * Nn;
    int* base = base_all + (size_t)z * (Nn + 1);
    int* cur = cur_all + (size_t)z * Nn;
    __shared__ int sb[SCAN_T];
    int tid = threadIdx.x;
    const int CH = (Nn + SCAN_T - 1) / SCAN_T;
    int lo = tid * CH;
    int hi = lo + CH < Nn ? lo + CH : Nn;
    if (lo > Nn) lo = Nn;
    int s = 0;
    for (int i = lo; i < hi; i++) s += deg[i];
    sb[tid] = s;
    __syncthreads();
    for (int d = 1; d < SCAN_T; d <<= 1) {
        int v = (tid >= d) ? sb[tid - d] : 0;
        __syncthreads();
        sb[tid] += v;
        __syncthreads();
    }
    int run = sb[tid] - s;
    for (int i = lo; i < hi; i++) {
        base[i] = run;
        cur[i] = run;
        run += deg[i];
    }
    if (tid == SCAN_T - 1) base[Nn] = run;
}

__global__ void permute_k(const int* __restrict__ src,
                          const int* __restrict__ dst,
                          int* __restrict__ cur, int* __restrict__ csr) {
    int i = blockIdx.x * blockDim.x + threadIdx.x;
    if (i >= Ee) return;
    int d = dst[i];
    int p = atomicAdd(&cur[d], 1);
    csr[p] = src[i];
}

// ---- gather-mean from a strided source block --------------------------------
__global__ void __launch_bounds__(256)
gather_sum_k(const float* __restrict__ t, int ldt, const int* __restrict__ csr,
             const int* __restrict__ base, float* __restrict__ out) {
    int node = blockIdx.x * 4 + (threadIdx.x >> 6);
    int c4 = threadIdx.x & 63;
    if (node >= Nn) return;
    int s0 = __ldg(base + node);
    int s1 = __ldg(base + node + 1);
    float4 acc = make_float4(0.f, 0.f, 0.f, 0.f);
    int i = s0;
    for (; i + 4 <= s1; i += 4) {
        int a0 = __ldg(csr + i), a1 = __ldg(csr + i + 1);
        int a2 = __ldg(csr + i + 2), a3 = __ldg(csr + i + 3);
        float4 v0 = *(const float4*)(t + (size_t)a0 * ldt + c4 * 4);
        float4 v1 = *(const float4*)(t + (size_t)a1 * ldt + c4 * 4);
        float4 v2 = *(const float4*)(t + (size_t)a2 * ldt + c4 * 4);
        float4 v3 = *(const float4*)(t + (size_t)a3 * ldt + c4 * 4);
        acc.x += v0.x + v1.x + v2.x + v3.x;
        acc.y += v0.y + v1.y + v2.y + v3.y;
        acc.z += v0.z + v1.z + v2.z + v3.z;
        acc.w += v0.w + v1.w + v2.w + v3.w;
    }
    for (; i < s1; i++) {
        int a = __ldg(csr + i);
        float4 v = *(const float4*)(t + (size_t)a * ldt + c4 * 4);
        acc.x += v.x; acc.y += v.y; acc.z += v.z; acc.w += v.w;
    }
    float w = 1.0f / fmaxf((float)(s1 - s0), 1.0f);
    acc.x *= w; acc.y *= w; acc.z *= w; acc.w *= w;
    *(float4*)(out + (size_t)node * 256 + c4 * 4) = acc;
}

// ---- batched weight fusion ----
struct FuseWArgs {
    const float* Wupd[12];
    const float* W[12];
    int off[12];
    int dW[12];
    float* out[12];
};
__global__ void fuse_w_all_k(FuseWArgs a) {
    int z = blockIdx.y;
    int o = blockIdx.x;
    int k = threadIdx.x;
    int dW = a.dW[z];
    if (k >= dW) return;
    const float* wrow = a.Wupd[z] + (size_t)o * (2 * Hh) + a.off[z];
    const float* W = a.W[z];
    float s = 0.0f;
#pragma unroll 8
    for (int j = 0; j < Hh; j++) s += wrow[j] * W[(size_t)j * dW + k];
    a.out[z][(size_t)o * dW + k] = s;
}

struct FuseBArgs {
    const float* Wupd[6];
    const float* bdst[6];
    const float* bsrc[6];
    const float* bupd[6];
    float* out[6];
};
__global__ void fuse_bias_all_k(FuseBArgs a) {
    int z = blockIdx.x;
    int o = threadIdx.x;
    const float* wrow = a.Wupd[z] + (size_t)o * (2 * Hh);
    const float* bdst = a.bdst[z];
    const float* bsrc = a.bsrc[z];
    float s = a.bupd[z][o];
#pragma unroll 8
    for (int j = 0; j < Hh; j++) s += wrow[j] * bdst[j] + wrow[Hh + j] * bsrc[j];
    a.out[z][o] = s;
}

__global__ void assemble_k(const float* __restrict__ Wtmp,
                           const float* __restrict__ btmp,
                           float* __restrict__ WdA, float* __restrict__ WdA2,
                           float* __restrict__ bdA, float* __restrict__ bdA2,
                           float* __restrict__ biasB1, float* __restrict__ biasB2) {
    int z = blockIdx.y;
    int i = blockIdx.x * blockDim.x + threadIdx.x;
    const float* a = Wtmp + (size_t)(z * 2) * 65536;
    const float* b = Wtmp + (size_t)(z * 2 + 1) * 65536;
    float* W = z ? WdA2 : WdA;
    if (i < 65536) W[i] = a[i] + b[i];
    if (i < 256) {
        (z ? bdA2 : bdA)[i] = btmp[(z * 2) * 256 + i] + btmp[(z * 2 + 1) * 256 + i];
        (z ? biasB2 : biasB1)[i] = 0.f;
    }
}

// ---- BN (strided x, fused add of 1-2 aggregate buffers) ----
#define ROWS_PER_BLK 256
__global__ void col_stats3_k(const float* __restrict__ x, int ldx,
                             const float* __restrict__ a1,
                             const float* __restrict__ a2, float prescale,
                             float* __restrict__ sums) {
    int c = threadIdx.x;
    int r0 = blockIdx.x * ROWS_PER_BLK;
    int r1 = r0 + ROWS_PER_BLK;
    if (r1 > Nn) r1 = Nn;
    float s = 0.0f, s2 = 0.0f;
    for (int r = r0; r < r1; r++) {
        float v = x[(size_t)r * ldx + c] + a1[(size_t)r * 256 + c];
        if (a2) v += a2[(size_t)r * 256 + c];
        v *= prescale;
        s += v;
        s2 += v * v;
    }
    atomicAdd(&sums[c], s);
    atomicAdd(&sums[Hh + c], s2);
}

__global__ void bn_finalize_k(const float* __restrict__ sums,
                              const float* __restrict__ g,
                              const float* __restrict__ b,
                              float* __restrict__ prm) {
    int c = threadIdx.x;
    float mean = sums[c] / (float)Nn;
    float var = sums[Hh + c] / (float)Nn - mean * mean;
    float sc = g[c] * rsqrtf(var + EPSv);
    prm[c] = sc;
    prm[Hh + c] = b[c] - mean * sc;
}

__global__ void bn_apply3_k(const float* __restrict__ x, int ldx,
                            const float* __restrict__ a1,
                            const float* __restrict__ a2,
                            const float* __restrict__ prm, float prescale,
                            float* __restrict__ y) {
    int i = blockIdx.x * blockDim.x + threadIdx.x;
    if (i >= Nn * (Hh / 4)) return;
    int r = i >> 6;
    int c = (i & 63) * 4;
    float4 v = *(const float4*)(x + (size_t)r * ldx + c);
    float4 g1 = *(const float4*)(a1 + (size_t)r * 256 + c);
    if (a2) {
        float4 g2 = *(const float4*)(a2 + (size_t)r * 256 + c);
        v.x += g2.x; v.y += g2.y; v.z += g2.z; v.w += g2.w;
    }
    float4 sc = *(const float4*)(prm + c);
    float4 sh = *(const float4*)(prm + Hh + c);
    float t0 = (v.x + g1.x) * prescale * sc.x + sh.x;
    float t1 = (v.y + g1.y) * prescale * sc.y + sh.y;
    float t2 = (v.z + g1.z) * prescale * sc.z + sh.z;
    float t3 = (v.w + g1.w) * prescale * sc.w + sh.w;
    float4 r4;
    r4.x = t0 >= 0.f ? t0 : SLOPEv * t0;
    r4.y = t1 >= 0.f ? t1 : SLOPEv * t1;
    r4.z = t2 >= 0.f ? t2 : SLOPEv * t2;
    r4.w = t3 >= 0.f ? t3 : SLOPEv * t3;
    *(float4*)(y + (size_t)r * 256 + c) = r4;
}

// ---------------- host orchestration ----------------------------------------

static void run_gemm(cudaStream_t st, const float* A, const float* W,
                     const float* bias, float* C, int M, int K, int N) {
    dim3 grid((M + 127) / 128, N / 128);
    gemm_mma_k<<<grid, 256, GM_SMEM, st>>>(A, W, bias, C, M, K);
}

static void run_gather(cudaStream_t st, const float* t, int ldt, const int* csr,
                       const int* base, float* out) {
    gather_sum_k<<<(Nn + 3) / 4, 256, 0, st>>>(t, ldt, csr, base, out);
}

static void run_bn(cudaStream_t st, const float* x, int ldx, const float* a1,
                   const float* a2, float prescale, const float* g,
                   const float* b, float* y, float* stats, float* prm) {
    cudaMemsetAsync(stats, 0, 2 * Hh * sizeof(float), st);
    col_stats3_k<<<(Nn + ROWS_PER_BLK - 1) / ROWS_PER_BLK, Hh, 0, st>>>(x, ldx, a1, a2, prescale, stats);
    bn_finalize_k<<<1, Hh, 0, st>>>(stats, g, b, prm);
    bn_apply3_k<<<(Nn * (Hh / 4) + 255) / 256, 256, 0, st>>>(x, ldx, a1, a2, prm, prescale, y);
}

extern "C" void kernel_launch(void* const* d_in, const int* in_sizes, int n_in,
                              void* d_out, int out_size) {
    const float* x_A = (const float*)d_in[0];
    const float* x_B = (const float*)d_in[1];
    const int* e_ab = (const int*)d_in[2];
    const int* e_ba = (const int*)d_in[3];
    const int* e_aa = (const int*)d_in[4];
    const float* ab_Wsrc1 = (const float*)d_in[5];
    const float* ab_bsrc1 = (const float*)d_in[6];
    const float* ab_Wdst1 = (const float*)d_in[7];
    const float* ab_bdst1 = (const float*)d_in[8];
    const float* ab_Wupd1 = (const float*)d_in[9];
    const float* ab_bupd1 = (const float*)d_in[10];
    const float* ba_Wsrc1 = (const float*)d_in[11];
    const float* ba_bsrc1 = (const float*)d_in[12];
    const float* ba_Wdst1 = (const float*)d_in[13];
    const float* ba_bdst1 = (const float*)d_in[14];
    const float* ba_Wupd1 = (const float*)d_in[15];
    const float* ba_bupd1 = (const float*)d_in[16];
    const float* aa_Wsrc1 = (const float*)d_in[17];
    const float* aa_bsrc1 = (const float*)d_in[18];
    const float* aa_Wdst1 = (const float*)d_in[19];
    const float* aa_bdst1 = (const float*)d_in[20];
    const float* aa_Wupd1 = (const float*)d_in[21];
    const float* aa_bupd1 = (const float*)d_in[22];
    const float* Wsrc2 = (const float*)d_in[23];
    const float* bsrc2 = (const float*)d_in[24];
    const float* Wdst2 = (const float*)d_in[25];
    const float* bdst2 = (const float*)d_in[26];
    const float* Wupd2 = (const float*)d_in[27];
    const float* bupd2 = (const float*)d_in[28];
    const float* bn_g = (const float*)d_in[29];
    const float* bn_b = (const float*)d_in[30];
    float* out = (float*)d_out;

    float *TtA, *TB1, *TdA, *TB2, *TtA2, *TdA2, *aggr, *hA, *hB;
    float *WtA, *WB1, *WdA, *WB2, *WtA2, *WdA2;
    float *biasB1, *biasB2, *bdA, *bdA2, *Wtmp, *btmp, *stats, *prm;
    int *deg, *base, *cursor, *csr;
    cudaGetSymbolAddress((void**)&TtA, g_TtA);
    cudaGetSymbolAddress((void**)&TB1, g_TB1);
    cudaGetSymbolAddress((void**)&TdA, g_TdA);
    cudaGetSymbolAddress((void**)&TB2, g_TB2);
    cudaGetSymbolAddress((void**)&TtA2, g_TtA2);
    cudaGetSymbolAddress((void**)&TdA2, g_TdA2);
    cudaGetSymbolAddress((void**)&aggr, g_aggr);
    cudaGetSymbolAddress((void**)&hA, g_hA);
    cudaGetSymbolAddress((void**)&hB, g_hB);
    cudaGetSymbolAddress((void**)&WtA, g_WtA);
    cudaGetSymbolAddress((void**)&WB1, g_WB1);
    cudaGetSymbolAddress((void**)&WdA, g_WdA);
    cudaGetSymbolAddress((void**)&WB2, g_WB2);
    cudaGetSymbolAddress((void**)&WtA2, g_WtA2);
    cudaGetSymbolAddress((void**)&WdA2, g_WdA2);
    cudaGetSymbolAddress((void**)&biasB1, g_biasB1);
    cudaGetSymbolAddress((void**)&biasB2, g_biasB2);
    cudaGetSymbolAddress((void**)&bdA, g_bdA);
    cudaGetSymbolAddress((void**)&bdA2, g_bdA2);
    cudaGetSymbolAddress((void**)&Wtmp, g_Wtmp);
    cudaGetSymbolAddress((void**)&btmp, g_btmp);
    cudaGetSymbolAddress((void**)&stats, g_stats);
    cudaGetSymbolAddress((void**)&prm, g_prm);
    cudaGetSymbolAddress((void**)&deg, g_deg);
    cudaGetSymbolAddress((void**)&base, g_base);
    cudaGetSymbolAddress((void**)&cursor, g_cursor);
    cudaGetSymbolAddress((void**)&csr, g_csr);

#define AGGR(i) (aggr + (size_t)(i) * Nn * 256)
#define BASE(z) (base + (size_t)(z) * (Nn + 1))
#define CUR(z) (cursor + (size_t)(z) * Nn)
#define CSR(z) (csr + (size_t)(z) * Ee)

    static cudaStream_t s1 = nullptr, s2 = nullptr;
    static cudaEvent_t evFork, evFuse, evTA, evB1, evB1g, evA1a, evA1b, evHB,
        evB2, evTA2, evA2a, evA2b, evB2g;
    if (!s1) {
        cudaStreamCreateWithFlags(&s1, cudaStreamNonBlocking);
        cudaStreamCreateWithFlags(&s2, cudaStreamNonBlocking);
        cudaEvent_t* evs[] = {&evFork, &evFuse, &evTA, &evB1, &evB1g, &evA1a,
                              &evA1b, &evHB, &evB2, &evTA2, &evA2a, &evA2b,
                              &evB2g};
        for (auto e : evs) cudaEventCreateWithFlags(e, cudaEventDisableTiming);
        cudaFuncSetAttribute(gemm_mma_k,
                             cudaFuncAttributeMaxDynamicSharedMemorySize,
                             GM_SMEM);
    }
    cudaStream_t s0 = 0;

    cudaEventRecord(evFork, s0);
    cudaStreamWaitEvent(s1, evFork, 0);
    cudaStreamWaitEvent(s2, evFork, 0);

    // ===== s0: weight fusion into merged buffers ===========================
    {
        FuseWArgs fw;
        const float* wu2[3] = {Wupd2 + 0 * (size_t)Hh * 2 * Hh,
                               Wupd2 + 1 * (size_t)Hh * 2 * Hh,
                               Wupd2 + 2 * (size_t)Hh * 2 * Hh};
        fw.Wupd[0] = ab_Wupd1; fw.W[0] = ab_Wsrc1; fw.off[0] = Hh; fw.dW[0] = DAv; fw.out[0] = WtA;
        fw.Wupd[1] = aa_Wupd1; fw.W[1] = aa_Wsrc1; fw.off[1] = Hh; fw.dW[1] = DAv; fw.out[1] = WtA + 256 * 256;
        fw.Wupd[2] = ba_Wupd1; fw.W[2] = ba_Wsrc1; fw.off[2] = Hh; fw.dW[2] = DBv; fw.out[2] = WB1;
        fw.Wupd[3] = ab_Wupd1; fw.W[3] = ab_Wdst1; fw.off[3] = 0;  fw.dW[3] = DBv; fw.out[3] = WB1 + 256 * 128;
        fw.Wupd[4] = ba_Wupd1; fw.W[4] = ba_Wdst1; fw.off[4] = 0; fw.dW[4] = DAv; fw.out[4] = Wtmp + 0 * 65536;
        fw.Wupd[5] = aa_Wupd1; fw.W[5] = aa_Wdst1; fw.off[5] = 0; fw.dW[5] = DAv; fw.out[5] = Wtmp + 1 * 65536;
        fw.Wupd[6] = wu2[1]; fw.W[6] = Wsrc2 + 1 * (size_t)Hh * Hh; fw.off[6] = Hh; fw.dW[6] = Hh; fw.out[6] = WB2;
        fw.Wupd[7] = wu2[0]; fw.W[7] = Wdst2 + 0 * (size_t)Hh * Hh; fw.off[7] = 0;  fw.dW[7] = Hh; fw.out[7] = WB2 + 256 * 256;
        fw.Wupd[8] = wu2[2]; fw.W[8] = Wsrc2 + 2 * (size_t)Hh * Hh; fw.off[8] = Hh; fw.dW[8] = Hh; fw.out[8] = WtA2;
        fw.Wupd[9] = wu2[0]; fw.W[9] = Wsrc2 + 0 * (size_t)Hh * Hh; fw.off[9] = Hh; fw.dW[9] = Hh; fw.out[9] = WtA2 + 256 * 256;
        fw.Wupd[10] = wu2[1]; fw.W[10] = Wdst2 + 1 * (size_t)Hh * Hh; fw.off[10] = 0; fw.dW[10] = Hh; fw.out[10] = Wtmp + 2 * 65536;
        fw.Wupd[11] = wu2[2]; fw.W[11] = Wdst2 + 2 * (size_t)Hh * Hh; fw.off[11] = 0; fw.dW[11] = Hh; fw.out[11] = Wtmp + 3 * 65536;
        fuse_w_all_k<<<dim3(Hh, 12), 256, 0, s0>>>(fw);

        FuseBArgs fb;
        fb.Wupd[0] = ab_Wupd1; fb.bdst[0] = ab_bdst1; fb.bsrc[0] = ab_bsrc1; fb.bupd[0] = ab_bupd1; fb.out[0] = biasB1 + 256;
        fb.Wupd[1] = ba_Wupd1; fb.bdst[1] = ba_bdst1; fb.bsrc[1] = ba_bsrc1; fb.bupd[1] = ba_bupd1; fb.out[1] = btmp + 0 * 256;
        fb.Wupd[2] = aa_Wupd1; fb.bdst[2] = aa_bdst1; fb.bsrc[2] = aa_bsrc1; fb.bupd[2] = aa_bupd1; fb.out[2] = btmp + 1 * 256;
        fb.Wupd[3] = wu2[0]; fb.bdst[3] = bdst2 + 0 * Hh; fb.bsrc[3] = bsrc2 + 0 * Hh; fb.bupd[3] = bupd2 + 0 * Hh; fb.out[3] = biasB2 + 256;
        fb.Wupd[4] = wu2[1]; fb.bdst[4] = bdst2 + 1 * Hh; fb.bsrc[4] = bsrc2 + 1 * Hh; fb.bupd[4] = bupd2 + 1 * Hh; fb.out[4] = btmp + 2 * 256;
        fb.Wupd[5] = wu2[2]; fb.bdst[5] = bdst2 + 2 * Hh; fb.bsrc[5] = bsrc2 + 2 * Hh; fb.bupd[5] = bupd2 + 2 * Hh; fb.out[5] = btmp + 3 * 256;
        fuse_bias_all_k<<<6, Hh, 0, s0>>>(fb);
        assemble_k<<<dim3(256, 2), 256, 0, s0>>>(Wtmp, btmp, WdA, WdA2, bdA,
                                                 bdA2, biasB1, biasB2);
    }
    cudaEventRecord(evFuse, s0);

    // ===== s0: x_A family ==================================================
    run_gemm(s0, x_A, WtA, nullptr, TtA, Nn, DAv, 512);   // [t_ab | t_aa]
    cudaEventRecord(evTA, s0);
    run_gemm(s0, x_A, WdA, bdA, TdA, Nn, DAv, 256);       // eA

    // ===== s1: CSR build then x_B family ===================================
    cudaMemsetAsync(deg, 0, 3 * Nn * sizeof(int), s1);
    hist_k<<<(Ee + 255) / 256, 256, 0, s1>>>(e_ab + Ee, deg + 0 * Nn);
    hist_k<<<(Ee + 255) / 256, 256, 0, s1>>>(e_ba + Ee, deg + 1 * Nn);
    hist_k<<<(Ee + 255) / 256, 256, 0, s1>>>(e_aa + Ee, deg + 2 * Nn);
    scan_k<<<3, SCAN_T, 0, s1>>>(deg, base, cursor);
    permute_k<<<(Ee + 255) / 256, 256, 0, s1>>>(e_ab, e_ab + Ee, CUR(0), CSR(0));
    permute_k<<<(Ee + 255) / 256, 256, 0, s1>>>(e_ba, e_ba + Ee, CUR(1), CSR(1));
    permute_k<<<(Ee + 255) / 256, 256, 0, s1>>>(e_aa, e_aa + Ee, CUR(2), CSR(2));
    cudaStreamWaitEvent(s1, evFuse, 0);
    run_gemm(s1, x_B, WB1, biasB1, TB1, Nn, DBv, 512);    // [t_ba | eB]
    cudaEventRecord(evB1, s1);

    // ===== layer-1 gathers =================================================
    run_gather(s1, TB1, 512, CSR(1), BASE(1), AGGR(1));   // aA1a (t_ba)
    cudaEventRecord(evA1a, s1);
    cudaStreamWaitEvent(s2, evTA, 0);
    run_gather(s2, TtA, 512, CSR(0), BASE(0), AGGR(0));   // aB1 (t_ab)
    cudaEventRecord(evB1g, s2);
    cudaStreamWaitEvent(s1, evTA, 0);
    run_gather(s1, TtA + 256, 512, CSR(2), BASE(2), AGGR(2));  // aA1b (t_aa)
    cudaEventRecord(evA1b, s1);

    // ===== s0: BN_B1 -> hB; s1: hB family ==================================
    cudaStreamWaitEvent(s0, evB1, 0);
    cudaStreamWaitEvent(s0, evB1g, 0);
    run_bn(s0, TB1 + 256, 512, AGGR(0), nullptr, 1.0f, bn_g + 1 * Hh,
           bn_b + 1 * Hh, hB, stats, prm);
    cudaEventRecord(evHB, s0);
    cudaStreamWaitEvent(s1, evHB, 0);
    run_gemm(s1, hB, WB2, biasB2, TB2, Nn, Hh, 512);      // [t2_ba | eB2]
    cudaEventRecord(evB2, s1);

    // ===== s0: BN_A1 -> hA; hA family ======================================
    cudaStreamWaitEvent(s0, evA1a, 0);
    cudaStreamWaitEvent(s0, evA1b, 0);
    run_bn(s0, TdA, 256, AGGR(1), AGGR(2), 0.5f, bn_g + 0 * Hh, bn_b + 0 * Hh,
           hA, stats, prm);
    run_gemm(s0, hA, WtA2, nullptr, TtA2, Nn, Hh, 512);   // [t2_aa | t2_ab]
    cudaEventRecord(evTA2, s0);
    run_gemm(s0, hA, WdA2, bdA2, TdA2, Nn, Hh, 256);      // eA2

    // ===== layer-2 gathers (parallel on s1/s2) =============================
    cudaStreamWaitEvent(s2, evB2, 0);
    run_gather(s2, TB2, 512, CSR(1), BASE(1), AGGR(3));   // aA2a (t2_ba)
    cudaEventRecord(evA2a, s2);
    cudaStreamWaitEvent(s1, evTA2, 0);
    run_gather(s1, TtA2, 512, CSR(2), BASE(2), AGGR(4));  // aA2b (t2_aa)
    cudaEventRecord(evA2b, s1);
    cudaStreamWaitEvent(s2, evTA2, 0);
    run_gather(s2, TtA2 + 256, 512, CSR(0), BASE(0), AGGR(5));  // aB2 (t2_ab)
    cudaEventRecord(evB2g, s2);

    // ===== s0: output BNs ==================================================
    cudaStreamWaitEvent(s0, evA2a, 0);
    cudaStreamWaitEvent(s0, evA2b, 0);
    run_bn(s0, TdA2, 256, AGGR(3), AGGR(4), 0.5f, bn_g + 2 * Hh, bn_b + 2 * Hh,
           out, stats, prm);
    cudaStreamWaitEvent(s0, evB2, 0);
    cudaStreamWaitEvent(s0, evB2g, 0);
    run_bn(s0, TB2 + 256, 512, AGGR(5), nullptr, 1.0f, bn_g + 3 * Hh,
           bn_b + 3 * Hh, out + (size_t)Nn * Hh, stats, prm);
}